// round 1
// baseline (speedup 1.0000x reference)
#include <cuda_runtime.h>

#define B_   4
#define S_   2048
#define D_   1024
#define H_   16
#define HD_  64
#define MTOT (B_ * S_)   // 8192

// Scratch (module-load allocations, allowed)
__device__ float g_xp[MTOT * D_];  // x + pe
__device__ float g_q [MTOT * D_];  // [B,H,S,HD]
__device__ float g_k [MTOT * D_];
__device__ float g_v [MTOT * D_];
__device__ float g_o [MTOT * D_];  // attention out, [B,S,D]
__device__ float g_h [MTOT * D_];  // pre-LN hidden

// ---------------------------------------------------------------------------
// x + positional encoding -> g_xp
// ---------------------------------------------------------------------------
__global__ __launch_bounds__(256) void pe_add_kernel(const float* __restrict__ x,
                                                     const float* __restrict__ pe) {
    int i = blockIdx.x * 256 + threadIdx.x;   // float4 index, 2,097,152 total
    int row = i >> 8;                          // 256 float4 per row of 1024
    int s   = row & (S_ - 1);
    int d4  = i & 255;
    float4 a = reinterpret_cast<const float4*>(x)[i];
    float4 p = reinterpret_cast<const float4*>(pe)[s * 256 + d4];
    a.x += p.x; a.y += p.y; a.z += p.z; a.w += p.w;
    reinterpret_cast<float4*>(g_xp)[i] = a;
}

// ---------------------------------------------------------------------------
// 128x128x8 SGEMM: Y = A[8192x1024] @ W[1024x1024] + bias, two epilogues:
//   MODE 0: scatter to [B,H,S,HD] (QKV projections)
//   MODE 1: plain [M,N] with residual add (output projection)
// ---------------------------------------------------------------------------
template <int MODE>
__global__ __launch_bounds__(256) void gemm_kernel(const float* __restrict__ A,
                                                   const float* __restrict__ W,
                                                   const float* __restrict__ bias,
                                                   const float* __restrict__ resid,
                                                   float* __restrict__ out) {
    __shared__ float As[8][128];
    __shared__ float Bs[8][128];
    const int tid   = threadIdx.x;
    const int mBase = blockIdx.y * 128;
    const int nBase = blockIdx.x * 128;
    const int tx = tid & 15, ty = tid >> 4;
    const int arow = tid >> 1, acol = (tid & 1) * 4;
    const int brow = tid >> 5, bcol = (tid & 31) * 4;
    const float* Ap = A + (mBase + arow) * D_ + acol;
    const float* Wp = W + brow * D_ + nBase + bcol;

    float c[8][8];
#pragma unroll
    for (int i = 0; i < 8; i++)
#pragma unroll
        for (int j = 0; j < 8; j++) c[i][j] = 0.f;

    for (int k0 = 0; k0 < D_; k0 += 8) {
        float4 av = *reinterpret_cast<const float4*>(Ap + k0);
        float4 bv = *reinterpret_cast<const float4*>(Wp + k0 * D_);
        As[acol + 0][arow] = av.x;
        As[acol + 1][arow] = av.y;
        As[acol + 2][arow] = av.z;
        As[acol + 3][arow] = av.w;
        *reinterpret_cast<float4*>(&Bs[brow][bcol]) = bv;
        __syncthreads();
#pragma unroll
        for (int kk = 0; kk < 8; kk++) {
            float a[8], b[8];
#pragma unroll
            for (int i = 0; i < 8; i++) a[i] = As[kk][ty * 8 + i];
#pragma unroll
            for (int j = 0; j < 8; j++) b[j] = Bs[kk][tx * 8 + j];
#pragma unroll
            for (int i = 0; i < 8; i++)
#pragma unroll
                for (int j = 0; j < 8; j++) c[i][j] = fmaf(a[i], b[j], c[i][j]);
        }
        __syncthreads();
    }

    const int gn0 = nBase + tx * 8;
    if (MODE == 0) {
        // scatter to [B,H,S,HD]; the 8-wide j block never crosses a head boundary
        const int h   = gn0 >> 6;
        const int hd0 = gn0 & 63;
        float4 bz0 = *reinterpret_cast<const float4*>(bias + gn0);
        float4 bz1 = *reinterpret_cast<const float4*>(bias + gn0 + 4);
#pragma unroll
        for (int i = 0; i < 8; i++) {
            int gm = mBase + ty * 8 + i;
            int b  = gm >> 11;
            int s  = gm & (S_ - 1);
            float* dst = out + (((b * H_ + h) * S_) + s) * HD_ + hd0;
            float4 o0 = make_float4(c[i][0] + bz0.x, c[i][1] + bz0.y,
                                    c[i][2] + bz0.z, c[i][3] + bz0.w);
            float4 o1 = make_float4(c[i][4] + bz1.x, c[i][5] + bz1.y,
                                    c[i][6] + bz1.z, c[i][7] + bz1.w);
            *reinterpret_cast<float4*>(dst)     = o0;
            *reinterpret_cast<float4*>(dst + 4) = o1;
        }
    } else {
        float4 bz0 = *reinterpret_cast<const float4*>(bias + gn0);
        float4 bz1 = *reinterpret_cast<const float4*>(bias + gn0 + 4);
#pragma unroll
        for (int i = 0; i < 8; i++) {
            int gm = mBase + ty * 8 + i;
            const float* rrow = resid + gm * D_;
            float* orow = out + gm * D_;
            float4 r0 = *reinterpret_cast<const float4*>(rrow + gn0);
            float4 r1 = *reinterpret_cast<const float4*>(rrow + gn0 + 4);
            float4 o0 = make_float4(c[i][0] + bz0.x + r0.x, c[i][1] + bz0.y + r0.y,
                                    c[i][2] + bz0.z + r0.z, c[i][3] + bz0.w + r0.w);
            float4 o1 = make_float4(c[i][4] + bz1.x + r1.x, c[i][5] + bz1.y + r1.y,
                                    c[i][6] + bz1.z + r1.z, c[i][7] + bz1.w + r1.w);
            *reinterpret_cast<float4*>(orow + gn0)     = o0;
            *reinterpret_cast<float4*>(orow + gn0 + 4) = o1;
        }
    }
}

// ---------------------------------------------------------------------------
// Flash attention. One block = 64 queries of one (b,h); loops over 32 key
// tiles of 64. Thread (qg,dg) owns a 4x4 micro-tile of scores / outputs.
// Row-softmax groups are 16 consecutive lanes -> shfl reductions only.
// ---------------------------------------------------------------------------
__global__ __launch_bounds__(256) void flash_kernel(const float* __restrict__ Q,
                                                    const float* __restrict__ K,
                                                    const float* __restrict__ V,
                                                    float* __restrict__ O) {
    __shared__ float q_t[64][64];  // [d][row], pre-scaled by 1/sqrt(64)
    __shared__ float kp [64][64];  // k transposed [d][key]; reused as p [key][row]
    __shared__ float v_s[64][64];  // [key][d]

    const int bh = blockIdx.y;        // b*16 + h
    const int qb = blockIdx.x * 64;   // query tile base
    const int t  = threadIdx.x;
    const float* Qh = Q + bh * (S_ * HD_);
    const float* Kh = K + bh * (S_ * HD_);
    const float* Vh = V + bh * (S_ * HD_);

    const int lr  = t >> 2;          // load row 0..63
    const int ld0 = (t & 3) * 16;    // load col base
    {
        const float* src = Qh + (qb + lr) * HD_ + ld0;
#pragma unroll
        for (int ii = 0; ii < 4; ii++) {
            float4 v4 = *reinterpret_cast<const float4*>(src + ii * 4);
            q_t[ld0 + ii * 4 + 0][lr] = v4.x * 0.125f;
            q_t[ld0 + ii * 4 + 1][lr] = v4.y * 0.125f;
            q_t[ld0 + ii * 4 + 2][lr] = v4.z * 0.125f;
            q_t[ld0 + ii * 4 + 3][lr] = v4.w * 0.125f;
        }
    }

    const int qg = t >> 4;   // query group 0..15 (rows qg*4..+3)
    const int dg = t & 15;   // key group for scores / dim group for output

    float m[4], l[4], o[4][4];
#pragma unroll
    for (int i = 0; i < 4; i++) {
        m[i] = -1e30f; l[i] = 0.f;
#pragma unroll
        for (int j = 0; j < 4; j++) o[i][j] = 0.f;
    }

    for (int kt = 0; kt < S_; kt += 64) {
        {
            const float* ksrc = Kh + (kt + lr) * HD_ + ld0;
            const float* vsrc = Vh + (kt + lr) * HD_ + ld0;
#pragma unroll
            for (int ii = 0; ii < 4; ii++) {
                float4 kv = *reinterpret_cast<const float4*>(ksrc + ii * 4);
                kp[ld0 + ii * 4 + 0][lr] = kv.x;
                kp[ld0 + ii * 4 + 1][lr] = kv.y;
                kp[ld0 + ii * 4 + 2][lr] = kv.z;
                kp[ld0 + ii * 4 + 3][lr] = kv.w;
                *reinterpret_cast<float4*>(&v_s[lr][ld0 + ii * 4]) =
                    *reinterpret_cast<const float4*>(vsrc + ii * 4);
            }
        }
        __syncthreads();

        // scores: rows qg*4+i, keys dg*4+j
        float s[4][4];
#pragma unroll
        for (int i = 0; i < 4; i++)
#pragma unroll
            for (int j = 0; j < 4; j++) s[i][j] = 0.f;
#pragma unroll
        for (int d = 0; d < 64; d++) {
            float4 qv = *reinterpret_cast<const float4*>(&q_t[d][qg * 4]);
            float4 kv = *reinterpret_cast<const float4*>(&kp[d][dg * 4]);
            float qa[4] = {qv.x, qv.y, qv.z, qv.w};
            float ka[4] = {kv.x, kv.y, kv.z, kv.w};
#pragma unroll
            for (int i = 0; i < 4; i++)
#pragma unroll
                for (int j = 0; j < 4; j++) s[i][j] = fmaf(qa[i], ka[j], s[i][j]);
        }

        // online softmax; row r's 16 owner lanes are consecutive -> shfl reduce
        float alpha[4];
#pragma unroll
        for (int i = 0; i < 4; i++) {
            float mx = fmaxf(fmaxf(s[i][0], s[i][1]), fmaxf(s[i][2], s[i][3]));
#pragma unroll
            for (int msk = 1; msk < 16; msk <<= 1)
                mx = fmaxf(mx, __shfl_xor_sync(0xffffffffu, mx, msk));
            float mn = fmaxf(m[i], mx);
            alpha[i] = __expf(m[i] - mn);
            m[i] = mn;
            float sum = 0.f;
#pragma unroll
            for (int j = 0; j < 4; j++) {
                s[i][j] = __expf(s[i][j] - mn);
                sum += s[i][j];
            }
#pragma unroll
            for (int msk = 1; msk < 16; msk <<= 1)
                sum += __shfl_xor_sync(0xffffffffu, sum, msk);
            l[i] = l[i] * alpha[i] + sum;
        }
        __syncthreads();           // everyone done reading kp as K

        // store p transposed: p[key][row]
#pragma unroll
        for (int j = 0; j < 4; j++)
            *reinterpret_cast<float4*>(&kp[dg * 4 + j][qg * 4]) =
                make_float4(s[0][j], s[1][j], s[2][j], s[3][j]);
#pragma unroll
        for (int i = 0; i < 4; i++)
#pragma unroll
            for (int j = 0; j < 4; j++) o[i][j] *= alpha[i];
        __syncthreads();           // p visible

        // O += P @ V : rows qg*4+i, dims dg*4+j
#pragma unroll
        for (int k = 0; k < 64; k++) {
            float4 pv = *reinterpret_cast<const float4*>(&kp[k][qg * 4]);
            float4 vv = *reinterpret_cast<const float4*>(&v_s[k][dg * 4]);
            float pa[4] = {pv.x, pv.y, pv.z, pv.w};
            float va[4] = {vv.x, vv.y, vv.z, vv.w};
#pragma unroll
            for (int i = 0; i < 4; i++)
#pragma unroll
                for (int j = 0; j < 4; j++) o[i][j] = fmaf(pa[i], va[j], o[i][j]);
        }
        __syncthreads();           // before next tile overwrites kp / v_s
    }

    const int b = bh >> 4, h = bh & 15;
#pragma unroll
    for (int i = 0; i < 4; i++) {
        float inv = 1.0f / l[i];
        float4 r4 = make_float4(o[i][0] * inv, o[i][1] * inv,
                                o[i][2] * inv, o[i][3] * inv);
        int row = qb + qg * 4 + i;
        *reinterpret_cast<float4*>(O + (b * S_ + row) * D_ + h * HD_ + dg * 4) = r4;
    }
}

// ---------------------------------------------------------------------------
// LayerNorm over last dim (1024), one block per row
// ---------------------------------------------------------------------------
__global__ __launch_bounds__(256) void ln_kernel(const float* __restrict__ Hm,
                                                 const float* __restrict__ gamma,
                                                 const float* __restrict__ beta,
                                                 float* __restrict__ out) {
    const int row = blockIdx.x;
    const int t   = threadIdx.x;
    const float* hr = Hm + row * D_;
    float4 v = *reinterpret_cast<const float4*>(hr + t * 4);
    float s  = v.x + v.y + v.z + v.w;
    float ss = v.x * v.x + v.y * v.y + v.z * v.z + v.w * v.w;
#pragma unroll
    for (int msk = 16; msk > 0; msk >>= 1) {
        s  += __shfl_xor_sync(0xffffffffu, s, msk);
        ss += __shfl_xor_sync(0xffffffffu, ss, msk);
    }
    __shared__ float rs[8], rss[8];
    __shared__ float mu_s, rstd_s;
    int w = t >> 5;
    if ((t & 31) == 0) { rs[w] = s; rss[w] = ss; }
    __syncthreads();
    if (t == 0) {
        float S = 0.f, SS = 0.f;
#pragma unroll
        for (int i = 0; i < 8; i++) { S += rs[i]; SS += rss[i]; }
        float mu  = S * (1.0f / D_);
        float var = SS * (1.0f / D_) - mu * mu;
        mu_s = mu;
        rstd_s = rsqrtf(var + 1e-5f);
    }
    __syncthreads();
    float mu = mu_s, rstd = rstd_s;
    float4 g4 = *reinterpret_cast<const float4*>(gamma + t * 4);
    float4 b4 = *reinterpret_cast<const float4*>(beta + t * 4);
    float4 o4;
    o4.x = (v.x - mu) * rstd * g4.x + b4.x;
    o4.y = (v.y - mu) * rstd * g4.y + b4.y;
    o4.z = (v.z - mu) * rstd * g4.z + b4.z;
    o4.w = (v.w - mu) * rstd * g4.w + b4.w;
    *reinterpret_cast<float4*>(out + row * D_ + t * 4) = o4;
}

// ---------------------------------------------------------------------------
extern "C" void kernel_launch(void* const* d_in, const int* in_sizes, int n_in,
                              void* d_out, int out_size) {
    (void)in_sizes; (void)n_in; (void)out_size;
    const float* x     = (const float*)d_in[0];
    const float* wq    = (const float*)d_in[1];
    const float* bq    = (const float*)d_in[2];
    const float* wk    = (const float*)d_in[3];
    const float* bk    = (const float*)d_in[4];
    const float* wv    = (const float*)d_in[5];
    const float* bv    = (const float*)d_in[6];
    const float* wo    = (const float*)d_in[7];
    const float* bo    = (const float*)d_in[8];
    const float* gamma = (const float*)d_in[9];
    const float* beta  = (const float*)d_in[10];
    const float* pe    = (const float*)d_in[11];
    float* out = (float*)d_out;

    float *xp, *q, *k, *v, *o, *h;
    cudaGetSymbolAddress((void**)&xp, g_xp);
    cudaGetSymbolAddress((void**)&q,  g_q);
    cudaGetSymbolAddress((void**)&k,  g_k);
    cudaGetSymbolAddress((void**)&v,  g_v);
    cudaGetSymbolAddress((void**)&o,  g_o);
    cudaGetSymbolAddress((void**)&h,  g_h);

    // 1) x + pe
    pe_add_kernel<<<(MTOT * D_ / 4) / 256, 256>>>(x, pe);

    // 2) Q/K/V projections, scattered to [B,H,S,HD]
    dim3 ggrid(D_ / 128, MTOT / 128);
    gemm_kernel<0><<<ggrid, 256>>>(xp, wq, bq, nullptr, q);
    gemm_kernel<0><<<ggrid, 256>>>(xp, wk, bk, nullptr, k);
    gemm_kernel<0><<<ggrid, 256>>>(xp, wv, bv, nullptr, v);

    // 3) attention -> [B,S,D]
    dim3 fgrid(S_ / 64, B_ * H_);
    flash_kernel<<<fgrid, 256>>>(q, k, v, o);

    // 4) output projection + bias + residual
    gemm_kernel<1><<<ggrid, 256>>>(o, wo, bo, xp, h);

    // 5) layernorm -> d_out
    ln_kernel<<<MTOT, 256>>>(h, gamma, beta, out);
}

// round 3
// speedup vs baseline: 1.3716x; 1.3716x over previous
#include <cuda_runtime.h>
#include <cstdint>

#define B_   4
#define S_   2048
#define D_   1024
#define H_   16
#define HD_  64
#define MTOT (B_ * S_)   // 8192

// ---------------------------------------------------------------------------
// Scratch (module-load device globals; allocation-free at run time)
// ---------------------------------------------------------------------------
__device__ float g_xp [MTOT * D_];     // x + pe
__device__ float g_q  [MTOT * D_];     // [B,H,S,HD]
__device__ float g_k  [MTOT * D_];
__device__ float g_v  [MTOT * D_];
__device__ float g_o  [MTOT * D_];     // attention out [B,S,D]
__device__ float g_h  [MTOT * D_];     // pre-LN hidden
__device__ float g_wt4[4 * D_ * D_];   // 4 transposed weights [N,K]

// ---------------------------------------------------------------------------
__device__ __forceinline__ uint32_t f2tf(float f) {
    uint32_t u;
    asm("cvt.rna.tf32.f32 %0, %1;" : "=r"(u) : "f"(f));
    return u;
}
__device__ __forceinline__ void mma8(float c[4], const uint32_t a[4], const uint32_t b[2]) {
    asm volatile("mma.sync.aligned.m16n8k8.row.col.f32.tf32.tf32.f32 "
                 "{%0,%1,%2,%3}, {%4,%5,%6,%7}, {%8,%9}, {%0,%1,%2,%3};"
                 : "+f"(c[0]), "+f"(c[1]), "+f"(c[2]), "+f"(c[3])
                 : "r"(a[0]), "r"(a[1]), "r"(a[2]), "r"(a[3]), "r"(b[0]), "r"(b[1]));
}

// ---------------------------------------------------------------------------
// x + positional encoding -> g_xp
// ---------------------------------------------------------------------------
__global__ __launch_bounds__(256) void pe_add_kernel(const float* __restrict__ x,
                                                     const float* __restrict__ pe) {
    int i = blockIdx.x * 256 + threadIdx.x;
    int row = i >> 8;
    int s   = row & (S_ - 1);
    int d4  = i & 255;
    float4 a = reinterpret_cast<const float4*>(x)[i];
    float4 p = reinterpret_cast<const float4*>(pe)[s * 256 + d4];
    a.x += p.x; a.y += p.y; a.z += p.z; a.w += p.w;
    reinterpret_cast<float4*>(g_xp)[i] = a;
}

// ---------------------------------------------------------------------------
// Batched 1024x1024 transpose of all 4 weights: wt4[z][n][k] = Wz[k][n]
// ---------------------------------------------------------------------------
__global__ __launch_bounds__(256) void transpose4_kernel(const float* __restrict__ w0,
                                                         const float* __restrict__ w1,
                                                         const float* __restrict__ w2,
                                                         const float* __restrict__ w3) {
    __shared__ float tile[32][33];
    const float* W = (blockIdx.z == 0) ? w0 : (blockIdx.z == 1) ? w1
                   : (blockIdx.z == 2) ? w2 : w3;
    float* Wt = g_wt4 + (size_t)blockIdx.z * D_ * D_;
    int bx = blockIdx.x * 32, by = blockIdx.y * 32;
#pragma unroll
    for (int i = 0; i < 32; i += 8)
        tile[threadIdx.y + i][threadIdx.x] = W[(by + threadIdx.y + i) * D_ + bx + threadIdx.x];
    __syncthreads();
#pragma unroll
    for (int i = 0; i < 32; i += 8)
        Wt[(bx + threadIdx.y + i) * D_ + by + threadIdx.x] = tile[threadIdx.x][threadIdx.y + i];
}

// ---------------------------------------------------------------------------
// tf32 mma.sync GEMM: Y[8192x1024] = A[M,K] @ Wt[N,K]^T (+bias)
//   MODE 0: scatter to [B,H,S,HD]; MODE 1: [M,N] + residual
// CTA 128x128, BK=32, 8 warps (2m x 4n), warp tile 64x32, frag m16n8k8.
// SMEM: A/B tiles row-major [128][36] (stride 36 -> conflict-free frag loads),
// stored pre-converted to tf32. Double-buffered.
// ---------------------------------------------------------------------------
#define SSTR 36
#define SBUF (128 * SSTR)                 // elems per tile buffer
#define GSM_TOTAL (4 * SBUF * 4)          // 4 buffers (A0,B0,A1,B1) * 4B

template <int MODE>
__global__ __launch_bounds__(256) void gemm_mma_kernel(const float* __restrict__ A,
                                                       const float* __restrict__ Wt,
                                                       const float* __restrict__ bias,
                                                       const float* __restrict__ resid,
                                                       float* __restrict__ out) {
    extern __shared__ uint32_t smem[];
    // layout: [buf][A|B][SBUF]
    const int t    = threadIdx.x;
    const int wid  = t >> 5;
    const int lane = t & 31;
    const int grp  = lane >> 2;       // 0..7
    const int tg   = lane & 3;        // 0..3
    const int wm   = wid & 1;         // warp m 0..1
    const int wn   = wid >> 1;        // warp n 0..3
    const int mBase = blockIdx.y * 128;
    const int nBase = blockIdx.x * 128;

    const int mrow = t >> 1;          // loader row 0..127
    const int kh   = (t & 1) * 16;    // loader k half

    const float* Ag = A  + (size_t)(mBase + mrow) * D_ + kh;
    const float* Bg = Wt + (size_t)(nBase + mrow) * D_ + kh;

    float acc[4][4][4];
#pragma unroll
    for (int i = 0; i < 4; i++)
#pragma unroll
        for (int j = 0; j < 4; j++)
#pragma unroll
            for (int r = 0; r < 4; r++) acc[i][j][r] = 0.f;

    float4 pa[4], pb[4];

    auto ldg_chunk = [&](int c) {
        const float* a = Ag + c * 32;
        const float* b = Bg + c * 32;
#pragma unroll
        for (int i = 0; i < 4; i++) {
            pa[i] = *reinterpret_cast<const float4*>(a + i * 4);
            pb[i] = *reinterpret_cast<const float4*>(b + i * 4);
        }
    };
    auto sts_chunk = [&](int buf) {
        uint32_t* sa = smem + buf * 2 * SBUF + mrow * SSTR + kh;
        uint32_t* sb = sa + SBUF;
#pragma unroll
        for (int i = 0; i < 4; i++) {
            uint4 av = make_uint4(f2tf(pa[i].x), f2tf(pa[i].y), f2tf(pa[i].z), f2tf(pa[i].w));
            uint4 bv = make_uint4(f2tf(pb[i].x), f2tf(pb[i].y), f2tf(pb[i].z), f2tf(pb[i].w));
            *reinterpret_cast<uint4*>(sa + i * 4) = av;
            *reinterpret_cast<uint4*>(sb + i * 4) = bv;
        }
    };
    auto compute = [&](int buf) {
        const uint32_t* sa = smem + buf * 2 * SBUF;
        const uint32_t* sb = sa + SBUF;
#pragma unroll
        for (int s = 0; s < 4; s++) {
            const int kb = s * 8;
            uint32_t af[4][4], bf[4][2];
#pragma unroll
            for (int mf = 0; mf < 4; mf++) {
                const int r = wm * 64 + mf * 16 + grp;
                af[mf][0] = sa[r * SSTR + kb + tg];
                af[mf][1] = sa[(r + 8) * SSTR + kb + tg];
                af[mf][2] = sa[r * SSTR + kb + tg + 4];
                af[mf][3] = sa[(r + 8) * SSTR + kb + tg + 4];
            }
#pragma unroll
            for (int nf = 0; nf < 4; nf++) {
                const int n = wn * 32 + nf * 8 + grp;
                bf[nf][0] = sb[n * SSTR + kb + tg];
                bf[nf][1] = sb[n * SSTR + kb + tg + 4];
            }
#pragma unroll
            for (int mf = 0; mf < 4; mf++)
#pragma unroll
                for (int nf = 0; nf < 4; nf++)
                    mma8(acc[mf][nf], af[mf], bf[nf]);
        }
    };

    ldg_chunk(0);
    sts_chunk(0);
    __syncthreads();
    for (int c = 0; c < 32; c++) {
        if (c < 31) ldg_chunk(c + 1);
        compute(c & 1);
        __syncthreads();
        if (c < 31) {
            sts_chunk((c + 1) & 1);
            __syncthreads();
        }
    }

    // ---- epilogue ----
    float2 bz[4];
#pragma unroll
    for (int nf = 0; nf < 4; nf++)
        bz[nf] = *reinterpret_cast<const float2*>(bias + nBase + wn * 32 + nf * 8 + tg * 2);

#pragma unroll
    for (int mf = 0; mf < 4; mf++) {
#pragma unroll
        for (int half = 0; half < 2; half++) {
            const int gm = mBase + wm * 64 + mf * 16 + grp + half * 8;
            if (MODE == 0) {
                const int b = gm >> 11;
                const int s = gm & (S_ - 1);
                float* rowbase = out + ((size_t)(b * H_) * S_ + s) * HD_;
#pragma unroll
                for (int nf = 0; nf < 4; nf++) {
                    const int n  = nBase + wn * 32 + nf * 8 + tg * 2;
                    const int h  = n >> 6;
                    const int hd = n & 63;
                    float2 v2;
                    v2.x = acc[mf][nf][half * 2 + 0] + bz[nf].x;
                    v2.y = acc[mf][nf][half * 2 + 1] + bz[nf].y;
                    *reinterpret_cast<float2*>(rowbase + (size_t)h * S_ * HD_ + hd) = v2;
                }
            } else {
                const float* rr = resid + (size_t)gm * D_;
                float* orow     = out   + (size_t)gm * D_;
#pragma unroll
                for (int nf = 0; nf < 4; nf++) {
                    const int n = nBase + wn * 32 + nf * 8 + tg * 2;
                    float2 r2 = *reinterpret_cast<const float2*>(rr + n);
                    float2 v2;
                    v2.x = acc[mf][nf][half * 2 + 0] + bz[nf].x + r2.x;
                    v2.y = acc[mf][nf][half * 2 + 1] + bz[nf].y + r2.y;
                    *reinterpret_cast<float2*>(orow + n) = v2;
                }
            }
        }
    }
}

// ---------------------------------------------------------------------------
// Flash attention (fp32 SIMT) — unchanged
// ---------------------------------------------------------------------------
__global__ __launch_bounds__(256) void flash_kernel(const float* __restrict__ Q,
                                                    const float* __restrict__ K,
                                                    const float* __restrict__ V,
                                                    float* __restrict__ O) {
    __shared__ float q_t[64][64];
    __shared__ float kp [64][64];
    __shared__ float v_s[64][64];

    const int bh = blockIdx.y;
    const int qb = blockIdx.x * 64;
    const int t  = threadIdx.x;
    const float* Qh = Q + bh * (S_ * HD_);
    const float* Kh = K + bh * (S_ * HD_);
    const float* Vh = V + bh * (S_ * HD_);

    const int lr  = t >> 2;
    const int ld0 = (t & 3) * 16;
    {
        const float* src = Qh + (qb + lr) * HD_ + ld0;
#pragma unroll
        for (int ii = 0; ii < 4; ii++) {
            float4 v4 = *reinterpret_cast<const float4*>(src + ii * 4);
            q_t[ld0 + ii * 4 + 0][lr] = v4.x * 0.125f;
            q_t[ld0 + ii * 4 + 1][lr] = v4.y * 0.125f;
            q_t[ld0 + ii * 4 + 2][lr] = v4.z * 0.125f;
            q_t[ld0 + ii * 4 + 3][lr] = v4.w * 0.125f;
        }
    }

    const int qg = t >> 4;
    const int dg = t & 15;

    float m[4], l[4], o[4][4];
#pragma unroll
    for (int i = 0; i < 4; i++) {
        m[i] = -1e30f; l[i] = 0.f;
#pragma unroll
        for (int j = 0; j < 4; j++) o[i][j] = 0.f;
    }

    for (int kt = 0; kt < S_; kt += 64) {
        {
            const float* ksrc = Kh + (kt + lr) * HD_ + ld0;
            const float* vsrc = Vh + (kt + lr) * HD_ + ld0;
#pragma unroll
            for (int ii = 0; ii < 4; ii++) {
                float4 kv = *reinterpret_cast<const float4*>(ksrc + ii * 4);
                kp[ld0 + ii * 4 + 0][lr] = kv.x;
                kp[ld0 + ii * 4 + 1][lr] = kv.y;
                kp[ld0 + ii * 4 + 2][lr] = kv.z;
                kp[ld0 + ii * 4 + 3][lr] = kv.w;
                *reinterpret_cast<float4*>(&v_s[lr][ld0 + ii * 4]) =
                    *reinterpret_cast<const float4*>(vsrc + ii * 4);
            }
        }
        __syncthreads();

        float s[4][4];
#pragma unroll
        for (int i = 0; i < 4; i++)
#pragma unroll
            for (int j = 0; j < 4; j++) s[i][j] = 0.f;
#pragma unroll
        for (int d = 0; d < 64; d++) {
            float4 qv = *reinterpret_cast<const float4*>(&q_t[d][qg * 4]);
            float4 kv = *reinterpret_cast<const float4*>(&kp[d][dg * 4]);
            float qa[4] = {qv.x, qv.y, qv.z, qv.w};
            float ka[4] = {kv.x, kv.y, kv.z, kv.w};
#pragma unroll
            for (int i = 0; i < 4; i++)
#pragma unroll
                for (int j = 0; j < 4; j++) s[i][j] = fmaf(qa[i], ka[j], s[i][j]);
        }

        float alpha[4];
#pragma unroll
        for (int i = 0; i < 4; i++) {
            float mx = fmaxf(fmaxf(s[i][0], s[i][1]), fmaxf(s[i][2], s[i][3]));
#pragma unroll
            for (int msk = 1; msk < 16; msk <<= 1)
                mx = fmaxf(mx, __shfl_xor_sync(0xffffffffu, mx, msk));
            float mn = fmaxf(m[i], mx);
            alpha[i] = __expf(m[i] - mn);
            m[i] = mn;
            float sum = 0.f;
#pragma unroll
            for (int j = 0; j < 4; j++) {
                s[i][j] = __expf(s[i][j] - mn);
                sum += s[i][j];
            }
#pragma unroll
            for (int msk = 1; msk < 16; msk <<= 1)
                sum += __shfl_xor_sync(0xffffffffu, sum, msk);
            l[i] = l[i] * alpha[i] + sum;
        }
        __syncthreads();

#pragma unroll
        for (int j = 0; j < 4; j++)
            *reinterpret_cast<float4*>(&kp[dg * 4 + j][qg * 4]) =
                make_float4(s[0][j], s[1][j], s[2][j], s[3][j]);
#pragma unroll
        for (int i = 0; i < 4; i++)
#pragma unroll
            for (int j = 0; j < 4; j++) o[i][j] *= alpha[i];
        __syncthreads();

#pragma unroll
        for (int k = 0; k < 64; k++) {
            float4 pv = *reinterpret_cast<const float4*>(&kp[k][qg * 4]);
            float4 vv = *reinterpret_cast<const float4*>(&v_s[k][dg * 4]);
            float pa[4] = {pv.x, pv.y, pv.z, pv.w};
            float va[4] = {vv.x, vv.y, vv.z, vv.w};
#pragma unroll
            for (int i = 0; i < 4; i++)
#pragma unroll
                for (int j = 0; j < 4; j++) o[i][j] = fmaf(pa[i], va[j], o[i][j]);
        }
        __syncthreads();
    }

    const int b = bh >> 4, h = bh & 15;
#pragma unroll
    for (int i = 0; i < 4; i++) {
        float inv = 1.0f / l[i];
        float4 r4 = make_float4(o[i][0] * inv, o[i][1] * inv,
                                o[i][2] * inv, o[i][3] * inv);
        int row = qb + qg * 4 + i;
        *reinterpret_cast<float4*>(O + (b * S_ + row) * D_ + h * HD_ + dg * 4) = r4;
    }
}

// ---------------------------------------------------------------------------
// LayerNorm over last dim (1024), one block per row
// ---------------------------------------------------------------------------
__global__ __launch_bounds__(256) void ln_kernel(const float* __restrict__ Hm,
                                                 const float* __restrict__ gamma,
                                                 const float* __restrict__ beta,
                                                 float* __restrict__ out) {
    const int row = blockIdx.x;
    const int t   = threadIdx.x;
    const float* hr = Hm + row * D_;
    float4 v = *reinterpret_cast<const float4*>(hr + t * 4);
    float s  = v.x + v.y + v.z + v.w;
    float ss = v.x * v.x + v.y * v.y + v.z * v.z + v.w * v.w;
#pragma unroll
    for (int msk = 16; msk > 0; msk >>= 1) {
        s  += __shfl_xor_sync(0xffffffffu, s, msk);
        ss += __shfl_xor_sync(0xffffffffu, ss, msk);
    }
    __shared__ float rs[8], rss[8];
    __shared__ float mu_s, rstd_s;
    int w = t >> 5;
    if ((t & 31) == 0) { rs[w] = s; rss[w] = ss; }
    __syncthreads();
    if (t == 0) {
        float S = 0.f, SS = 0.f;
#pragma unroll
        for (int i = 0; i < 8; i++) { S += rs[i]; SS += rss[i]; }
        float mu  = S * (1.0f / D_);
        float var = SS * (1.0f / D_) - mu * mu;
        mu_s = mu;
        rstd_s = rsqrtf(var + 1e-5f);
    }
    __syncthreads();
    float mu = mu_s, rstd = rstd_s;
    float4 g4 = *reinterpret_cast<const float4*>(gamma + t * 4);
    float4 b4 = *reinterpret_cast<const float4*>(beta + t * 4);
    float4 o4;
    o4.x = (v.x - mu) * rstd * g4.x + b4.x;
    o4.y = (v.y - mu) * rstd * g4.y + b4.y;
    o4.z = (v.z - mu) * rstd * g4.z + b4.z;
    o4.w = (v.w - mu) * rstd * g4.w + b4.w;
    *reinterpret_cast<float4*>(out + row * D_ + t * 4) = o4;
}

// ---------------------------------------------------------------------------
extern "C" void kernel_launch(void* const* d_in, const int* in_sizes, int n_in,
                              void* d_out, int out_size) {
    (void)in_sizes; (void)n_in; (void)out_size;
    const float* x     = (const float*)d_in[0];
    const float* wq    = (const float*)d_in[1];
    const float* bq    = (const float*)d_in[2];
    const float* wk    = (const float*)d_in[3];
    const float* bk    = (const float*)d_in[4];
    const float* wv    = (const float*)d_in[5];
    const float* bv    = (const float*)d_in[6];
    const float* wo    = (const float*)d_in[7];
    const float* bo    = (const float*)d_in[8];
    const float* gamma = (const float*)d_in[9];
    const float* beta  = (const float*)d_in[10];
    const float* pe    = (const float*)d_in[11];
    float* out = (float*)d_out;

    float *xp, *q, *k, *v, *o, *h, *wt;
    cudaGetSymbolAddress((void**)&xp, g_xp);
    cudaGetSymbolAddress((void**)&q,  g_q);
    cudaGetSymbolAddress((void**)&k,  g_k);
    cudaGetSymbolAddress((void**)&v,  g_v);
    cudaGetSymbolAddress((void**)&o,  g_o);
    cudaGetSymbolAddress((void**)&h,  g_h);
    cudaGetSymbolAddress((void**)&wt, g_wt4);

    cudaFuncSetAttribute(gemm_mma_kernel<0>,
                         cudaFuncAttributeMaxDynamicSharedMemorySize, GSM_TOTAL);
    cudaFuncSetAttribute(gemm_mma_kernel<1>,
                         cudaFuncAttributeMaxDynamicSharedMemorySize, GSM_TOTAL);

    // 1) x + pe
    pe_add_kernel<<<(MTOT * D_ / 4) / 256, 256>>>(x, pe);

    // 2) transpose all 4 weights -> g_wt4 [N,K]
    transpose4_kernel<<<dim3(32, 32, 4), dim3(32, 8)>>>(wq, wk, wv, wo);

    // 3) Q/K/V projections via tf32 mma.sync
    dim3 ggrid(D_ / 128, MTOT / 128);
    gemm_mma_kernel<0><<<ggrid, 256, GSM_TOTAL>>>(xp, wt + 0 * (size_t)D_ * D_, bq, nullptr, q);
    gemm_mma_kernel<0><<<ggrid, 256, GSM_TOTAL>>>(xp, wt + 1 * (size_t)D_ * D_, bk, nullptr, k);
    gemm_mma_kernel<0><<<ggrid, 256, GSM_TOTAL>>>(xp, wt + 2 * (size_t)D_ * D_, bv, nullptr, v);

    // 4) attention
    dim3 fgrid(S_ / 64, B_ * H_);
    flash_kernel<<<fgrid, 256>>>(q, k, v, o);

    // 5) output projection + bias + residual
    gemm_mma_kernel<1><<<ggrid, 256, GSM_TOTAL>>>(o, wt + 3 * (size_t)D_ * D_, bo, xp, h);

    // 6) layernorm
    ln_kernel<<<MTOT, 256>>>(h, gamma, beta, out);
}

// round 4
// speedup vs baseline: 2.9458x; 2.1477x over previous
#include <cuda_runtime.h>
#include <cstdint>

#define B_   4
#define S_   2048
#define D_   1024
#define H_   16
#define HD_  64
#define MTOT (B_ * S_)   // 8192

// ---------------------------------------------------------------------------
// Scratch (module-load device globals; allocation-free at run time)
// ---------------------------------------------------------------------------
__device__ float g_xp [MTOT * D_];     // x + pe
__device__ float g_q  [MTOT * D_];     // [B,H,S,HD]
__device__ float g_k  [MTOT * D_];
__device__ float g_v  [MTOT * D_];
__device__ float g_o  [MTOT * D_];     // attention out [B,S,D]
__device__ float g_h  [MTOT * D_];     // pre-LN hidden
__device__ float g_wt4[4 * D_ * D_];   // 4 transposed weights [N,K]

// ---------------------------------------------------------------------------
__device__ __forceinline__ uint32_t f2tf(float f) {
    uint32_t u;
    asm("cvt.rna.tf32.f32 %0, %1;" : "=r"(u) : "f"(f));
    return u;
}
__device__ __forceinline__ void mma8(float c[4], const uint32_t a[4], const uint32_t b[2]) {
    asm volatile("mma.sync.aligned.m16n8k8.row.col.f32.tf32.tf32.f32 "
                 "{%0,%1,%2,%3}, {%4,%5,%6,%7}, {%8,%9}, {%0,%1,%2,%3};"
                 : "+f"(c[0]), "+f"(c[1]), "+f"(c[2]), "+f"(c[3])
                 : "r"(a[0]), "r"(a[1]), "r"(a[2]), "r"(a[3]), "r"(b[0]), "r"(b[1]));
}

// ---------------------------------------------------------------------------
// x + positional encoding -> g_xp
// ---------------------------------------------------------------------------
__global__ __launch_bounds__(256) void pe_add_kernel(const float* __restrict__ x,
                                                     const float* __restrict__ pe) {
    int i = blockIdx.x * 256 + threadIdx.x;
    int row = i >> 8;
    int s   = row & (S_ - 1);
    int d4  = i & 255;
    float4 a = reinterpret_cast<const float4*>(x)[i];
    float4 p = reinterpret_cast<const float4*>(pe)[s * 256 + d4];
    a.x += p.x; a.y += p.y; a.z += p.z; a.w += p.w;
    reinterpret_cast<float4*>(g_xp)[i] = a;
}

// ---------------------------------------------------------------------------
// Batched 1024x1024 transpose of all 4 weights: wt4[z][n][k] = Wz[k][n]
// ---------------------------------------------------------------------------
__global__ __launch_bounds__(256) void transpose4_kernel(const float* __restrict__ w0,
                                                         const float* __restrict__ w1,
                                                         const float* __restrict__ w2,
                                                         const float* __restrict__ w3) {
    __shared__ float tile[32][33];
    const float* W = (blockIdx.z == 0) ? w0 : (blockIdx.z == 1) ? w1
                   : (blockIdx.z == 2) ? w2 : w3;
    float* Wt = g_wt4 + (size_t)blockIdx.z * D_ * D_;
    int bx = blockIdx.x * 32, by = blockIdx.y * 32;
#pragma unroll
    for (int i = 0; i < 32; i += 8)
        tile[threadIdx.y + i][threadIdx.x] = W[(by + threadIdx.y + i) * D_ + bx + threadIdx.x];
    __syncthreads();
#pragma unroll
    for (int i = 0; i < 32; i += 8)
        Wt[(bx + threadIdx.y + i) * D_ + by + threadIdx.x] = tile[threadIdx.x][threadIdx.y + i];
}

// ---------------------------------------------------------------------------
// tf32 mma.sync GEMM (unchanged from round 3)
// ---------------------------------------------------------------------------
#define SSTR 36
#define SBUF (128 * SSTR)
#define GSM_TOTAL (4 * SBUF * 4)

template <int MODE>
__global__ __launch_bounds__(256) void gemm_mma_kernel(const float* __restrict__ A,
                                                       const float* __restrict__ Wt,
                                                       const float* __restrict__ bias,
                                                       const float* __restrict__ resid,
                                                       float* __restrict__ out) {
    extern __shared__ uint32_t smem[];
    const int t    = threadIdx.x;
    const int wid  = t >> 5;
    const int lane = t & 31;
    const int grp  = lane >> 2;
    const int tg   = lane & 3;
    const int wm   = wid & 1;
    const int wn   = wid >> 1;
    const int mBase = blockIdx.y * 128;
    const int nBase = blockIdx.x * 128;

    const int mrow = t >> 1;
    const int kh   = (t & 1) * 16;

    const float* Ag = A  + (size_t)(mBase + mrow) * D_ + kh;
    const float* Bg = Wt + (size_t)(nBase + mrow) * D_ + kh;

    float acc[4][4][4];
#pragma unroll
    for (int i = 0; i < 4; i++)
#pragma unroll
        for (int j = 0; j < 4; j++)
#pragma unroll
            for (int r = 0; r < 4; r++) acc[i][j][r] = 0.f;

    float4 pa[4], pb[4];

    auto ldg_chunk = [&](int c) {
        const float* a = Ag + c * 32;
        const float* b = Bg + c * 32;
#pragma unroll
        for (int i = 0; i < 4; i++) {
            pa[i] = *reinterpret_cast<const float4*>(a + i * 4);
            pb[i] = *reinterpret_cast<const float4*>(b + i * 4);
        }
    };
    auto sts_chunk = [&](int buf) {
        uint32_t* sa = smem + buf * 2 * SBUF + mrow * SSTR + kh;
        uint32_t* sb = sa + SBUF;
#pragma unroll
        for (int i = 0; i < 4; i++) {
            uint4 av = make_uint4(f2tf(pa[i].x), f2tf(pa[i].y), f2tf(pa[i].z), f2tf(pa[i].w));
            uint4 bv = make_uint4(f2tf(pb[i].x), f2tf(pb[i].y), f2tf(pb[i].z), f2tf(pb[i].w));
            *reinterpret_cast<uint4*>(sa + i * 4) = av;
            *reinterpret_cast<uint4*>(sb + i * 4) = bv;
        }
    };
    auto compute = [&](int buf) {
        const uint32_t* sa = smem + buf * 2 * SBUF;
        const uint32_t* sb = sa + SBUF;
#pragma unroll
        for (int s = 0; s < 4; s++) {
            const int kb = s * 8;
            uint32_t af[4][4], bf[4][2];
#pragma unroll
            for (int mf = 0; mf < 4; mf++) {
                const int r = wm * 64 + mf * 16 + grp;
                af[mf][0] = sa[r * SSTR + kb + tg];
                af[mf][1] = sa[(r + 8) * SSTR + kb + tg];
                af[mf][2] = sa[r * SSTR + kb + tg + 4];
                af[mf][3] = sa[(r + 8) * SSTR + kb + tg + 4];
            }
#pragma unroll
            for (int nf = 0; nf < 4; nf++) {
                const int n = wn * 32 + nf * 8 + grp;
                bf[nf][0] = sb[n * SSTR + kb + tg];
                bf[nf][1] = sb[n * SSTR + kb + tg + 4];
            }
#pragma unroll
            for (int mf = 0; mf < 4; mf++)
#pragma unroll
                for (int nf = 0; nf < 4; nf++)
                    mma8(acc[mf][nf], af[mf], bf[nf]);
        }
    };

    ldg_chunk(0);
    sts_chunk(0);
    __syncthreads();
    for (int c = 0; c < 32; c++) {
        if (c < 31) ldg_chunk(c + 1);
        compute(c & 1);
        __syncthreads();
        if (c < 31) {
            sts_chunk((c + 1) & 1);
            __syncthreads();
        }
    }

    float2 bz[4];
#pragma unroll
    for (int nf = 0; nf < 4; nf++)
        bz[nf] = *reinterpret_cast<const float2*>(bias + nBase + wn * 32 + nf * 8 + tg * 2);

#pragma unroll
    for (int mf = 0; mf < 4; mf++) {
#pragma unroll
        for (int half = 0; half < 2; half++) {
            const int gm = mBase + wm * 64 + mf * 16 + grp + half * 8;
            if (MODE == 0) {
                const int b = gm >> 11;
                const int s = gm & (S_ - 1);
                float* rowbase = out + ((size_t)(b * H_) * S_ + s) * HD_;
#pragma unroll
                for (int nf = 0; nf < 4; nf++) {
                    const int n  = nBase + wn * 32 + nf * 8 + tg * 2;
                    const int h  = n >> 6;
                    const int hd = n & 63;
                    float2 v2;
                    v2.x = acc[mf][nf][half * 2 + 0] + bz[nf].x;
                    v2.y = acc[mf][nf][half * 2 + 1] + bz[nf].y;
                    *reinterpret_cast<float2*>(rowbase + (size_t)h * S_ * HD_ + hd) = v2;
                }
            } else {
                const float* rr = resid + (size_t)gm * D_;
                float* orow     = out   + (size_t)gm * D_;
#pragma unroll
                for (int nf = 0; nf < 4; nf++) {
                    const int n = nBase + wn * 32 + nf * 8 + tg * 2;
                    float2 r2 = *reinterpret_cast<const float2*>(rr + n);
                    float2 v2;
                    v2.x = acc[mf][nf][half * 2 + 0] + bz[nf].x + r2.x;
                    v2.y = acc[mf][nf][half * 2 + 1] + bz[nf].y + r2.y;
                    *reinterpret_cast<float2*>(orow + n) = v2;
                }
            }
        }
    }
}

// ---------------------------------------------------------------------------
// Flash attention via tf32 mma.sync.
// Block: 256 threads = 8 warps; 128 queries (16 per warp); key tiles of 64.
// SMEM (uint32 tf32 payloads):
//   Ksm [64][68]   key tile, [key][d]       (stride 68 -> conflict-free b-frags)
//   Vsm [64][72]   value tile, [key][hd]    (stride 72 -> conflict-free b-frags)
//   Psm [8][16][68] per-warp P / Q staging  (stride 68 -> conflict-free a-frags)
// ---------------------------------------------------------------------------
#define KSTR 68
#define VSTR 72
#define PSTR 68
#define PWSZ (16 * PSTR)
#define FSM_K 0
#define FSM_V (64 * KSTR)
#define FSM_P (FSM_V + 64 * VSTR)
#define FSM_TOTAL ((FSM_P + 8 * PWSZ) * 4)

__global__ __launch_bounds__(256, 2) void flash_mma_kernel(const float* __restrict__ Qg,
                                                           const float* __restrict__ Kg,
                                                           const float* __restrict__ Vg,
                                                           float* __restrict__ Og) {
    extern __shared__ uint32_t fsm[];
    uint32_t* Ksm = fsm + FSM_K;
    uint32_t* Vsm = fsm + FSM_V;
    uint32_t* Psm = fsm + FSM_P;

    const int t    = threadIdx.x;
    const int wid  = t >> 5;
    const int lane = t & 31;
    const int grp  = lane >> 2;
    const int tg   = lane & 3;
    const int bh   = blockIdx.y;
    const int qb   = blockIdx.x * 128;

    const float* Qh = Qg + (size_t)bh * S_ * HD_;
    const float* Kh = Kg + (size_t)bh * S_ * HD_;
    const float* Vh = Vg + (size_t)bh * S_ * HD_;

    // ---- stage Q tile (scaled, tf32) into Psm, then lift to a-frags ----
    {
        const int row = t >> 1;
        const int c0  = (t & 1) * 32;
        const float* src = Qh + (size_t)(qb + row) * HD_ + c0;
        uint32_t* dst = Psm + (row >> 4) * PWSZ + (row & 15) * PSTR + c0;
#pragma unroll
        for (int i = 0; i < 8; i++) {
            float4 v4 = *reinterpret_cast<const float4*>(src + i * 4);
            dst[i * 4 + 0] = f2tf(v4.x * 0.125f);
            dst[i * 4 + 1] = f2tf(v4.y * 0.125f);
            dst[i * 4 + 2] = f2tf(v4.z * 0.125f);
            dst[i * 4 + 3] = f2tf(v4.w * 0.125f);
        }
    }
    __syncthreads();

    uint32_t* Pw = Psm + wid * PWSZ;
    uint32_t qf[8][4];
#pragma unroll
    for (int s = 0; s < 8; s++) {
        const int kb = s * 8;
        qf[s][0] = Pw[grp * PSTR + kb + tg];
        qf[s][1] = Pw[(grp + 8) * PSTR + kb + tg];
        qf[s][2] = Pw[grp * PSTR + kb + tg + 4];
        qf[s][3] = Pw[(grp + 8) * PSTR + kb + tg + 4];
    }
    __syncthreads();

    float m0 = -1e30f, m1 = -1e30f, l0 = 0.f, l1 = 0.f;
    float o[8][4];
#pragma unroll
    for (int nt = 0; nt < 8; nt++)
#pragma unroll
        for (int r = 0; r < 4; r++) o[nt][r] = 0.f;

    for (int kt = 0; kt < S_; kt += 64) {
        // ---- load K/V tiles (tf32) ----
        {
            const int row = t >> 2;
            const int c0  = (t & 3) * 16;
            const float* ks = Kh + (size_t)(kt + row) * HD_ + c0;
            const float* vs = Vh + (size_t)(kt + row) * HD_ + c0;
            uint32_t* kd = Ksm + row * KSTR + c0;
            uint32_t* vd = Vsm + row * VSTR + c0;
#pragma unroll
            for (int i = 0; i < 4; i++) {
                float4 kv = *reinterpret_cast<const float4*>(ks + i * 4);
                float4 vv = *reinterpret_cast<const float4*>(vs + i * 4);
                kd[i * 4 + 0] = f2tf(kv.x); kd[i * 4 + 1] = f2tf(kv.y);
                kd[i * 4 + 2] = f2tf(kv.z); kd[i * 4 + 3] = f2tf(kv.w);
                vd[i * 4 + 0] = f2tf(vv.x); vd[i * 4 + 1] = f2tf(vv.y);
                vd[i * 4 + 2] = f2tf(vv.z); vd[i * 4 + 3] = f2tf(vv.w);
            }
        }
        __syncthreads();

        // ---- scores = Q @ K^T ----
        float sc[8][4];
#pragma unroll
        for (int nt = 0; nt < 8; nt++)
#pragma unroll
            for (int r = 0; r < 4; r++) sc[nt][r] = 0.f;
#pragma unroll
        for (int s = 0; s < 8; s++) {
            const int kb = s * 8;
#pragma unroll
            for (int nt = 0; nt < 8; nt++) {
                uint32_t bf[2];
                bf[0] = Ksm[(nt * 8 + grp) * KSTR + kb + tg];
                bf[1] = Ksm[(nt * 8 + grp) * KSTR + kb + tg + 4];
                mma8(sc[nt], qf[s], bf);
            }
        }

        // ---- online softmax (rows grp and grp+8; quad shfl reductions) ----
        float mx0 = -1e30f, mx1 = -1e30f;
#pragma unroll
        for (int nt = 0; nt < 8; nt++) {
            mx0 = fmaxf(mx0, fmaxf(sc[nt][0], sc[nt][1]));
            mx1 = fmaxf(mx1, fmaxf(sc[nt][2], sc[nt][3]));
        }
        mx0 = fmaxf(mx0, __shfl_xor_sync(0xffffffffu, mx0, 1));
        mx0 = fmaxf(mx0, __shfl_xor_sync(0xffffffffu, mx0, 2));
        mx1 = fmaxf(mx1, __shfl_xor_sync(0xffffffffu, mx1, 1));
        mx1 = fmaxf(mx1, __shfl_xor_sync(0xffffffffu, mx1, 2));
        const float mn0 = fmaxf(m0, mx0);
        const float mn1 = fmaxf(m1, mx1);
        const float a0 = __expf(m0 - mn0);
        const float a1 = __expf(m1 - mn1);
        m0 = mn0; m1 = mn1;
        float s0 = 0.f, s1 = 0.f;
#pragma unroll
        for (int nt = 0; nt < 8; nt++) {
            sc[nt][0] = __expf(sc[nt][0] - mn0);
            sc[nt][1] = __expf(sc[nt][1] - mn0);
            sc[nt][2] = __expf(sc[nt][2] - mn1);
            sc[nt][3] = __expf(sc[nt][3] - mn1);
            s0 += sc[nt][0] + sc[nt][1];
            s1 += sc[nt][2] + sc[nt][3];
        }
        s0 += __shfl_xor_sync(0xffffffffu, s0, 1);
        s0 += __shfl_xor_sync(0xffffffffu, s0, 2);
        s1 += __shfl_xor_sync(0xffffffffu, s1, 1);
        s1 += __shfl_xor_sync(0xffffffffu, s1, 2);
        l0 = l0 * a0 + s0;
        l1 = l1 * a1 + s1;
#pragma unroll
        for (int nt = 0; nt < 8; nt++) {
            o[nt][0] *= a0; o[nt][1] *= a0;
            o[nt][2] *= a1; o[nt][3] *= a1;
        }

        // ---- P (tf32) -> per-warp smem, then a-frags ----
#pragma unroll
        for (int nt = 0; nt < 8; nt++) {
            uint2 lo = make_uint2(f2tf(sc[nt][0]), f2tf(sc[nt][1]));
            uint2 hi = make_uint2(f2tf(sc[nt][2]), f2tf(sc[nt][3]));
            *reinterpret_cast<uint2*>(&Pw[grp * PSTR + nt * 8 + tg * 2])       = lo;
            *reinterpret_cast<uint2*>(&Pw[(grp + 8) * PSTR + nt * 8 + tg * 2]) = hi;
        }
        __syncwarp();

        // ---- O += P @ V ----
#pragma unroll
        for (int s = 0; s < 8; s++) {
            const int kb = s * 8;
            uint32_t pf[4];
            pf[0] = Pw[grp * PSTR + kb + tg];
            pf[1] = Pw[(grp + 8) * PSTR + kb + tg];
            pf[2] = Pw[grp * PSTR + kb + tg + 4];
            pf[3] = Pw[(grp + 8) * PSTR + kb + tg + 4];
#pragma unroll
            for (int nt = 0; nt < 8; nt++) {
                uint32_t bf[2];
                bf[0] = Vsm[(kb + tg) * VSTR + nt * 8 + grp];
                bf[1] = Vsm[(kb + tg + 4) * VSTR + nt * 8 + grp];
                mma8(o[nt], pf, bf);
            }
        }
        __syncthreads();
    }

    // ---- epilogue: O/l -> [B,S,D] ----
    const int b = bh >> 4, h = bh & 15;
    const float inv0 = 1.0f / l0;
    const float inv1 = 1.0f / l1;
    const int r0 = qb + wid * 16 + grp;
    float* base0 = Og + ((size_t)b * S_ + r0) * D_ + h * HD_;
    float* base1 = base0 + (size_t)8 * D_;
#pragma unroll
    for (int nt = 0; nt < 8; nt++) {
        *reinterpret_cast<float2*>(base0 + nt * 8 + tg * 2) =
            make_float2(o[nt][0] * inv0, o[nt][1] * inv0);
        *reinterpret_cast<float2*>(base1 + nt * 8 + tg * 2) =
            make_float2(o[nt][2] * inv1, o[nt][3] * inv1);
    }
}

// ---------------------------------------------------------------------------
// LayerNorm over last dim (1024), one block per row
// ---------------------------------------------------------------------------
__global__ __launch_bounds__(256) void ln_kernel(const float* __restrict__ Hm,
                                                 const float* __restrict__ gamma,
                                                 const float* __restrict__ beta,
                                                 float* __restrict__ out) {
    const int row = blockIdx.x;
    const int t   = threadIdx.x;
    const float* hr = Hm + row * D_;
    float4 v = *reinterpret_cast<const float4*>(hr + t * 4);
    float s  = v.x + v.y + v.z + v.w;
    float ss = v.x * v.x + v.y * v.y + v.z * v.z + v.w * v.w;
#pragma unroll
    for (int msk = 16; msk > 0; msk >>= 1) {
        s  += __shfl_xor_sync(0xffffffffu, s, msk);
        ss += __shfl_xor_sync(0xffffffffu, ss, msk);
    }
    __shared__ float rs[8], rss[8];
    __shared__ float mu_s, rstd_s;
    int w = t >> 5;
    if ((t & 31) == 0) { rs[w] = s; rss[w] = ss; }
    __syncthreads();
    if (t == 0) {
        float S = 0.f, SS = 0.f;
#pragma unroll
        for (int i = 0; i < 8; i++) { S += rs[i]; SS += rss[i]; }
        float mu  = S * (1.0f / D_);
        float var = SS * (1.0f / D_) - mu * mu;
        mu_s = mu;
        rstd_s = rsqrtf(var + 1e-5f);
    }
    __syncthreads();
    float mu = mu_s, rstd = rstd_s;
    float4 g4 = *reinterpret_cast<const float4*>(gamma + t * 4);
    float4 b4 = *reinterpret_cast<const float4*>(beta + t * 4);
    float4 o4;
    o4.x = (v.x - mu) * rstd * g4.x + b4.x;
    o4.y = (v.y - mu) * rstd * g4.y + b4.y;
    o4.z = (v.z - mu) * rstd * g4.z + b4.z;
    o4.w = (v.w - mu) * rstd * g4.w + b4.w;
    *reinterpret_cast<float4*>(out + row * D_ + t * 4) = o4;
}

// ---------------------------------------------------------------------------
extern "C" void kernel_launch(void* const* d_in, const int* in_sizes, int n_in,
                              void* d_out, int out_size) {
    (void)in_sizes; (void)n_in; (void)out_size;
    const float* x     = (const float*)d_in[0];
    const float* wq    = (const float*)d_in[1];
    const float* bq    = (const float*)d_in[2];
    const float* wk    = (const float*)d_in[3];
    const float* bk    = (const float*)d_in[4];
    const float* wv    = (const float*)d_in[5];
    const float* bv    = (const float*)d_in[6];
    const float* wo    = (const float*)d_in[7];
    const float* bo    = (const float*)d_in[8];
    const float* gamma = (const float*)d_in[9];
    const float* beta  = (const float*)d_in[10];
    const float* pe    = (const float*)d_in[11];
    float* out = (float*)d_out;

    float *xp, *q, *k, *v, *o, *h, *wt;
    cudaGetSymbolAddress((void**)&xp, g_xp);
    cudaGetSymbolAddress((void**)&q,  g_q);
    cudaGetSymbolAddress((void**)&k,  g_k);
    cudaGetSymbolAddress((void**)&v,  g_v);
    cudaGetSymbolAddress((void**)&o,  g_o);
    cudaGetSymbolAddress((void**)&h,  g_h);
    cudaGetSymbolAddress((void**)&wt, g_wt4);

    cudaFuncSetAttribute(gemm_mma_kernel<0>,
                         cudaFuncAttributeMaxDynamicSharedMemorySize, GSM_TOTAL);
    cudaFuncSetAttribute(gemm_mma_kernel<1>,
                         cudaFuncAttributeMaxDynamicSharedMemorySize, GSM_TOTAL);
    cudaFuncSetAttribute(flash_mma_kernel,
                         cudaFuncAttributeMaxDynamicSharedMemorySize, FSM_TOTAL);

    // 1) x + pe
    pe_add_kernel<<<(MTOT * D_ / 4) / 256, 256>>>(x, pe);

    // 2) transpose all 4 weights -> g_wt4 [N,K]
    transpose4_kernel<<<dim3(32, 32, 4), dim3(32, 8)>>>(wq, wk, wv, wo);

    // 3) Q/K/V projections via tf32 mma.sync
    dim3 ggrid(D_ / 128, MTOT / 128);
    gemm_mma_kernel<0><<<ggrid, 256, GSM_TOTAL>>>(xp, wt + 0 * (size_t)D_ * D_, bq, nullptr, q);
    gemm_mma_kernel<0><<<ggrid, 256, GSM_TOTAL>>>(xp, wt + 1 * (size_t)D_ * D_, bk, nullptr, k);
    gemm_mma_kernel<0><<<ggrid, 256, GSM_TOTAL>>>(xp, wt + 2 * (size_t)D_ * D_, bv, nullptr, v);

    // 4) attention via tf32 mma.sync
    dim3 fgrid(S_ / 128, B_ * H_);
    flash_mma_kernel<<<fgrid, 256, FSM_TOTAL>>>(q, k, v, o);

    // 5) output projection + bias + residual
    gemm_mma_kernel<1><<<ggrid, 256, GSM_TOTAL>>>(o, wt + 3 * (size_t)D_ * D_, bo, xp, h);

    // 6) layernorm
    ln_kernel<<<MTOT, 256>>>(h, gamma, beta, out);
}

// round 5
// speedup vs baseline: 3.3222x; 1.1278x over previous
#include <cuda_runtime.h>
#include <cstdint>

#define B_   4
#define S_   2048
#define D_   1024
#define H_   16
#define HD_  64
#define MTOT (B_ * S_)   // 8192

// ---------------------------------------------------------------------------
// Scratch (module-load device globals; allocation-free at run time)
// ---------------------------------------------------------------------------
__device__ float g_xp [MTOT * D_];     // x + pe
__device__ float g_q  [MTOT * D_];     // [B,H,S,HD]
__device__ float g_k  [MTOT * D_];
__device__ float g_v  [MTOT * D_];
__device__ float g_o  [MTOT * D_];     // attention out [B,S,D]
__device__ float g_h  [MTOT * D_];     // pre-LN hidden
__device__ float g_wt4[4 * D_ * D_];   // 4 transposed weights [N,K]

// ---------------------------------------------------------------------------
__device__ __forceinline__ uint32_t f2tf(float f) {
    uint32_t u;
    asm("cvt.rna.tf32.f32 %0, %1;" : "=r"(u) : "f"(f));
    return u;
}
__device__ __forceinline__ void mma8(float c[4], const uint32_t a[4], const uint32_t b[2]) {
    asm volatile("mma.sync.aligned.m16n8k8.row.col.f32.tf32.tf32.f32 "
                 "{%0,%1,%2,%3}, {%4,%5,%6,%7}, {%8,%9}, {%0,%1,%2,%3};"
                 : "+f"(c[0]), "+f"(c[1]), "+f"(c[2]), "+f"(c[3])
                 : "r"(a[0]), "r"(a[1]), "r"(a[2]), "r"(a[3]), "r"(b[0]), "r"(b[1]));
}
__device__ __forceinline__ uint32_t cvta_smem(const void* p) {
    uint32_t a;
    asm("{ .reg .u64 t; cvta.to.shared.u64 t, %1; cvt.u32.u64 %0, t; }" : "=r"(a) : "l"(p));
    return a;
}
// ldmatrix x4: lanes 0-7 address rows of mat0, 8-15 mat1, 16-23 mat2, 24-31 mat3.
// Result reg i = 32-bit element (row lane/4, col lane%4) of matrix i.
__device__ __forceinline__ void ldsm4(uint32_t r[4], uint32_t addr) {
    asm volatile("ldmatrix.sync.aligned.m8n8.x4.shared.b16 {%0,%1,%2,%3}, [%4];"
                 : "=r"(r[0]), "=r"(r[1]), "=r"(r[2]), "=r"(r[3]) : "r"(addr));
}

// ---------------------------------------------------------------------------
// x + positional encoding -> g_xp
// ---------------------------------------------------------------------------
__global__ __launch_bounds__(256) void pe_add_kernel(const float* __restrict__ x,
                                                     const float* __restrict__ pe) {
    int i = blockIdx.x * 256 + threadIdx.x;
    int row = i >> 8;
    int s   = row & (S_ - 1);
    int d4  = i & 255;
    float4 a = reinterpret_cast<const float4*>(x)[i];
    float4 p = reinterpret_cast<const float4*>(pe)[s * 256 + d4];
    a.x += p.x; a.y += p.y; a.z += p.z; a.w += p.w;
    reinterpret_cast<float4*>(g_xp)[i] = a;
}

// ---------------------------------------------------------------------------
// Batched 1024x1024 transpose of all 4 weights: wt4[z][n][k] = Wz[k][n]
// ---------------------------------------------------------------------------
__global__ __launch_bounds__(256) void transpose4_kernel(const float* __restrict__ w0,
                                                         const float* __restrict__ w1,
                                                         const float* __restrict__ w2,
                                                         const float* __restrict__ w3) {
    __shared__ float tile[32][33];
    const float* W = (blockIdx.z == 0) ? w0 : (blockIdx.z == 1) ? w1
                   : (blockIdx.z == 2) ? w2 : w3;
    float* Wt = g_wt4 + (size_t)blockIdx.z * D_ * D_;
    int bx = blockIdx.x * 32, by = blockIdx.y * 32;
#pragma unroll
    for (int i = 0; i < 32; i += 8)
        tile[threadIdx.y + i][threadIdx.x] = W[(by + threadIdx.y + i) * D_ + bx + threadIdx.x];
    __syncthreads();
#pragma unroll
    for (int i = 0; i < 32; i += 8)
        Wt[(bx + threadIdx.y + i) * D_ + by + threadIdx.x] = tile[threadIdx.x][threadIdx.y + i];
}

// ---------------------------------------------------------------------------
// tf32 mma.sync GEMM with ldmatrix fragment loads, single sync per chunk.
// ---------------------------------------------------------------------------
#define SSTR 36
#define SBUF (128 * SSTR)
#define GSM_TOTAL (4 * SBUF * 4)

template <int MODE>
__global__ __launch_bounds__(256) void gemm_mma_kernel(const float* __restrict__ A,
                                                       const float* __restrict__ Wt,
                                                       const float* __restrict__ bias,
                                                       const float* __restrict__ resid,
                                                       float* __restrict__ out) {
    extern __shared__ uint32_t smem[];
    const uint32_t smem_sb = cvta_smem(smem);
    const int t    = threadIdx.x;
    const int wid  = t >> 5;
    const int lane = t & 31;
    const int grp  = lane >> 2;
    const int tg   = lane & 3;
    const int wm   = wid & 1;
    const int wn   = wid >> 1;
    const int mBase = blockIdx.y * 128;
    const int nBase = blockIdx.x * 128;

    // ldmatrix per-lane addressing
    const int lm  = lane & 7;
    const int sel = lane >> 3;                 // 0..3
    const int a_row_off = lm + ((sel & 1) ? 8 : 0);
    const int a_col_off = (sel & 2) ? 4 : 0;
    const int b_row_off = lm + ((sel & 2) ? 8 : 0);
    const int b_col_off = (sel & 1) ? 4 : 0;

    const int mrow = t >> 1;
    const int kh   = (t & 1) * 16;

    const float* Ag = A  + (size_t)(mBase + mrow) * D_ + kh;
    const float* Bg = Wt + (size_t)(nBase + mrow) * D_ + kh;

    float acc[4][4][4];
#pragma unroll
    for (int i = 0; i < 4; i++)
#pragma unroll
        for (int j = 0; j < 4; j++)
#pragma unroll
            for (int r = 0; r < 4; r++) acc[i][j][r] = 0.f;

    float4 pa[4], pb[4];

    auto ldg_chunk = [&](int c) {
        const float* a = Ag + c * 32;
        const float* b = Bg + c * 32;
#pragma unroll
        for (int i = 0; i < 4; i++) {
            pa[i] = *reinterpret_cast<const float4*>(a + i * 4);
            pb[i] = *reinterpret_cast<const float4*>(b + i * 4);
        }
    };
    auto sts_chunk = [&](int buf) {
        uint32_t* sa = smem + buf * 2 * SBUF + mrow * SSTR + kh;
        uint32_t* sb = sa + SBUF;
#pragma unroll
        for (int i = 0; i < 4; i++) {
            uint4 av = make_uint4(f2tf(pa[i].x), f2tf(pa[i].y), f2tf(pa[i].z), f2tf(pa[i].w));
            uint4 bv = make_uint4(f2tf(pb[i].x), f2tf(pb[i].y), f2tf(pb[i].z), f2tf(pb[i].w));
            *reinterpret_cast<uint4*>(sa + i * 4) = av;
            *reinterpret_cast<uint4*>(sb + i * 4) = bv;
        }
    };
    auto compute = [&](int buf) {
        const uint32_t saddrA = smem_sb + (buf * 2 * SBUF) * 4;
        const uint32_t saddrB = saddrA + SBUF * 4;
#pragma unroll
        for (int s = 0; s < 4; s++) {
            const int kb = s * 8;
            uint32_t af[4][4], bm[2][4];
#pragma unroll
            for (int mf = 0; mf < 4; mf++) {
                const int r = wm * 64 + mf * 16;
                ldsm4(af[mf], saddrA + 4 * ((r + a_row_off) * SSTR + kb + a_col_off));
            }
#pragma unroll
            for (int p = 0; p < 2; p++) {
                const int n0 = wn * 32 + p * 16;
                ldsm4(bm[p], saddrB + 4 * ((n0 + b_row_off) * SSTR + kb + b_col_off));
            }
#pragma unroll
            for (int mf = 0; mf < 4; mf++)
#pragma unroll
                for (int nf = 0; nf < 4; nf++) {
                    uint32_t bf[2] = { bm[nf >> 1][(nf & 1) * 2],
                                       bm[nf >> 1][(nf & 1) * 2 + 1] };
                    mma8(acc[mf][nf], af[mf], bf);
                }
        }
    };

    ldg_chunk(0);
    sts_chunk(0);
    __syncthreads();
    for (int c = 0; c < 32; c++) {
        if (c < 31) ldg_chunk(c + 1);
        compute(c & 1);
        if (c < 31) {
            sts_chunk((c + 1) & 1);
            __syncthreads();
        }
    }

    float2 bz[4];
#pragma unroll
    for (int nf = 0; nf < 4; nf++)
        bz[nf] = *reinterpret_cast<const float2*>(bias + nBase + wn * 32 + nf * 8 + tg * 2);

#pragma unroll
    for (int mf = 0; mf < 4; mf++) {
#pragma unroll
        for (int half = 0; half < 2; half++) {
            const int gm = mBase + wm * 64 + mf * 16 + grp + half * 8;
            if (MODE == 0) {
                const int b = gm >> 11;
                const int s = gm & (S_ - 1);
                float* rowbase = out + ((size_t)(b * H_) * S_ + s) * HD_;
#pragma unroll
                for (int nf = 0; nf < 4; nf++) {
                    const int n  = nBase + wn * 32 + nf * 8 + tg * 2;
                    const int h  = n >> 6;
                    const int hd = n & 63;
                    float2 v2;
                    v2.x = acc[mf][nf][half * 2 + 0] + bz[nf].x;
                    v2.y = acc[mf][nf][half * 2 + 1] + bz[nf].y;
                    *reinterpret_cast<float2*>(rowbase + (size_t)h * S_ * HD_ + hd) = v2;
                }
            } else {
                const float* rr = resid + (size_t)gm * D_;
                float* orow     = out   + (size_t)gm * D_;
#pragma unroll
                for (int nf = 0; nf < 4; nf++) {
                    const int n = nBase + wn * 32 + nf * 8 + tg * 2;
                    float2 r2 = *reinterpret_cast<const float2*>(rr + n);
                    float2 v2;
                    v2.x = acc[mf][nf][half * 2 + 0] + bz[nf].x + r2.x;
                    v2.y = acc[mf][nf][half * 2 + 1] + bz[nf].y + r2.y;
                    *reinterpret_cast<float2*>(orow + n) = v2;
                }
            }
        }
    }
}

// ---------------------------------------------------------------------------
// Flash attention via tf32 mma.sync + ldmatrix for K / P fragments.
// ---------------------------------------------------------------------------
#define KSTR 68
#define VSTR 72
#define PSTR 68
#define PWSZ (16 * PSTR)
#define FSM_K 0
#define FSM_V (64 * KSTR)
#define FSM_P (FSM_V + 64 * VSTR)
#define FSM_TOTAL ((FSM_P + 8 * PWSZ) * 4)

__global__ __launch_bounds__(256, 2) void flash_mma_kernel(const float* __restrict__ Qg,
                                                           const float* __restrict__ Kg,
                                                           const float* __restrict__ Vg,
                                                           float* __restrict__ Og) {
    extern __shared__ uint32_t fsm[];
    uint32_t* Ksm = fsm + FSM_K;
    uint32_t* Vsm = fsm + FSM_V;
    uint32_t* Psm = fsm + FSM_P;
    const uint32_t fsm_sb  = cvta_smem(fsm);
    const uint32_t Ksm_sb  = fsm_sb + FSM_K * 4;

    const int t    = threadIdx.x;
    const int wid  = t >> 5;
    const int lane = t & 31;
    const int grp  = lane >> 2;
    const int tg   = lane & 3;
    const int bh   = blockIdx.y;
    const int qb   = blockIdx.x * 128;

    const int lm  = lane & 7;
    const int sel = lane >> 3;
    const int a_row_off = lm + ((sel & 1) ? 8 : 0);
    const int a_col_off = (sel & 2) ? 4 : 0;
    const int b_row_off = lm + ((sel & 2) ? 8 : 0);
    const int b_col_off = (sel & 1) ? 4 : 0;

    const float* Qh = Qg + (size_t)bh * S_ * HD_;
    const float* Kh = Kg + (size_t)bh * S_ * HD_;
    const float* Vh = Vg + (size_t)bh * S_ * HD_;

    // ---- stage Q tile (scaled, tf32) into Psm, then lift to a-frags ----
    {
        const int row = t >> 1;
        const int c0  = (t & 1) * 32;
        const float* src = Qh + (size_t)(qb + row) * HD_ + c0;
        uint32_t* dst = Psm + (row >> 4) * PWSZ + (row & 15) * PSTR + c0;
#pragma unroll
        for (int i = 0; i < 8; i++) {
            float4 v4 = *reinterpret_cast<const float4*>(src + i * 4);
            dst[i * 4 + 0] = f2tf(v4.x * 0.125f);
            dst[i * 4 + 1] = f2tf(v4.y * 0.125f);
            dst[i * 4 + 2] = f2tf(v4.z * 0.125f);
            dst[i * 4 + 3] = f2tf(v4.w * 0.125f);
        }
    }
    __syncthreads();

    uint32_t* Pw = Psm + wid * PWSZ;
    const uint32_t Pw_sb = fsm_sb + (FSM_P + wid * PWSZ) * 4;
    uint32_t qf[8][4];
#pragma unroll
    for (int s = 0; s < 8; s++) {
        const int kb = s * 8;
        ldsm4(qf[s], Pw_sb + 4 * (a_row_off * PSTR + kb + a_col_off));
    }
    __syncthreads();

    float m0 = -1e30f, m1 = -1e30f, l0 = 0.f, l1 = 0.f;
    float o[8][4];
#pragma unroll
    for (int nt = 0; nt < 8; nt++)
#pragma unroll
        for (int r = 0; r < 4; r++) o[nt][r] = 0.f;

    for (int kt = 0; kt < S_; kt += 64) {
        // ---- load K/V tiles (tf32) ----
        {
            const int row = t >> 2;
            const int c0  = (t & 3) * 16;
            const float* ks = Kh + (size_t)(kt + row) * HD_ + c0;
            const float* vs = Vh + (size_t)(kt + row) * HD_ + c0;
            uint32_t* kd = Ksm + row * KSTR + c0;
            uint32_t* vd = Vsm + row * VSTR + c0;
#pragma unroll
            for (int i = 0; i < 4; i++) {
                float4 kv = *reinterpret_cast<const float4*>(ks + i * 4);
                float4 vv = *reinterpret_cast<const float4*>(vs + i * 4);
                kd[i * 4 + 0] = f2tf(kv.x); kd[i * 4 + 1] = f2tf(kv.y);
                kd[i * 4 + 2] = f2tf(kv.z); kd[i * 4 + 3] = f2tf(kv.w);
                vd[i * 4 + 0] = f2tf(vv.x); vd[i * 4 + 1] = f2tf(vv.y);
                vd[i * 4 + 2] = f2tf(vv.z); vd[i * 4 + 3] = f2tf(vv.w);
            }
        }
        __syncthreads();

        // ---- scores = Q @ K^T (ldmatrix K b-frags) ----
        float sc[8][4];
#pragma unroll
        for (int nt = 0; nt < 8; nt++)
#pragma unroll
            for (int r = 0; r < 4; r++) sc[nt][r] = 0.f;
#pragma unroll
        for (int s = 0; s < 8; s++) {
            const int kb = s * 8;
            uint32_t bm[4][4];
#pragma unroll
            for (int p = 0; p < 4; p++)
                ldsm4(bm[p], Ksm_sb + 4 * ((p * 16 + b_row_off) * KSTR + kb + b_col_off));
#pragma unroll
            for (int nt = 0; nt < 8; nt++) {
                uint32_t bf[2] = { bm[nt >> 1][(nt & 1) * 2],
                                   bm[nt >> 1][(nt & 1) * 2 + 1] };
                mma8(sc[nt], qf[s], bf);
            }
        }

        // ---- online softmax ----
        float mx0 = -1e30f, mx1 = -1e30f;
#pragma unroll
        for (int nt = 0; nt < 8; nt++) {
            mx0 = fmaxf(mx0, fmaxf(sc[nt][0], sc[nt][1]));
            mx1 = fmaxf(mx1, fmaxf(sc[nt][2], sc[nt][3]));
        }
        mx0 = fmaxf(mx0, __shfl_xor_sync(0xffffffffu, mx0, 1));
        mx0 = fmaxf(mx0, __shfl_xor_sync(0xffffffffu, mx0, 2));
        mx1 = fmaxf(mx1, __shfl_xor_sync(0xffffffffu, mx1, 1));
        mx1 = fmaxf(mx1, __shfl_xor_sync(0xffffffffu, mx1, 2));
        const float mn0 = fmaxf(m0, mx0);
        const float mn1 = fmaxf(m1, mx1);
        const float a0 = __expf(m0 - mn0);
        const float a1 = __expf(m1 - mn1);
        m0 = mn0; m1 = mn1;
        float s0 = 0.f, s1 = 0.f;
#pragma unroll
        for (int nt = 0; nt < 8; nt++) {
            sc[nt][0] = __expf(sc[nt][0] - mn0);
            sc[nt][1] = __expf(sc[nt][1] - mn0);
            sc[nt][2] = __expf(sc[nt][2] - mn1);
            sc[nt][3] = __expf(sc[nt][3] - mn1);
            s0 += sc[nt][0] + sc[nt][1];
            s1 += sc[nt][2] + sc[nt][3];
        }
        s0 += __shfl_xor_sync(0xffffffffu, s0, 1);
        s0 += __shfl_xor_sync(0xffffffffu, s0, 2);
        s1 += __shfl_xor_sync(0xffffffffu, s1, 1);
        s1 += __shfl_xor_sync(0xffffffffu, s1, 2);
        l0 = l0 * a0 + s0;
        l1 = l1 * a1 + s1;
#pragma unroll
        for (int nt = 0; nt < 8; nt++) {
            o[nt][0] *= a0; o[nt][1] *= a0;
            o[nt][2] *= a1; o[nt][3] *= a1;
        }

        // ---- P (tf32) -> per-warp smem ----
#pragma unroll
        for (int nt = 0; nt < 8; nt++) {
            uint2 lo = make_uint2(f2tf(sc[nt][0]), f2tf(sc[nt][1]));
            uint2 hi = make_uint2(f2tf(sc[nt][2]), f2tf(sc[nt][3]));
            *reinterpret_cast<uint2*>(&Pw[grp * PSTR + nt * 8 + tg * 2])       = lo;
            *reinterpret_cast<uint2*>(&Pw[(grp + 8) * PSTR + nt * 8 + tg * 2]) = hi;
        }
        __syncwarp();

        // ---- O += P @ V (ldmatrix P a-frags) ----
#pragma unroll
        for (int s = 0; s < 8; s++) {
            const int kb = s * 8;
            uint32_t pf[4];
            ldsm4(pf, Pw_sb + 4 * (a_row_off * PSTR + kb + a_col_off));
#pragma unroll
            for (int nt = 0; nt < 8; nt++) {
                uint32_t bf[2];
                bf[0] = Vsm[(kb + tg) * VSTR + nt * 8 + grp];
                bf[1] = Vsm[(kb + tg + 4) * VSTR + nt * 8 + grp];
                mma8(o[nt], pf, bf);
            }
        }
        __syncthreads();
    }

    // ---- epilogue ----
    const int b = bh >> 4, h = bh & 15;
    const float inv0 = 1.0f / l0;
    const float inv1 = 1.0f / l1;
    const int r0 = qb + wid * 16 + grp;
    float* base0 = Og + ((size_t)b * S_ + r0) * D_ + h * HD_;
    float* base1 = base0 + (size_t)8 * D_;
#pragma unroll
    for (int nt = 0; nt < 8; nt++) {
        *reinterpret_cast<float2*>(base0 + nt * 8 + tg * 2) =
            make_float2(o[nt][0] * inv0, o[nt][1] * inv0);
        *reinterpret_cast<float2*>(base1 + nt * 8 + tg * 2) =
            make_float2(o[nt][2] * inv1, o[nt][3] * inv1);
    }
}

// ---------------------------------------------------------------------------
// LayerNorm over last dim (1024), one block per row
// ---------------------------------------------------------------------------
__global__ __launch_bounds__(256) void ln_kernel(const float* __restrict__ Hm,
                                                 const float* __restrict__ gamma,
                                                 const float* __restrict__ beta,
                                                 float* __restrict__ out) {
    const int row = blockIdx.x;
    const int t   = threadIdx.x;
    const float* hr = Hm + row * D_;
    float4 v = *reinterpret_cast<const float4*>(hr + t * 4);
    float s  = v.x + v.y + v.z + v.w;
    float ss = v.x * v.x + v.y * v.y + v.z * v.z + v.w * v.w;
#pragma unroll
    for (int msk = 16; msk > 0; msk >>= 1) {
        s  += __shfl_xor_sync(0xffffffffu, s, msk);
        ss += __shfl_xor_sync(0xffffffffu, ss, msk);
    }
    __shared__ float rs[8], rss[8];
    __shared__ float mu_s, rstd_s;
    int w = t >> 5;
    if ((t & 31) == 0) { rs[w] = s; rss[w] = ss; }
    __syncthreads();
    if (t == 0) {
        float S = 0.f, SS = 0.f;
#pragma unroll
        for (int i = 0; i < 8; i++) { S += rs[i]; SS += rss[i]; }
        float mu  = S * (1.0f / D_);
        float var = SS * (1.0f / D_) - mu * mu;
        mu_s = mu;
        rstd_s = rsqrtf(var + 1e-5f);
    }
    __syncthreads();
    float mu = mu_s, rstd = rstd_s;
    float4 g4 = *reinterpret_cast<const float4*>(gamma + t * 4);
    float4 b4 = *reinterpret_cast<const float4*>(beta + t * 4);
    float4 o4;
    o4.x = (v.x - mu) * rstd * g4.x + b4.x;
    o4.y = (v.y - mu) * rstd * g4.y + b4.y;
    o4.z = (v.z - mu) * rstd * g4.z + b4.z;
    o4.w = (v.w - mu) * rstd * g4.w + b4.w;
    *reinterpret_cast<float4*>(out + row * D_ + t * 4) = o4;
}

// ---------------------------------------------------------------------------
extern "C" void kernel_launch(void* const* d_in, const int* in_sizes, int n_in,
                              void* d_out, int out_size) {
    (void)in_sizes; (void)n_in; (void)out_size;
    const float* x     = (const float*)d_in[0];
    const float* wq    = (const float*)d_in[1];
    const float* bq    = (const float*)d_in[2];
    const float* wk    = (const float*)d_in[3];
    const float* bk    = (const float*)d_in[4];
    const float* wv    = (const float*)d_in[5];
    const float* bv    = (const float*)d_in[6];
    const float* wo    = (const float*)d_in[7];
    const float* bo    = (const float*)d_in[8];
    const float* gamma = (const float*)d_in[9];
    const float* beta  = (const float*)d_in[10];
    const float* pe    = (const float*)d_in[11];
    float* out = (float*)d_out;

    float *xp, *q, *k, *v, *o, *h, *wt;
    cudaGetSymbolAddress((void**)&xp, g_xp);
    cudaGetSymbolAddress((void**)&q,  g_q);
    cudaGetSymbolAddress((void**)&k,  g_k);
    cudaGetSymbolAddress((void**)&v,  g_v);
    cudaGetSymbolAddress((void**)&o,  g_o);
    cudaGetSymbolAddress((void**)&h,  g_h);
    cudaGetSymbolAddress((void**)&wt, g_wt4);

    cudaFuncSetAttribute(gemm_mma_kernel<0>,
                         cudaFuncAttributeMaxDynamicSharedMemorySize, GSM_TOTAL);
    cudaFuncSetAttribute(gemm_mma_kernel<1>,
                         cudaFuncAttributeMaxDynamicSharedMemorySize, GSM_TOTAL);
    cudaFuncSetAttribute(flash_mma_kernel,
                         cudaFuncAttributeMaxDynamicSharedMemorySize, FSM_TOTAL);

    // 1) x + pe
    pe_add_kernel<<<(MTOT * D_ / 4) / 256, 256>>>(x, pe);

    // 2) transpose all 4 weights -> g_wt4 [N,K]
    transpose4_kernel<<<dim3(32, 32, 4), dim3(32, 8)>>>(wq, wk, wv, wo);

    // 3) Q/K/V projections via tf32 mma.sync
    dim3 ggrid(D_ / 128, MTOT / 128);
    gemm_mma_kernel<0><<<ggrid, 256, GSM_TOTAL>>>(xp, wt + 0 * (size_t)D_ * D_, bq, nullptr, q);
    gemm_mma_kernel<0><<<ggrid, 256, GSM_TOTAL>>>(xp, wt + 1 * (size_t)D_ * D_, bk, nullptr, k);
    gemm_mma_kernel<0><<<ggrid, 256, GSM_TOTAL>>>(xp, wt + 2 * (size_t)D_ * D_, bv, nullptr, v);

    // 4) attention via tf32 mma.sync
    dim3 fgrid(S_ / 128, B_ * H_);
    flash_mma_kernel<<<fgrid, 256, FSM_TOTAL>>>(q, k, v, o);

    // 5) output projection + bias + residual
    gemm_mma_kernel<1><<<ggrid, 256, GSM_TOTAL>>>(o, wt + 3 * (size_t)D_ * D_, bo, xp, h);

    // 6) layernorm
    ln_kernel<<<MTOT, 256>>>(h, gamma, beta, out);
}

// round 6
// speedup vs baseline: 4.3540x; 1.3106x over previous
#include <cuda_runtime.h>
#include <cstdint>

#define B_   4
#define S_   2048
#define D_   1024
#define H_   16
#define HD_  64
#define MTOT (B_ * S_)   // 8192

// ---------------------------------------------------------------------------
// Scratch (module-load device globals; allocation-free at run time)
// ---------------------------------------------------------------------------
__device__ float g_xp [MTOT * D_];     // x + pe (tf32-rounded)
__device__ float g_q  [MTOT * D_];     // [B,H,S,HD] (tf32-rounded, pre-scaled)
__device__ float g_k  [MTOT * D_];
__device__ float g_v  [MTOT * D_];
__device__ float g_o  [MTOT * D_];     // attention out [B,S,D] (raw fp32)
__device__ float g_h  [MTOT * D_];     // pre-LN hidden
__device__ float g_wt4[4 * D_ * D_];   // 4 transposed weights [N,K] (tf32-rounded)

// ---------------------------------------------------------------------------
__device__ __forceinline__ uint32_t f2tf(float f) {
    uint32_t u;
    asm("cvt.rna.tf32.f32 %0, %1;" : "=r"(u) : "f"(f));
    return u;
}
__device__ __forceinline__ float f2tf_f(float f) {
    return __uint_as_float(f2tf(f));
}
__device__ __forceinline__ void mma8(float c[4], const uint32_t a[4], const uint32_t b[2]) {
    asm volatile("mma.sync.aligned.m16n8k8.row.col.f32.tf32.tf32.f32 "
                 "{%0,%1,%2,%3}, {%4,%5,%6,%7}, {%8,%9}, {%0,%1,%2,%3};"
                 : "+f"(c[0]), "+f"(c[1]), "+f"(c[2]), "+f"(c[3])
                 : "r"(a[0]), "r"(a[1]), "r"(a[2]), "r"(a[3]), "r"(b[0]), "r"(b[1]));
}
__device__ __forceinline__ uint32_t cvta_smem(const void* p) {
    uint32_t a;
    asm("{ .reg .u64 t; cvta.to.shared.u64 t, %1; cvt.u32.u64 %0, t; }" : "=r"(a) : "l"(p));
    return a;
}
__device__ __forceinline__ void ldsm4(uint32_t r[4], uint32_t addr) {
    asm volatile("ldmatrix.sync.aligned.m8n8.x4.shared.b16 {%0,%1,%2,%3}, [%4];"
                 : "=r"(r[0]), "=r"(r[1]), "=r"(r[2]), "=r"(r[3]) : "r"(addr));
}
#define CP_ASYNC16(dst, src) \
    asm volatile("cp.async.cg.shared.global [%0], [%1], 16;" :: "r"(dst), "l"(src) : "memory")
#define CP_COMMIT() asm volatile("cp.async.commit_group;" ::: "memory")
#define CP_WAIT0()  asm volatile("cp.async.wait_group 0;" ::: "memory")

// ---------------------------------------------------------------------------
// x + positional encoding -> g_xp (tf32-rounded)
// ---------------------------------------------------------------------------
__global__ __launch_bounds__(256) void pe_add_kernel(const float* __restrict__ x,
                                                     const float* __restrict__ pe) {
    int i = blockIdx.x * 256 + threadIdx.x;
    int row = i >> 8;
    int s   = row & (S_ - 1);
    int d4  = i & 255;
    float4 a = reinterpret_cast<const float4*>(x)[i];
    float4 p = reinterpret_cast<const float4*>(pe)[s * 256 + d4];
    a.x = f2tf_f(a.x + p.x); a.y = f2tf_f(a.y + p.y);
    a.z = f2tf_f(a.z + p.z); a.w = f2tf_f(a.w + p.w);
    reinterpret_cast<float4*>(g_xp)[i] = a;
}

// ---------------------------------------------------------------------------
// Batched transpose of all 4 weights: wt4[z][n][k] = tf32(Wz[k][n])
// ---------------------------------------------------------------------------
__global__ __launch_bounds__(256) void transpose4_kernel(const float* __restrict__ w0,
                                                         const float* __restrict__ w1,
                                                         const float* __restrict__ w2,
                                                         const float* __restrict__ w3) {
    __shared__ float tile[32][33];
    const float* W = (blockIdx.z == 0) ? w0 : (blockIdx.z == 1) ? w1
                   : (blockIdx.z == 2) ? w2 : w3;
    float* Wt = g_wt4 + (size_t)blockIdx.z * D_ * D_;
    int bx = blockIdx.x * 32, by = blockIdx.y * 32;
#pragma unroll
    for (int i = 0; i < 32; i += 8)
        tile[threadIdx.y + i][threadIdx.x] = W[(by + threadIdx.y + i) * D_ + bx + threadIdx.x];
    __syncthreads();
#pragma unroll
    for (int i = 0; i < 32; i += 8)
        Wt[(bx + threadIdx.y + i) * D_ + by + threadIdx.x] =
            f2tf_f(tile[threadIdx.x][threadIdx.y + i]);
}

// ---------------------------------------------------------------------------
// tf32 mma.sync GEMM: 4 warps, CTA 128x128, warp tile 64x64, cp.async loads.
//   MODE 0: scatter to [B,H,S,HD], out = tf32((acc+bias)*scale)
//   MODE 1: [M,N] + bias + residual (fp32)
// SMEM per buffer: A 128x36, B 128x36 (tf32 words). Double buffered.
// ---------------------------------------------------------------------------
#define SSTR 36
#define ABYTES (128 * SSTR * 4)
#define BUFB   (2 * ABYTES)
#define GSM_TOTAL (2 * BUFB)

template <int MODE>
__global__ __launch_bounds__(128, 2) void gemm_mma_kernel(const float* __restrict__ A,
                                                          const float* __restrict__ Wt,
                                                          const float* __restrict__ bias,
                                                          const float* __restrict__ resid,
                                                          float* __restrict__ out,
                                                          float scale) {
    extern __shared__ uint32_t smem[];
    const uint32_t sb = cvta_smem(smem);
    const int t    = threadIdx.x;
    const int wid  = t >> 5;
    const int lane = t & 31;
    const int grp  = lane >> 2;
    const int tg   = lane & 3;
    const int wm   = wid & 1;
    const int wn   = wid >> 1;
    const int mBase = blockIdx.y * 128;
    const int nBase = blockIdx.x * 128;

    const int lm  = lane & 7;
    const int sel = lane >> 3;
    const int a_row_off = lm + ((sel & 1) ? 8 : 0);
    const int a_col_off = (sel & 2) ? 4 : 0;
    const int b_row_off = lm + ((sel & 2) ? 8 : 0);
    const int b_col_off = (sel & 1) ? 4 : 0;

    float acc[4][8][4];
#pragma unroll
    for (int i = 0; i < 4; i++)
#pragma unroll
        for (int j = 0; j < 8; j++)
#pragma unroll
            for (int r = 0; r < 4; r++) acc[i][j][r] = 0.f;

    auto issue = [&](int c, int buf) {
        const uint32_t base = sb + buf * BUFB;
#pragma unroll
        for (int ii = 0; ii < 8; ii++) {
            const int i   = t + 128 * ii;      // 0..1023
            const int row = i >> 3;
            const int c4  = i & 7;
            const float* sa = A  + (size_t)(mBase + row) * D_ + c * 32 + c4 * 4;
            const float* sw = Wt + (size_t)(nBase + row) * D_ + c * 32 + c4 * 4;
            CP_ASYNC16(base + 4 * (row * SSTR + c4 * 4), sa);
            CP_ASYNC16(base + ABYTES + 4 * (row * SSTR + c4 * 4), sw);
        }
        CP_COMMIT();
    };

    auto compute = [&](int buf) {
        const uint32_t sA = sb + buf * BUFB;
        const uint32_t sB = sA + ABYTES;
#pragma unroll
        for (int s = 0; s < 4; s++) {
            const int kb = s * 8;
            uint32_t af[4][4], bm[4][4];
#pragma unroll
            for (int mf = 0; mf < 4; mf++)
                ldsm4(af[mf], sA + 4 * ((wm * 64 + mf * 16 + a_row_off) * SSTR + kb + a_col_off));
#pragma unroll
            for (int p = 0; p < 4; p++)
                ldsm4(bm[p], sB + 4 * ((wn * 64 + p * 16 + b_row_off) * SSTR + kb + b_col_off));
#pragma unroll
            for (int mf = 0; mf < 4; mf++)
#pragma unroll
                for (int nf = 0; nf < 8; nf++) {
                    uint32_t bf[2] = { bm[nf >> 1][(nf & 1) * 2],
                                       bm[nf >> 1][(nf & 1) * 2 + 1] };
                    mma8(acc[mf][nf], af[mf], bf);
                }
        }
    };

    issue(0, 0);
    for (int c = 0; c < 32; c++) {
        CP_WAIT0();
        __syncthreads();
        if (c < 31) issue(c + 1, (c + 1) & 1);
        compute(c & 1);
    }

    // ---- epilogue ----
    float2 bz[8];
#pragma unroll
    for (int nf = 0; nf < 8; nf++)
        bz[nf] = *reinterpret_cast<const float2*>(bias + nBase + wn * 64 + nf * 8 + tg * 2);

#pragma unroll
    for (int mf = 0; mf < 4; mf++) {
#pragma unroll
        for (int half = 0; half < 2; half++) {
            const int gm = mBase + wm * 64 + mf * 16 + grp + half * 8;
            if (MODE == 0) {
                const int h = (nBase + wn * 64) >> 6;
                const int b = gm >> 11;
                const int s = gm & (S_ - 1);
                float* dst = out + (((size_t)(b * H_ + h)) * S_ + s) * HD_;
#pragma unroll
                for (int nf = 0; nf < 8; nf++) {
                    float2 v2;
                    v2.x = f2tf_f((acc[mf][nf][half * 2 + 0] + bz[nf].x) * scale);
                    v2.y = f2tf_f((acc[mf][nf][half * 2 + 1] + bz[nf].y) * scale);
                    *reinterpret_cast<float2*>(dst + nf * 8 + tg * 2) = v2;
                }
            } else {
                const float* rr = resid + (size_t)gm * D_;
                float* orow     = out   + (size_t)gm * D_;
#pragma unroll
                for (int nf = 0; nf < 8; nf++) {
                    const int n = nBase + wn * 64 + nf * 8 + tg * 2;
                    float2 r2 = *reinterpret_cast<const float2*>(rr + n);
                    float2 v2;
                    v2.x = acc[mf][nf][half * 2 + 0] + bz[nf].x + r2.x;
                    v2.y = acc[mf][nf][half * 2 + 1] + bz[nf].y + r2.y;
                    *reinterpret_cast<float2*>(orow + n) = v2;
                }
            }
        }
    }
}

// ---------------------------------------------------------------------------
// Flash attention: 4 warps, 32 queries/warp (mf=2), q-tile 128, keys 64/tile.
// Q resident in smem (pre-scaled tf32 from gemm<0>); K/V/Q via cp.async.
// SMEM (u32): Q 128x68 | K 64x68 | V 64x72 | P 4x(32x68)
// ---------------------------------------------------------------------------
#define QSTR 68
#define KSTR 68
#define VSTR 72
#define PSTR 68
#define FQ_OFF 0
#define FK_OFF (128 * QSTR)                 // 8704
#define FV_OFF (FK_OFF + 64 * KSTR)         // 13056
#define FP_OFF (FV_OFF + 64 * VSTR)         // 17664
#define FSM_U32 (FP_OFF + 4 * 32 * PSTR)    // 26368
#define FSM_TOTAL (FSM_U32 * 4)             // 105472 B

__global__ __launch_bounds__(128, 2) void flash_mma_kernel(const float* __restrict__ Qg,
                                                           const float* __restrict__ Kg,
                                                           const float* __restrict__ Vg,
                                                           float* __restrict__ Og) {
    extern __shared__ uint32_t fsm[];
    const uint32_t sb  = cvta_smem(fsm);
    const uint32_t sbQ = sb + FQ_OFF * 4;
    const uint32_t sbK = sb + FK_OFF * 4;
    const uint32_t sbP = sb + FP_OFF * 4;
    uint32_t* Vsm = fsm + FV_OFF;
    uint32_t* Psm = fsm + FP_OFF;

    const int t    = threadIdx.x;
    const int wid  = t >> 5;
    const int lane = t & 31;
    const int grp  = lane >> 2;
    const int tg   = lane & 3;
    const int bh   = blockIdx.y;
    const int qb   = blockIdx.x * 128;

    const int lm  = lane & 7;
    const int sel = lane >> 3;
    const int a_row_off = lm + ((sel & 1) ? 8 : 0);
    const int a_col_off = (sel & 2) ? 4 : 0;
    const int b_row_off = lm + ((sel & 2) ? 8 : 0);
    const int b_col_off = (sel & 1) ? 4 : 0;

    const float* Qh = Qg + (size_t)bh * S_ * HD_;
    const float* Kh = Kg + (size_t)bh * S_ * HD_;
    const float* Vh = Vg + (size_t)bh * S_ * HD_;

    // ---- Q tile -> smem via cp.async (already tf32 + scaled) ----
#pragma unroll
    for (int ii = 0; ii < 16; ii++) {
        const int i   = t + 128 * ii;       // 0..2047 float4s
        const int row = i >> 4;
        const int c4  = i & 15;
        CP_ASYNC16(sbQ + 4 * (row * QSTR + c4 * 4),
                   Qh + (size_t)(qb + row) * HD_ + c4 * 4);
    }
    CP_COMMIT();

    uint32_t* Pw = Psm + wid * 32 * PSTR;
    const uint32_t Pw_sb = sbP + (wid * 32 * PSTR) * 4;

    float m[2][2], l[2][2];
#pragma unroll
    for (int i = 0; i < 2; i++) { m[i][0] = m[i][1] = -1e30f; l[i][0] = l[i][1] = 0.f; }
    float o[2][8][4];
#pragma unroll
    for (int mf = 0; mf < 2; mf++)
#pragma unroll
        for (int nt = 0; nt < 8; nt++)
#pragma unroll
            for (int r = 0; r < 4; r++) o[mf][nt][r] = 0.f;

    for (int kt = 0; kt < S_; kt += 64) {
        // ---- K/V tile via cp.async (Ksm/Vsm free: barrier at end of prev iter) ----
#pragma unroll
        for (int ii = 0; ii < 8; ii++) {
            const int i   = t + 128 * ii;   // 0..1023
            const int row = i >> 4;
            const int c4  = i & 15;
            CP_ASYNC16(sbK + 4 * (row * KSTR + c4 * 4),
                       Kh + (size_t)(kt + row) * HD_ + c4 * 4);
            CP_ASYNC16(sb + 4 * (FV_OFF + row * VSTR + c4 * 4),
                       Vh + (size_t)(kt + row) * HD_ + c4 * 4);
        }
        CP_COMMIT();
        CP_WAIT0();
        __syncthreads();

        // ---- scores = Q @ K^T ----
        float sc[2][8][4];
#pragma unroll
        for (int mf = 0; mf < 2; mf++)
#pragma unroll
            for (int nt = 0; nt < 8; nt++)
#pragma unroll
                for (int r = 0; r < 4; r++) sc[mf][nt][r] = 0.f;
#pragma unroll
        for (int s = 0; s < 8; s++) {
            const int kb = s * 8;
            uint32_t qf0[4], qf1[4], bm[4][4];
            ldsm4(qf0, sbQ + 4 * ((wid * 32 +  0 + a_row_off) * QSTR + kb + a_col_off));
            ldsm4(qf1, sbQ + 4 * ((wid * 32 + 16 + a_row_off) * QSTR + kb + a_col_off));
#pragma unroll
            for (int p = 0; p < 4; p++)
                ldsm4(bm[p], sbK + 4 * ((p * 16 + b_row_off) * KSTR + kb + b_col_off));
#pragma unroll
            for (int nt = 0; nt < 8; nt++) {
                uint32_t bf[2] = { bm[nt >> 1][(nt & 1) * 2],
                                   bm[nt >> 1][(nt & 1) * 2 + 1] };
                mma8(sc[0][nt], qf0, bf);
                mma8(sc[1][nt], qf1, bf);
            }
        }

        // ---- online softmax per m-frag ----
#pragma unroll
        for (int mf = 0; mf < 2; mf++) {
            float mx0 = -1e30f, mx1 = -1e30f;
#pragma unroll
            for (int nt = 0; nt < 8; nt++) {
                mx0 = fmaxf(mx0, fmaxf(sc[mf][nt][0], sc[mf][nt][1]));
                mx1 = fmaxf(mx1, fmaxf(sc[mf][nt][2], sc[mf][nt][3]));
            }
            mx0 = fmaxf(mx0, __shfl_xor_sync(0xffffffffu, mx0, 1));
            mx0 = fmaxf(mx0, __shfl_xor_sync(0xffffffffu, mx0, 2));
            mx1 = fmaxf(mx1, __shfl_xor_sync(0xffffffffu, mx1, 1));
            mx1 = fmaxf(mx1, __shfl_xor_sync(0xffffffffu, mx1, 2));
            const float mn0 = fmaxf(m[mf][0], mx0);
            const float mn1 = fmaxf(m[mf][1], mx1);
            const float a0 = __expf(m[mf][0] - mn0);
            const float a1 = __expf(m[mf][1] - mn1);
            m[mf][0] = mn0; m[mf][1] = mn1;
            float s0 = 0.f, s1 = 0.f;
#pragma unroll
            for (int nt = 0; nt < 8; nt++) {
                sc[mf][nt][0] = __expf(sc[mf][nt][0] - mn0);
                sc[mf][nt][1] = __expf(sc[mf][nt][1] - mn0);
                sc[mf][nt][2] = __expf(sc[mf][nt][2] - mn1);
                sc[mf][nt][3] = __expf(sc[mf][nt][3] - mn1);
                s0 += sc[mf][nt][0] + sc[mf][nt][1];
                s1 += sc[mf][nt][2] + sc[mf][nt][3];
            }
            s0 += __shfl_xor_sync(0xffffffffu, s0, 1);
            s0 += __shfl_xor_sync(0xffffffffu, s0, 2);
            s1 += __shfl_xor_sync(0xffffffffu, s1, 1);
            s1 += __shfl_xor_sync(0xffffffffu, s1, 2);
            l[mf][0] = l[mf][0] * a0 + s0;
            l[mf][1] = l[mf][1] * a1 + s1;
#pragma unroll
            for (int nt = 0; nt < 8; nt++) {
                o[mf][nt][0] *= a0; o[mf][nt][1] *= a0;
                o[mf][nt][2] *= a1; o[mf][nt][3] *= a1;
            }
            // store P (tf32) to per-warp region
#pragma unroll
            for (int nt = 0; nt < 8; nt++) {
                uint2 lo = make_uint2(f2tf(sc[mf][nt][0]), f2tf(sc[mf][nt][1]));
                uint2 hi = make_uint2(f2tf(sc[mf][nt][2]), f2tf(sc[mf][nt][3]));
                *reinterpret_cast<uint2*>(&Pw[(mf * 16 + grp) * PSTR + nt * 8 + tg * 2])     = lo;
                *reinterpret_cast<uint2*>(&Pw[(mf * 16 + grp + 8) * PSTR + nt * 8 + tg * 2]) = hi;
            }
        }
        __syncwarp();

        // ---- O += P @ V ----
#pragma unroll
        for (int s = 0; s < 8; s++) {
            const int kb = s * 8;
            uint32_t pf0[4], pf1[4];
            ldsm4(pf0, Pw_sb + 4 * (( 0 + a_row_off) * PSTR + kb + a_col_off));
            ldsm4(pf1, Pw_sb + 4 * ((16 + a_row_off) * PSTR + kb + a_col_off));
#pragma unroll
            for (int nt = 0; nt < 8; nt++) {
                uint32_t bf[2];
                bf[0] = Vsm[(kb + tg) * VSTR + nt * 8 + grp];
                bf[1] = Vsm[(kb + tg + 4) * VSTR + nt * 8 + grp];
                mma8(o[0][nt], pf0, bf);
                mma8(o[1][nt], pf1, bf);
            }
        }
        __syncthreads();
    }

    // ---- epilogue ----
    const int b = bh >> 4, h = bh & 15;
#pragma unroll
    for (int mf = 0; mf < 2; mf++) {
        const float inv0 = 1.0f / l[mf][0];
        const float inv1 = 1.0f / l[mf][1];
        const int r0 = qb + wid * 32 + mf * 16 + grp;
        float* base0 = Og + ((size_t)b * S_ + r0) * D_ + h * HD_;
        float* base1 = base0 + (size_t)8 * D_;
#pragma unroll
        for (int nt = 0; nt < 8; nt++) {
            *reinterpret_cast<float2*>(base0 + nt * 8 + tg * 2) =
                make_float2(o[mf][nt][0] * inv0, o[mf][nt][1] * inv0);
            *reinterpret_cast<float2*>(base1 + nt * 8 + tg * 2) =
                make_float2(o[mf][nt][2] * inv1, o[mf][nt][3] * inv1);
        }
    }
}

// ---------------------------------------------------------------------------
// LayerNorm over last dim (1024), one block per row
// ---------------------------------------------------------------------------
__global__ __launch_bounds__(256) void ln_kernel(const float* __restrict__ Hm,
                                                 const float* __restrict__ gamma,
                                                 const float* __restrict__ beta,
                                                 float* __restrict__ out) {
    const int row = blockIdx.x;
    const int t   = threadIdx.x;
    const float* hr = Hm + row * D_;
    float4 v = *reinterpret_cast<const float4*>(hr + t * 4);
    float s  = v.x + v.y + v.z + v.w;
    float ss = v.x * v.x + v.y * v.y + v.z * v.z + v.w * v.w;
#pragma unroll
    for (int msk = 16; msk > 0; msk >>= 1) {
        s  += __shfl_xor_sync(0xffffffffu, s, msk);
        ss += __shfl_xor_sync(0xffffffffu, ss, msk);
    }
    __shared__ float rs[8], rss[8];
    __shared__ float mu_s, rstd_s;
    int w = t >> 5;
    if ((t & 31) == 0) { rs[w] = s; rss[w] = ss; }
    __syncthreads();
    if (t == 0) {
        float S = 0.f, SS = 0.f;
#pragma unroll
        for (int i = 0; i < 8; i++) { S += rs[i]; SS += rss[i]; }
        float mu  = S * (1.0f / D_);
        float var = SS * (1.0f / D_) - mu * mu;
        mu_s = mu;
        rstd_s = rsqrtf(var + 1e-5f);
    }
    __syncthreads();
    float mu = mu_s, rstd = rstd_s;
    float4 g4 = *reinterpret_cast<const float4*>(gamma + t * 4);
    float4 b4 = *reinterpret_cast<const float4*>(beta + t * 4);
    float4 o4;
    o4.x = (v.x - mu) * rstd * g4.x + b4.x;
    o4.y = (v.y - mu) * rstd * g4.y + b4.y;
    o4.z = (v.z - mu) * rstd * g4.z + b4.z;
    o4.w = (v.w - mu) * rstd * g4.w + b4.w;
    *reinterpret_cast<float4*>(out + row * D_ + t * 4) = o4;
}

// ---------------------------------------------------------------------------
extern "C" void kernel_launch(void* const* d_in, const int* in_sizes, int n_in,
                              void* d_out, int out_size) {
    (void)in_sizes; (void)n_in; (void)out_size;
    const float* x     = (const float*)d_in[0];
    const float* wq    = (const float*)d_in[1];
    const float* bq    = (const float*)d_in[2];
    const float* wk    = (const float*)d_in[3];
    const float* bk    = (const float*)d_in[4];
    const float* wv    = (const float*)d_in[5];
    const float* bv    = (const float*)d_in[6];
    const float* wo    = (const float*)d_in[7];
    const float* bo    = (const float*)d_in[8];
    const float* gamma = (const float*)d_in[9];
    const float* beta  = (const float*)d_in[10];
    const float* pe    = (const float*)d_in[11];
    float* out = (float*)d_out;

    float *xp, *q, *k, *v, *o, *h, *wt;
    cudaGetSymbolAddress((void**)&xp, g_xp);
    cudaGetSymbolAddress((void**)&q,  g_q);
    cudaGetSymbolAddress((void**)&k,  g_k);
    cudaGetSymbolAddress((void**)&v,  g_v);
    cudaGetSymbolAddress((void**)&o,  g_o);
    cudaGetSymbolAddress((void**)&h,  g_h);
    cudaGetSymbolAddress((void**)&wt, g_wt4);

    cudaFuncSetAttribute(gemm_mma_kernel<0>,
                         cudaFuncAttributeMaxDynamicSharedMemorySize, GSM_TOTAL);
    cudaFuncSetAttribute(gemm_mma_kernel<1>,
                         cudaFuncAttributeMaxDynamicSharedMemorySize, GSM_TOTAL);
    cudaFuncSetAttribute(flash_mma_kernel,
                         cudaFuncAttributeMaxDynamicSharedMemorySize, FSM_TOTAL);

    // 1) x + pe (tf32-rounded)
    pe_add_kernel<<<(MTOT * D_ / 4) / 256, 256>>>(x, pe);

    // 2) transpose + round all 4 weights -> g_wt4 [N,K]
    transpose4_kernel<<<dim3(32, 32, 4), dim3(32, 8)>>>(wq, wk, wv, wo);

    // 3) Q/K/V projections (Q pre-scaled by 1/sqrt(HD))
    dim3 ggrid(D_ / 128, MTOT / 128);
    gemm_mma_kernel<0><<<ggrid, 128, GSM_TOTAL>>>(xp, wt + 0 * (size_t)D_ * D_, bq, nullptr, q, 0.125f);
    gemm_mma_kernel<0><<<ggrid, 128, GSM_TOTAL>>>(xp, wt + 1 * (size_t)D_ * D_, bk, nullptr, k, 1.0f);
    gemm_mma_kernel<0><<<ggrid, 128, GSM_TOTAL>>>(xp, wt + 2 * (size_t)D_ * D_, bv, nullptr, v, 1.0f);

    // 4) attention
    dim3 fgrid(S_ / 128, B_ * H_);
    flash_mma_kernel<<<fgrid, 128, FSM_TOTAL>>>(q, k, v, o);

    // 5) output projection + bias + residual
    gemm_mma_kernel<1><<<ggrid, 128, GSM_TOTAL>>>(o, wt + 3 * (size_t)D_ * D_, bo, xp, h, 1.0f);

    // 6) layernorm
    ln_kernel<<<MTOT, 256>>>(h, gamma, beta, out);
}

// round 9
// speedup vs baseline: 4.4803x; 1.0290x over previous
#include <cuda_runtime.h>
#include <cstdint>

#define B_   4
#define S_   2048
#define D_   1024
#define H_   16
#define HD_  64
#define MTOT (B_ * S_)   // 8192

// ---------------------------------------------------------------------------
// Scratch (module-load device globals; allocation-free at run time)
// ---------------------------------------------------------------------------
__device__ float g_xp [MTOT * D_];     // x + pe (tf32-rounded)
__device__ float g_q  [MTOT * D_];     // [B,H,S,HD] (tf32-rounded, pre-scaled)
__device__ float g_k  [MTOT * D_];
__device__ float g_v  [MTOT * D_];
__device__ float g_o  [MTOT * D_];     // attention out [B,S,D] (raw fp32)
__device__ float g_h  [MTOT * D_];     // pre-LN hidden
__device__ float g_wt4[4 * D_ * D_];   // 4 transposed weights [N,K] (tf32-rounded)

// ---------------------------------------------------------------------------
__device__ __forceinline__ uint32_t f2tf(float f) {
    uint32_t u;
    asm("cvt.rna.tf32.f32 %0, %1;" : "=r"(u) : "f"(f));
    return u;
}
__device__ __forceinline__ float f2tf_f(float f) {
    return __uint_as_float(f2tf(f));
}
__device__ __forceinline__ void mma8(float c[4], const uint32_t a[4], const uint32_t b[2]) {
    asm volatile("mma.sync.aligned.m16n8k8.row.col.f32.tf32.tf32.f32 "
                 "{%0,%1,%2,%3}, {%4,%5,%6,%7}, {%8,%9}, {%0,%1,%2,%3};"
                 : "+f"(c[0]), "+f"(c[1]), "+f"(c[2]), "+f"(c[3])
                 : "r"(a[0]), "r"(a[1]), "r"(a[2]), "r"(a[3]), "r"(b[0]), "r"(b[1]));
}
__device__ __forceinline__ uint32_t cvta_smem(const void* p) {
    uint32_t a;
    asm("{ .reg .u64 t; cvta.to.shared.u64 t, %1; cvt.u32.u64 %0, t; }" : "=r"(a) : "l"(p));
    return a;
}
__device__ __forceinline__ void ldsm4(uint32_t r[4], uint32_t addr) {
    asm volatile("ldmatrix.sync.aligned.m8n8.x4.shared.b16 {%0,%1,%2,%3}, [%4];"
                 : "=r"(r[0]), "=r"(r[1]), "=r"(r[2]), "=r"(r[3]) : "r"(addr));
}
#define CP_ASYNC16(dst, src) \
    asm volatile("cp.async.cg.shared.global [%0], [%1], 16;" :: "r"(dst), "l"(src) : "memory")
#define CP_COMMIT() asm volatile("cp.async.commit_group;" ::: "memory")
#define CP_WAIT0()  asm volatile("cp.async.wait_group 0;" ::: "memory")
#define CP_WAIT1()  asm volatile("cp.async.wait_group 1;" ::: "memory")

// ---------------------------------------------------------------------------
// x + positional encoding -> g_xp (tf32-rounded)
// ---------------------------------------------------------------------------
__global__ __launch_bounds__(256) void pe_add_kernel(const float* __restrict__ x,
                                                     const float* __restrict__ pe) {
    int i = blockIdx.x * 256 + threadIdx.x;
    int row = i >> 8;
    int s   = row & (S_ - 1);
    int d4  = i & 255;
    float4 a = reinterpret_cast<const float4*>(x)[i];
    float4 p = reinterpret_cast<const float4*>(pe)[s * 256 + d4];
    a.x = f2tf_f(a.x + p.x); a.y = f2tf_f(a.y + p.y);
    a.z = f2tf_f(a.z + p.z); a.w = f2tf_f(a.w + p.w);
    reinterpret_cast<float4*>(g_xp)[i] = a;
}

// ---------------------------------------------------------------------------
// Batched transpose of all 4 weights: wt4[z][n][k] = tf32(Wz[k][n])
// ---------------------------------------------------------------------------
__global__ __launch_bounds__(256) void transpose4_kernel(const float* __restrict__ w0,
                                                         const float* __restrict__ w1,
                                                         const float* __restrict__ w2,
                                                         const float* __restrict__ w3) {
    __shared__ float tile[32][33];
    const float* W = (blockIdx.z == 0) ? w0 : (blockIdx.z == 1) ? w1
                   : (blockIdx.z == 2) ? w2 : w3;
    float* Wt = g_wt4 + (size_t)blockIdx.z * D_ * D_;
    int bx = blockIdx.x * 32, by = blockIdx.y * 32;
#pragma unroll
    for (int i = 0; i < 32; i += 8)
        tile[threadIdx.y + i][threadIdx.x] = W[(by + threadIdx.y + i) * D_ + bx + threadIdx.x];
    __syncthreads();
#pragma unroll
    for (int i = 0; i < 32; i += 8)
        Wt[(bx + threadIdx.y + i) * D_ + by + threadIdx.x] =
            f2tf_f(tile[threadIdx.x][threadIdx.y + i]);
}

// ---------------------------------------------------------------------------
// tf32 mma.sync GEMM: 4 warps, CTA 128x128, warp tile 64x64.
// 3-stage cp.async pipeline (wait_group 1 -> two chunks always in flight).
// ---------------------------------------------------------------------------
#define SSTR 36
#define ABYTES (128 * SSTR * 4)
#define BUFB   (2 * ABYTES)
#define NSTAGE 3
#define GSM_TOTAL (NSTAGE * BUFB)

template <int MODE>
__global__ __launch_bounds__(128, 2) void gemm_mma_kernel(const float* __restrict__ A,
                                                          const float* __restrict__ Wt,
                                                          const float* __restrict__ bias,
                                                          const float* __restrict__ resid,
                                                          float* __restrict__ out,
                                                          float scale) {
    extern __shared__ uint32_t smem[];
    const uint32_t sb = cvta_smem(smem);
    const int t    = threadIdx.x;
    const int wid  = t >> 5;
    const int lane = t & 31;
    const int grp  = lane >> 2;
    const int tg   = lane & 3;
    const int wm   = wid & 1;
    const int wn   = wid >> 1;
    const int mBase = blockIdx.y * 128;
    const int nBase = blockIdx.x * 128;

    const int lm  = lane & 7;
    const int sel = lane >> 3;
    const int a_row_off = lm + ((sel & 1) ? 8 : 0);
    const int a_col_off = (sel & 2) ? 4 : 0;
    const int b_row_off = lm + ((sel & 2) ? 8 : 0);
    const int b_col_off = (sel & 1) ? 4 : 0;

    float acc[4][8][4];
#pragma unroll
    for (int i = 0; i < 4; i++)
#pragma unroll
        for (int j = 0; j < 8; j++)
#pragma unroll
            for (int r = 0; r < 4; r++) acc[i][j][r] = 0.f;

    auto issue = [&](int c, int buf) {
        const uint32_t base = sb + buf * BUFB;
#pragma unroll
        for (int ii = 0; ii < 8; ii++) {
            const int i   = t + 128 * ii;      // 0..1023
            const int row = i >> 3;
            const int c4  = i & 7;
            const float* sa = A  + (size_t)(mBase + row) * D_ + c * 32 + c4 * 4;
            const float* sw = Wt + (size_t)(nBase + row) * D_ + c * 32 + c4 * 4;
            CP_ASYNC16(base + 4 * (row * SSTR + c4 * 4), sa);
            CP_ASYNC16(base + ABYTES + 4 * (row * SSTR + c4 * 4), sw);
        }
        CP_COMMIT();
    };

    auto compute = [&](int buf) {
        const uint32_t sA = sb + buf * BUFB;
        const uint32_t sB = sA + ABYTES;
#pragma unroll
        for (int s = 0; s < 4; s++) {
            const int kb = s * 8;
            uint32_t af[4][4], bm[4][4];
#pragma unroll
            for (int mf = 0; mf < 4; mf++)
                ldsm4(af[mf], sA + 4 * ((wm * 64 + mf * 16 + a_row_off) * SSTR + kb + a_col_off));
#pragma unroll
            for (int p = 0; p < 4; p++)
                ldsm4(bm[p], sB + 4 * ((wn * 64 + p * 16 + b_row_off) * SSTR + kb + b_col_off));
#pragma unroll
            for (int mf = 0; mf < 4; mf++)
#pragma unroll
                for (int nf = 0; nf < 8; nf++) {
                    uint32_t bf[2] = { bm[nf >> 1][(nf & 1) * 2],
                                       bm[nf >> 1][(nf & 1) * 2 + 1] };
                    mma8(acc[mf][nf], af[mf], bf);
                }
        }
    };

    issue(0, 0);
    issue(1, 1);
    int buf = 0, nbuf = 2;
#pragma unroll 1
    for (int c = 0; c < 32; c++) {
        if (c < 30) CP_WAIT1(); else CP_WAIT0();
        __syncthreads();
        if (c + 2 < 32) issue(c + 2, nbuf);
        compute(buf);
        buf  = (buf == 2)  ? 0 : buf + 1;
        nbuf = (nbuf == 2) ? 0 : nbuf + 1;
    }

    // ---- epilogue ----
    float2 bz[8];
#pragma unroll
    for (int nf = 0; nf < 8; nf++)
        bz[nf] = *reinterpret_cast<const float2*>(bias + nBase + wn * 64 + nf * 8 + tg * 2);

#pragma unroll
    for (int mf = 0; mf < 4; mf++) {
#pragma unroll
        for (int half = 0; half < 2; half++) {
            const int gm = mBase + wm * 64 + mf * 16 + grp + half * 8;
            if (MODE == 0) {
                const int h = (nBase + wn * 64) >> 6;
                const int b = gm >> 11;
                const int s = gm & (S_ - 1);
                float* dst = out + (((size_t)(b * H_ + h)) * S_ + s) * HD_;
#pragma unroll
                for (int nf = 0; nf < 8; nf++) {
                    float2 v2;
                    v2.x = f2tf_f((acc[mf][nf][half * 2 + 0] + bz[nf].x) * scale);
                    v2.y = f2tf_f((acc[mf][nf][half * 2 + 1] + bz[nf].y) * scale);
                    *reinterpret_cast<float2*>(dst + nf * 8 + tg * 2) = v2;
                }
            } else {
                const float* rr = resid + (size_t)gm * D_;
                float* orow     = out   + (size_t)gm * D_;
#pragma unroll
                for (int nf = 0; nf < 8; nf++) {
                    const int n = nBase + wn * 64 + nf * 8 + tg * 2;
                    float2 r2 = *reinterpret_cast<const float2*>(rr + n);
                    float2 v2;
                    v2.x = acc[mf][nf][half * 2 + 0] + bz[nf].x + r2.x;
                    v2.y = acc[mf][nf][half * 2 + 1] + bz[nf].y + r2.y;
                    *reinterpret_cast<float2*>(orow + n) = v2;
                }
            }
        }
    }
}

// ---------------------------------------------------------------------------
// Flash attention: 4 warps, 32 queries/warp, q-tile 128, keys 64/tile.
// Split-phase cp.async prefetch: K(n+1) issued right after QK(n) releases Ksm
// (overlaps softmax+PV); V(n+1) issued after PV(n) releases Vsm (overlaps
// next QK). FIFO group completion makes wait_group 1 select exactly the
// needed tile.
// SMEM (u32): Q 128x68 | K 64x68 | V 64x72 | P 4x(32x68)
// ---------------------------------------------------------------------------
#define QSTR 68
#define KSTR 68
#define VSTR 72
#define PSTR 68
#define FQ_OFF 0
#define FK_OFF (128 * QSTR)
#define FV_OFF (FK_OFF + 64 * KSTR)
#define FP_OFF (FV_OFF + 64 * VSTR)
#define FSM_U32 (FP_OFF + 4 * 32 * PSTR)
#define FSM_TOTAL (FSM_U32 * 4)             // 105472 B

__global__ __launch_bounds__(128, 2) void flash_mma_kernel(const float* __restrict__ Qg,
                                                           const float* __restrict__ Kg,
                                                           const float* __restrict__ Vg,
                                                           float* __restrict__ Og) {
    extern __shared__ uint32_t fsm[];
    const uint32_t sb  = cvta_smem(fsm);
    const uint32_t sbQ = sb + FQ_OFF * 4;
    const uint32_t sbK = sb + FK_OFF * 4;
    const uint32_t sbP = sb + FP_OFF * 4;
    uint32_t* Vsm = fsm + FV_OFF;
    uint32_t* Psm = fsm + FP_OFF;

    const int t    = threadIdx.x;
    const int wid  = t >> 5;
    const int lane = t & 31;
    const int grp  = lane >> 2;
    const int tg   = lane & 3;
    const int bh   = blockIdx.y;
    const int qb   = blockIdx.x * 128;

    const int lm  = lane & 7;
    const int sel = lane >> 3;
    const int a_row_off = lm + ((sel & 1) ? 8 : 0);
    const int a_col_off = (sel & 2) ? 4 : 0;
    const int b_row_off = lm + ((sel & 2) ? 8 : 0);
    const int b_col_off = (sel & 1) ? 4 : 0;

    const float* Qh = Qg + (size_t)bh * S_ * HD_;
    const float* Kh = Kg + (size_t)bh * S_ * HD_;
    const float* Vh = Vg + (size_t)bh * S_ * HD_;

    auto issueK = [&](int kt) {
#pragma unroll
        for (int ii = 0; ii < 8; ii++) {
            const int i   = t + 128 * ii;   // 0..1023
            const int row = i >> 4;         // 0..63
            const int c4  = i & 15;         // 0..15
            CP_ASYNC16(sbK + 4 * (row * KSTR + c4 * 4),
                       Kh + (size_t)(kt + row) * HD_ + c4 * 4);
        }
        CP_COMMIT();
    };
    auto issueV = [&](int kt) {
#pragma unroll
        for (int ii = 0; ii < 8; ii++) {
            const int i   = t + 128 * ii;
            const int row = i >> 4;
            const int c4  = i & 15;
            CP_ASYNC16(sb + 4 * (FV_OFF + row * VSTR + c4 * 4),
                       Vh + (size_t)(kt + row) * HD_ + c4 * 4);
        }
        CP_COMMIT();
    };

    // ---- Q tile (group 1), K0 (group 2), V0 (group 3) ----
#pragma unroll
    for (int ii = 0; ii < 16; ii++) {
        const int i   = t + 128 * ii;
        const int row = i >> 4;
        const int c4  = i & 15;
        CP_ASYNC16(sbQ + 4 * (row * QSTR + c4 * 4),
                   Qh + (size_t)(qb + row) * HD_ + c4 * 4);
    }
    CP_COMMIT();
    issueK(0);
    issueV(0);

    uint32_t* Pw = Psm + wid * 32 * PSTR;
    const uint32_t Pw_sb = sbP + (wid * 32 * PSTR) * 4;

    float m[2][2], l[2][2];
#pragma unroll
    for (int i = 0; i < 2; i++) { m[i][0] = m[i][1] = -1e30f; l[i][0] = l[i][1] = 0.f; }
    float o[2][8][4];
#pragma unroll
    for (int mf = 0; mf < 2; mf++)
#pragma unroll
        for (int nt = 0; nt < 8; nt++)
#pragma unroll
            for (int r = 0; r < 4; r++) o[mf][nt][r] = 0.f;

#pragma unroll 1
    for (int n = 0; n < 32; n++) {
        const int kt = n * 64;
        // K(n) ready (V(n) may still be in flight)
        CP_WAIT1();
        __syncthreads();

        // ---- scores = Q @ K^T ----
        float sc[2][8][4];
#pragma unroll
        for (int mf = 0; mf < 2; mf++)
#pragma unroll
            for (int nt = 0; nt < 8; nt++)
#pragma unroll
                for (int r = 0; r < 4; r++) sc[mf][nt][r] = 0.f;
#pragma unroll
        for (int s = 0; s < 8; s++) {
            const int kb = s * 8;
            uint32_t qf0[4], qf1[4], bm[4][4];
            ldsm4(qf0, sbQ + 4 * ((wid * 32 +  0 + a_row_off) * QSTR + kb + a_col_off));
            ldsm4(qf1, sbQ + 4 * ((wid * 32 + 16 + a_row_off) * QSTR + kb + a_col_off));
#pragma unroll
            for (int p = 0; p < 4; p++)
                ldsm4(bm[p], sbK + 4 * ((p * 16 + b_row_off) * KSTR + kb + b_col_off));
#pragma unroll
            for (int nt = 0; nt < 8; nt++) {
                uint32_t bf[2] = { bm[nt >> 1][(nt & 1) * 2],
                                   bm[nt >> 1][(nt & 1) * 2 + 1] };
                mma8(sc[0][nt], qf0, bf);
                mma8(sc[1][nt], qf1, bf);
            }
        }

        // Ksm free -> prefetch K(n+1) under softmax+PV
        __syncthreads();
        if (n + 1 < 32) issueK(kt + 64);

        // ---- online softmax per m-frag ----
#pragma unroll
        for (int mf = 0; mf < 2; mf++) {
            float mx0 = -1e30f, mx1 = -1e30f;
#pragma unroll
            for (int nt = 0; nt < 8; nt++) {
                mx0 = fmaxf(mx0, fmaxf(sc[mf][nt][0], sc[mf][nt][1]));
                mx1 = fmaxf(mx1, fmaxf(sc[mf][nt][2], sc[mf][nt][3]));
            }
            mx0 = fmaxf(mx0, __shfl_xor_sync(0xffffffffu, mx0, 1));
            mx0 = fmaxf(mx0, __shfl_xor_sync(0xffffffffu, mx0, 2));
            mx1 = fmaxf(mx1, __shfl_xor_sync(0xffffffffu, mx1, 1));
            mx1 = fmaxf(mx1, __shfl_xor_sync(0xffffffffu, mx1, 2));
            const float mn0 = fmaxf(m[mf][0], mx0);
            const float mn1 = fmaxf(m[mf][1], mx1);
            const float a0 = __expf(m[mf][0] - mn0);
            const float a1 = __expf(m[mf][1] - mn1);
            m[mf][0] = mn0; m[mf][1] = mn1;
            float s0 = 0.f, s1 = 0.f;
#pragma unroll
            for (int nt = 0; nt < 8; nt++) {
                sc[mf][nt][0] = __expf(sc[mf][nt][0] - mn0);
                sc[mf][nt][1] = __expf(sc[mf][nt][1] - mn0);
                sc[mf][nt][2] = __expf(sc[mf][nt][2] - mn1);
                sc[mf][nt][3] = __expf(sc[mf][nt][3] - mn1);
                s0 += sc[mf][nt][0] + sc[mf][nt][1];
                s1 += sc[mf][nt][2] + sc[mf][nt][3];
            }
            s0 += __shfl_xor_sync(0xffffffffu, s0, 1);
            s0 += __shfl_xor_sync(0xffffffffu, s0, 2);
            s1 += __shfl_xor_sync(0xffffffffu, s1, 1);
            s1 += __shfl_xor_sync(0xffffffffu, s1, 2);
            l[mf][0] = l[mf][0] * a0 + s0;
            l[mf][1] = l[mf][1] * a1 + s1;
#pragma unroll
            for (int nt = 0; nt < 8; nt++) {
                o[mf][nt][0] *= a0; o[mf][nt][1] *= a0;
                o[mf][nt][2] *= a1; o[mf][nt][3] *= a1;
            }
#pragma unroll
            for (int nt = 0; nt < 8; nt++) {
                uint2 lo = make_uint2(f2tf(sc[mf][nt][0]), f2tf(sc[mf][nt][1]));
                uint2 hi = make_uint2(f2tf(sc[mf][nt][2]), f2tf(sc[mf][nt][3]));
                *reinterpret_cast<uint2*>(&Pw[(mf * 16 + grp) * PSTR + nt * 8 + tg * 2])     = lo;
                *reinterpret_cast<uint2*>(&Pw[(mf * 16 + grp + 8) * PSTR + nt * 8 + tg * 2]) = hi;
            }
        }
        __syncwarp();

        // V(n) ready (K(n+1) may still be in flight)
        if (n + 1 < 32) CP_WAIT1(); else CP_WAIT0();
        __syncthreads();

        // ---- O += P @ V ----
#pragma unroll
        for (int s = 0; s < 8; s++) {
            const int kb = s * 8;
            uint32_t pf0[4], pf1[4];
            ldsm4(pf0, Pw_sb + 4 * (( 0 + a_row_off) * PSTR + kb + a_col_off));
            ldsm4(pf1, Pw_sb + 4 * ((16 + a_row_off) * PSTR + kb + a_col_off));
#pragma unroll
            for (int nt = 0; nt < 8; nt++) {
                uint32_t bf[2];
                bf[0] = Vsm[(kb + tg) * VSTR + nt * 8 + grp];
                bf[1] = Vsm[(kb + tg + 4) * VSTR + nt * 8 + grp];
                mma8(o[0][nt], pf0, bf);
                mma8(o[1][nt], pf1, bf);
            }
        }

        // Vsm free -> prefetch V(n+1) under next tile's QK
        __syncthreads();
        if (n + 1 < 32) issueV(kt + 64);
    }

    // ---- epilogue ----
    const int b = bh >> 4, h = bh & 15;
#pragma unroll
    for (int mf = 0; mf < 2; mf++) {
        const float inv0 = 1.0f / l[mf][0];
        const float inv1 = 1.0f / l[mf][1];
        const int r0 = qb + wid * 32 + mf * 16 + grp;
        float* base0 = Og + ((size_t)b * S_ + r0) * D_ + h * HD_;
        float* base1 = base0 + (size_t)8 * D_;
#pragma unroll
        for (int nt = 0; nt < 8; nt++) {
            *reinterpret_cast<float2*>(base0 + nt * 8 + tg * 2) =
                make_float2(o[mf][nt][0] * inv0, o[mf][nt][1] * inv0);
            *reinterpret_cast<float2*>(base1 + nt * 8 + tg * 2) =
                make_float2(o[mf][nt][2] * inv1, o[mf][nt][3] * inv1);
        }
    }
}

// ---------------------------------------------------------------------------
// LayerNorm over last dim (1024), one block per row
// ---------------------------------------------------------------------------
__global__ __launch_bounds__(256) void ln_kernel(const float* __restrict__ Hm,
                                                 const float* __restrict__ gamma,
                                                 const float* __restrict__ beta,
                                                 float* __restrict__ out) {
    const int row = blockIdx.x;
    const int t   = threadIdx.x;
    const float* hr = Hm + row * D_;
    float4 v = *reinterpret_cast<const float4*>(hr + t * 4);
    float s  = v.x + v.y + v.z + v.w;
    float ss = v.x * v.x + v.y * v.y + v.z * v.z + v.w * v.w;
#pragma unroll
    for (int msk = 16; msk > 0; msk >>= 1) {
        s  += __shfl_xor_sync(0xffffffffu, s, msk);
        ss += __shfl_xor_sync(0xffffffffu, ss, msk);
    }
    __shared__ float rs[8], rss[8];
    __shared__ float mu_s, rstd_s;
    int w = t >> 5;
    if ((t & 31) == 0) { rs[w] = s; rss[w] = ss; }
    __syncthreads();
    if (t == 0) {
        float S = 0.f, SS = 0.f;
#pragma unroll
        for (int i = 0; i < 8; i++) { S += rs[i]; SS += rss[i]; }
        float mu  = S * (1.0f / D_);
        float var = SS * (1.0f / D_) - mu * mu;
        mu_s = mu;
        rstd_s = rsqrtf(var + 1e-5f);
    }
    __syncthreads();
    float mu = mu_s, rstd = rstd_s;
    float4 g4 = *reinterpret_cast<const float4*>(gamma + t * 4);
    float4 b4 = *reinterpret_cast<const float4*>(beta + t * 4);
    float4 o4;
    o4.x = (v.x - mu) * rstd * g4.x + b4.x;
    o4.y = (v.y - mu) * rstd * g4.y + b4.y;
    o4.z = (v.z - mu) * rstd * g4.z + b4.z;
    o4.w = (v.w - mu) * rstd * g4.w + b4.w;
    *reinterpret_cast<float4*>(out + row * D_ + t * 4) = o4;
}

// ---------------------------------------------------------------------------
extern "C" void kernel_launch(void* const* d_in, const int* in_sizes, int n_in,
                              void* d_out, int out_size) {
    (void)in_sizes; (void)n_in; (void)out_size;
    const float* x     = (const float*)d_in[0];
    const float* wq    = (const float*)d_in[1];
    const float* bq    = (const float*)d_in[2];
    const float* wk    = (const float*)d_in[3];
    const float* bk    = (const float*)d_in[4];
    const float* wv    = (const float*)d_in[5];
    const float* bv    = (const float*)d_in[6];
    const float* wo    = (const float*)d_in[7];
    const float* bo    = (const float*)d_in[8];
    const float* gamma = (const float*)d_in[9];
    const float* beta  = (const float*)d_in[10];
    const float* pe    = (const float*)d_in[11];
    float* out = (float*)d_out;

    float *xp, *q, *k, *v, *o, *h, *wt;
    cudaGetSymbolAddress((void**)&xp, g_xp);
    cudaGetSymbolAddress((void**)&q,  g_q);
    cudaGetSymbolAddress((void**)&k,  g_k);
    cudaGetSymbolAddress((void**)&v,  g_v);
    cudaGetSymbolAddress((void**)&o,  g_o);
    cudaGetSymbolAddress((void**)&h,  g_h);
    cudaGetSymbolAddress((void**)&wt, g_wt4);

    cudaFuncSetAttribute(gemm_mma_kernel<0>,
                         cudaFuncAttributeMaxDynamicSharedMemorySize, GSM_TOTAL);
    cudaFuncSetAttribute(gemm_mma_kernel<1>,
                         cudaFuncAttributeMaxDynamicSharedMemorySize, GSM_TOTAL);
    cudaFuncSetAttribute(flash_mma_kernel,
                         cudaFuncAttributeMaxDynamicSharedMemorySize, FSM_TOTAL);

    // 1) x + pe (tf32-rounded)
    pe_add_kernel<<<(MTOT * D_ / 4) / 256, 256>>>(x, pe);

    // 2) transpose + round all 4 weights -> g_wt4 [N,K]
    transpose4_kernel<<<dim3(32, 32, 4), dim3(32, 8)>>>(wq, wk, wv, wo);

    // 3) Q/K/V projections (Q pre-scaled by 1/sqrt(HD))
    dim3 ggrid(D_ / 128, MTOT / 128);
    gemm_mma_kernel<0><<<ggrid, 128, GSM_TOTAL>>>(xp, wt + 0 * (size_t)D_ * D_, bq, nullptr, q, 0.125f);
    gemm_mma_kernel<0><<<ggrid, 128, GSM_TOTAL>>>(xp, wt + 1 * (size_t)D_ * D_, bk, nullptr, k, 1.0f);
    gemm_mma_kernel<0><<<ggrid, 128, GSM_TOTAL>>>(xp, wt + 2 * (size_t)D_ * D_, bv, nullptr, v, 1.0f);

    // 4) attention
    dim3 fgrid(S_ / 128, B_ * H_);
    flash_mma_kernel<<<fgrid, 128, FSM_TOTAL>>>(q, k, v, o);

    // 5) output projection + bias + residual
    gemm_mma_kernel<1><<<ggrid, 128, GSM_TOTAL>>>(o, wt + 3 * (size_t)D_ * D_, bo, xp, h, 1.0f);

    // 6) layernorm
    ln_kernel<<<MTOT, 256>>>(h, gamma, beta, out);
}

// round 10
// speedup vs baseline: 4.5152x; 1.0078x over previous
#include <cuda_runtime.h>
#include <cstdint>

#define B_   4
#define S_   2048
#define D_   1024
#define H_   16
#define HD_  64
#define MTOT (B_ * S_)   // 8192

// ---------------------------------------------------------------------------
// Scratch (module-load device globals; allocation-free at run time)
// ---------------------------------------------------------------------------
__device__ float g_xp [MTOT * D_];     // x + pe (tf32-rounded)
__device__ float g_q  [MTOT * D_];     // [B,H,S,HD] (tf32-rounded, pre-scaled)
__device__ float g_k  [MTOT * D_];
__device__ float g_v  [MTOT * D_];
__device__ float g_o  [MTOT * D_];     // attention out [B,S,D] (raw fp32)
__device__ float g_h  [MTOT * D_];     // pre-LN hidden
__device__ float g_wt4[4 * D_ * D_];   // 4 transposed weights [N,K] (tf32-rounded)

// ---------------------------------------------------------------------------
__device__ __forceinline__ uint32_t f2tf(float f) {
    uint32_t u;
    asm("cvt.rna.tf32.f32 %0, %1;" : "=r"(u) : "f"(f));
    return u;
}
__device__ __forceinline__ float f2tf_f(float f) {
    return __uint_as_float(f2tf(f));
}
__device__ __forceinline__ void mma8(float c[4], const uint32_t a[4], const uint32_t b[2]) {
    asm volatile("mma.sync.aligned.m16n8k8.row.col.f32.tf32.tf32.f32 "
                 "{%0,%1,%2,%3}, {%4,%5,%6,%7}, {%8,%9}, {%0,%1,%2,%3};"
                 : "+f"(c[0]), "+f"(c[1]), "+f"(c[2]), "+f"(c[3])
                 : "r"(a[0]), "r"(a[1]), "r"(a[2]), "r"(a[3]), "r"(b[0]), "r"(b[1]));
}
__device__ __forceinline__ uint32_t cvta_smem(const void* p) {
    uint32_t a;
    asm("{ .reg .u64 t; cvta.to.shared.u64 t, %1; cvt.u32.u64 %0, t; }" : "=r"(a) : "l"(p));
    return a;
}
__device__ __forceinline__ void ldsm4(uint32_t r[4], uint32_t addr) {
    asm volatile("ldmatrix.sync.aligned.m8n8.x4.shared.b16 {%0,%1,%2,%3}, [%4];"
                 : "=r"(r[0]), "=r"(r[1]), "=r"(r[2]), "=r"(r[3]) : "r"(addr));
}
#define CP_ASYNC16(dst, src) \
    asm volatile("cp.async.cg.shared.global [%0], [%1], 16;" :: "r"(dst), "l"(src) : "memory")
#define CP_COMMIT() asm volatile("cp.async.commit_group;" ::: "memory")
#define CP_WAIT0()  asm volatile("cp.async.wait_group 0;" ::: "memory")
#define CP_WAIT1()  asm volatile("cp.async.wait_group 1;" ::: "memory")

// ---------------------------------------------------------------------------
// x + positional encoding -> g_xp (tf32-rounded)
// ---------------------------------------------------------------------------
__global__ __launch_bounds__(256) void pe_add_kernel(const float* __restrict__ x,
                                                     const float* __restrict__ pe) {
    int i = blockIdx.x * 256 + threadIdx.x;
    int row = i >> 8;
    int s   = row & (S_ - 1);
    int d4  = i & 255;
    float4 a = reinterpret_cast<const float4*>(x)[i];
    float4 p = reinterpret_cast<const float4*>(pe)[s * 256 + d4];
    a.x = f2tf_f(a.x + p.x); a.y = f2tf_f(a.y + p.y);
    a.z = f2tf_f(a.z + p.z); a.w = f2tf_f(a.w + p.w);
    reinterpret_cast<float4*>(g_xp)[i] = a;
}

// ---------------------------------------------------------------------------
// Batched transpose of all 4 weights: wt4[z][n][k] = tf32(Wz[k][n])
// ---------------------------------------------------------------------------
__global__ __launch_bounds__(256) void transpose4_kernel(const float* __restrict__ w0,
                                                         const float* __restrict__ w1,
                                                         const float* __restrict__ w2,
                                                         const float* __restrict__ w3) {
    __shared__ float tile[32][33];
    const float* W = (blockIdx.z == 0) ? w0 : (blockIdx.z == 1) ? w1
                   : (blockIdx.z == 2) ? w2 : w3;
    float* Wt = g_wt4 + (size_t)blockIdx.z * D_ * D_;
    int bx = blockIdx.x * 32, by = blockIdx.y * 32;
#pragma unroll
    for (int i = 0; i < 32; i += 8)
        tile[threadIdx.y + i][threadIdx.x] = W[(by + threadIdx.y + i) * D_ + bx + threadIdx.x];
    __syncthreads();
#pragma unroll
    for (int i = 0; i < 32; i += 8)
        Wt[(bx + threadIdx.y + i) * D_ + by + threadIdx.x] =
            f2tf_f(tile[threadIdx.x][threadIdx.y + i]);
}

// ---------------------------------------------------------------------------
// tf32 mma.sync GEMM: 8 warps (2m x 4n), CTA 128x128, warp tile 64x32.
// 3-stage cp.async pipeline, single barrier per chunk, 2 CTAs/SM.
// ---------------------------------------------------------------------------
#define SSTR 36
#define ABYTES (128 * SSTR * 4)
#define BUFB   (2 * ABYTES)
#define NSTAGE 3
#define GSM_TOTAL (NSTAGE * BUFB)          // 110592 B

template <int MODE>
__global__ __launch_bounds__(256, 2) void gemm_mma_kernel(const float* __restrict__ A,
                                                          const float* __restrict__ Wt,
                                                          const float* __restrict__ bias,
                                                          const float* __restrict__ resid,
                                                          float* __restrict__ out,
                                                          float scale) {
    extern __shared__ uint32_t smem[];
    const uint32_t sb = cvta_smem(smem);
    const int t    = threadIdx.x;
    const int wid  = t >> 5;
    const int lane = t & 31;
    const int grp  = lane >> 2;
    const int tg   = lane & 3;
    const int wm   = wid & 1;
    const int wn   = wid >> 1;
    const int mBase = blockIdx.y * 128;
    const int nBase = blockIdx.x * 128;

    const int lm  = lane & 7;
    const int sel = lane >> 3;
    const int a_row_off = lm + ((sel & 1) ? 8 : 0);
    const int a_col_off = (sel & 2) ? 4 : 0;
    const int b_row_off = lm + ((sel & 2) ? 8 : 0);
    const int b_col_off = (sel & 1) ? 4 : 0;

    float acc[4][4][4];
#pragma unroll
    for (int i = 0; i < 4; i++)
#pragma unroll
        for (int j = 0; j < 4; j++)
#pragma unroll
            for (int r = 0; r < 4; r++) acc[i][j][r] = 0.f;

    auto issue = [&](int c, int buf) {
        const uint32_t base = sb + buf * BUFB;
#pragma unroll
        for (int ii = 0; ii < 4; ii++) {
            const int i   = t + 256 * ii;      // 0..1023
            const int row = i >> 3;
            const int c4  = i & 7;
            const float* sa = A  + (size_t)(mBase + row) * D_ + c * 32 + c4 * 4;
            const float* sw = Wt + (size_t)(nBase + row) * D_ + c * 32 + c4 * 4;
            CP_ASYNC16(base + 4 * (row * SSTR + c4 * 4), sa);
            CP_ASYNC16(base + ABYTES + 4 * (row * SSTR + c4 * 4), sw);
        }
        CP_COMMIT();
    };

    auto compute = [&](int buf) {
        const uint32_t sA = sb + buf * BUFB;
        const uint32_t sB = sA + ABYTES;
#pragma unroll
        for (int s = 0; s < 4; s++) {
            const int kb = s * 8;
            uint32_t af[4][4], bm[2][4];
#pragma unroll
            for (int mf = 0; mf < 4; mf++)
                ldsm4(af[mf], sA + 4 * ((wm * 64 + mf * 16 + a_row_off) * SSTR + kb + a_col_off));
#pragma unroll
            for (int p = 0; p < 2; p++)
                ldsm4(bm[p], sB + 4 * ((wn * 32 + p * 16 + b_row_off) * SSTR + kb + b_col_off));
#pragma unroll
            for (int mf = 0; mf < 4; mf++)
#pragma unroll
                for (int nf = 0; nf < 4; nf++) {
                    uint32_t bf[2] = { bm[nf >> 1][(nf & 1) * 2],
                                       bm[nf >> 1][(nf & 1) * 2 + 1] };
                    mma8(acc[mf][nf], af[mf], bf);
                }
        }
    };

    issue(0, 0);
    issue(1, 1);
    int buf = 0, nbuf = 2;
#pragma unroll 1
    for (int c = 0; c < 32; c++) {
        if (c < 30) CP_WAIT1(); else CP_WAIT0();
        __syncthreads();
        if (c + 2 < 32) issue(c + 2, nbuf);
        compute(buf);
        buf  = (buf == 2)  ? 0 : buf + 1;
        nbuf = (nbuf == 2) ? 0 : nbuf + 1;
    }

    // ---- epilogue ----
    float2 bz[4];
#pragma unroll
    for (int nf = 0; nf < 4; nf++)
        bz[nf] = *reinterpret_cast<const float2*>(bias + nBase + wn * 32 + nf * 8 + tg * 2);

#pragma unroll
    for (int mf = 0; mf < 4; mf++) {
#pragma unroll
        for (int half = 0; half < 2; half++) {
            const int gm = mBase + wm * 64 + mf * 16 + grp + half * 8;
            if (MODE == 0) {
                const int h = (nBase + wn * 32) >> 6;   // 32-col block never crosses a head
                const int b = gm >> 11;
                const int s = gm & (S_ - 1);
                float* dst = out + (((size_t)(b * H_ + h)) * S_ + s) * HD_;
#pragma unroll
                for (int nf = 0; nf < 4; nf++) {
                    const int hd = (nBase + wn * 32 + nf * 8 + tg * 2) & 63;
                    float2 v2;
                    v2.x = f2tf_f((acc[mf][nf][half * 2 + 0] + bz[nf].x) * scale);
                    v2.y = f2tf_f((acc[mf][nf][half * 2 + 1] + bz[nf].y) * scale);
                    *reinterpret_cast<float2*>(dst + hd) = v2;
                }
            } else {
                const float* rr = resid + (size_t)gm * D_;
                float* orow     = out   + (size_t)gm * D_;
#pragma unroll
                for (int nf = 0; nf < 4; nf++) {
                    const int n = nBase + wn * 32 + nf * 8 + tg * 2;
                    float2 r2 = *reinterpret_cast<const float2*>(rr + n);
                    float2 v2;
                    v2.x = acc[mf][nf][half * 2 + 0] + bz[nf].x + r2.x;
                    v2.y = acc[mf][nf][half * 2 + 1] + bz[nf].y + r2.y;
                    *reinterpret_cast<float2*>(orow + n) = v2;
                }
            }
        }
    }
}

// ---------------------------------------------------------------------------
// Flash attention (unchanged from round 8): 4 warps, 32 queries/warp,
// split-phase cp.async K/V prefetch.
// SMEM (u32): Q 128x68 | K 64x68 | V 64x72 | P 4x(32x68)
// ---------------------------------------------------------------------------
#define QSTR 68
#define KSTR 68
#define VSTR 72
#define PSTR 68
#define FQ_OFF 0
#define FK_OFF (128 * QSTR)
#define FV_OFF (FK_OFF + 64 * KSTR)
#define FP_OFF (FV_OFF + 64 * VSTR)
#define FSM_U32 (FP_OFF + 4 * 32 * PSTR)
#define FSM_TOTAL (FSM_U32 * 4)             // 105472 B

__global__ __launch_bounds__(128, 2) void flash_mma_kernel(const float* __restrict__ Qg,
                                                           const float* __restrict__ Kg,
                                                           const float* __restrict__ Vg,
                                                           float* __restrict__ Og) {
    extern __shared__ uint32_t fsm[];
    const uint32_t sb  = cvta_smem(fsm);
    const uint32_t sbQ = sb + FQ_OFF * 4;
    const uint32_t sbK = sb + FK_OFF * 4;
    const uint32_t sbP = sb + FP_OFF * 4;
    uint32_t* Vsm = fsm + FV_OFF;
    uint32_t* Psm = fsm + FP_OFF;

    const int t    = threadIdx.x;
    const int wid  = t >> 5;
    const int lane = t & 31;
    const int grp  = lane >> 2;
    const int tg   = lane & 3;
    const int bh   = blockIdx.y;
    const int qb   = blockIdx.x * 128;

    const int lm  = lane & 7;
    const int sel = lane >> 3;
    const int a_row_off = lm + ((sel & 1) ? 8 : 0);
    const int a_col_off = (sel & 2) ? 4 : 0;
    const int b_row_off = lm + ((sel & 2) ? 8 : 0);
    const int b_col_off = (sel & 1) ? 4 : 0;

    const float* Qh = Qg + (size_t)bh * S_ * HD_;
    const float* Kh = Kg + (size_t)bh * S_ * HD_;
    const float* Vh = Vg + (size_t)bh * S_ * HD_;

    auto issueK = [&](int kt) {
#pragma unroll
        for (int ii = 0; ii < 8; ii++) {
            const int i   = t + 128 * ii;   // 0..1023
            const int row = i >> 4;         // 0..63
            const int c4  = i & 15;         // 0..15
            CP_ASYNC16(sbK + 4 * (row * KSTR + c4 * 4),
                       Kh + (size_t)(kt + row) * HD_ + c4 * 4);
        }
        CP_COMMIT();
    };
    auto issueV = [&](int kt) {
#pragma unroll
        for (int ii = 0; ii < 8; ii++) {
            const int i   = t + 128 * ii;
            const int row = i >> 4;
            const int c4  = i & 15;
            CP_ASYNC16(sb + 4 * (FV_OFF + row * VSTR + c4 * 4),
                       Vh + (size_t)(kt + row) * HD_ + c4 * 4);
        }
        CP_COMMIT();
    };

    // ---- Q tile (group 1), K0 (group 2), V0 (group 3) ----
#pragma unroll
    for (int ii = 0; ii < 16; ii++) {
        const int i   = t + 128 * ii;
        const int row = i >> 4;
        const int c4  = i & 15;
        CP_ASYNC16(sbQ + 4 * (row * QSTR + c4 * 4),
                   Qh + (size_t)(qb + row) * HD_ + c4 * 4);
    }
    CP_COMMIT();
    issueK(0);
    issueV(0);

    uint32_t* Pw = Psm + wid * 32 * PSTR;
    const uint32_t Pw_sb = sbP + (wid * 32 * PSTR) * 4;

    float m[2][2], l[2][2];
#pragma unroll
    for (int i = 0; i < 2; i++) { m[i][0] = m[i][1] = -1e30f; l[i][0] = l[i][1] = 0.f; }
    float o[2][8][4];
#pragma unroll
    for (int mf = 0; mf < 2; mf++)
#pragma unroll
        for (int nt = 0; nt < 8; nt++)
#pragma unroll
            for (int r = 0; r < 4; r++) o[mf][nt][r] = 0.f;

#pragma unroll 1
    for (int n = 0; n < 32; n++) {
        const int kt = n * 64;
        // K(n) ready (V(n) may still be in flight)
        CP_WAIT1();
        __syncthreads();

        // ---- scores = Q @ K^T ----
        float sc[2][8][4];
#pragma unroll
        for (int mf = 0; mf < 2; mf++)
#pragma unroll
            for (int nt = 0; nt < 8; nt++)
#pragma unroll
                for (int r = 0; r < 4; r++) sc[mf][nt][r] = 0.f;
#pragma unroll
        for (int s = 0; s < 8; s++) {
            const int kb = s * 8;
            uint32_t qf0[4], qf1[4], bm[4][4];
            ldsm4(qf0, sbQ + 4 * ((wid * 32 +  0 + a_row_off) * QSTR + kb + a_col_off));
            ldsm4(qf1, sbQ + 4 * ((wid * 32 + 16 + a_row_off) * QSTR + kb + a_col_off));
#pragma unroll
            for (int p = 0; p < 4; p++)
                ldsm4(bm[p], sbK + 4 * ((p * 16 + b_row_off) * KSTR + kb + b_col_off));
#pragma unroll
            for (int nt = 0; nt < 8; nt++) {
                uint32_t bf[2] = { bm[nt >> 1][(nt & 1) * 2],
                                   bm[nt >> 1][(nt & 1) * 2 + 1] };
                mma8(sc[0][nt], qf0, bf);
                mma8(sc[1][nt], qf1, bf);
            }
        }

        // Ksm free -> prefetch K(n+1) under softmax+PV
        __syncthreads();
        if (n + 1 < 32) issueK(kt + 64);

        // ---- online softmax per m-frag ----
#pragma unroll
        for (int mf = 0; mf < 2; mf++) {
            float mx0 = -1e30f, mx1 = -1e30f;
#pragma unroll
            for (int nt = 0; nt < 8; nt++) {
                mx0 = fmaxf(mx0, fmaxf(sc[mf][nt][0], sc[mf][nt][1]));
                mx1 = fmaxf(mx1, fmaxf(sc[mf][nt][2], sc[mf][nt][3]));
            }
            mx0 = fmaxf(mx0, __shfl_xor_sync(0xffffffffu, mx0, 1));
            mx0 = fmaxf(mx0, __shfl_xor_sync(0xffffffffu, mx0, 2));
            mx1 = fmaxf(mx1, __shfl_xor_sync(0xffffffffu, mx1, 1));
            mx1 = fmaxf(mx1, __shfl_xor_sync(0xffffffffu, mx1, 2));
            const float mn0 = fmaxf(m[mf][0], mx0);
            const float mn1 = fmaxf(m[mf][1], mx1);
            const float a0 = __expf(m[mf][0] - mn0);
            const float a1 = __expf(m[mf][1] - mn1);
            m[mf][0] = mn0; m[mf][1] = mn1;
            float s0 = 0.f, s1 = 0.f;
#pragma unroll
            for (int nt = 0; nt < 8; nt++) {
                sc[mf][nt][0] = __expf(sc[mf][nt][0] - mn0);
                sc[mf][nt][1] = __expf(sc[mf][nt][1] - mn0);
                sc[mf][nt][2] = __expf(sc[mf][nt][2] - mn1);
                sc[mf][nt][3] = __expf(sc[mf][nt][3] - mn1);
                s0 += sc[mf][nt][0] + sc[mf][nt][1];
                s1 += sc[mf][nt][2] + sc[mf][nt][3];
            }
            s0 += __shfl_xor_sync(0xffffffffu, s0, 1);
            s0 += __shfl_xor_sync(0xffffffffu, s0, 2);
            s1 += __shfl_xor_sync(0xffffffffu, s1, 1);
            s1 += __shfl_xor_sync(0xffffffffu, s1, 2);
            l[mf][0] = l[mf][0] * a0 + s0;
            l[mf][1] = l[mf][1] * a1 + s1;
#pragma unroll
            for (int nt = 0; nt < 8; nt++) {
                o[mf][nt][0] *= a0; o[mf][nt][1] *= a0;
                o[mf][nt][2] *= a1; o[mf][nt][3] *= a1;
            }
#pragma unroll
            for (int nt = 0; nt < 8; nt++) {
                uint2 lo = make_uint2(f2tf(sc[mf][nt][0]), f2tf(sc[mf][nt][1]));
                uint2 hi = make_uint2(f2tf(sc[mf][nt][2]), f2tf(sc[mf][nt][3]));
                *reinterpret_cast<uint2*>(&Pw[(mf * 16 + grp) * PSTR + nt * 8 + tg * 2])     = lo;
                *reinterpret_cast<uint2*>(&Pw[(mf * 16 + grp + 8) * PSTR + nt * 8 + tg * 2]) = hi;
            }
        }
        __syncwarp();

        // V(n) ready (K(n+1) may still be in flight)
        if (n + 1 < 32) CP_WAIT1(); else CP_WAIT0();
        __syncthreads();

        // ---- O += P @ V ----
#pragma unroll
        for (int s = 0; s < 8; s++) {
            const int kb = s * 8;
            uint32_t pf0[4], pf1[4];
            ldsm4(pf0, Pw_sb + 4 * (( 0 + a_row_off) * PSTR + kb + a_col_off));
            ldsm4(pf1, Pw_sb + 4 * ((16 + a_row_off) * PSTR + kb + a_col_off));
#pragma unroll
            for (int nt = 0; nt < 8; nt++) {
                uint32_t bf[2];
                bf[0] = Vsm[(kb + tg) * VSTR + nt * 8 + grp];
                bf[1] = Vsm[(kb + tg + 4) * VSTR + nt * 8 + grp];
                mma8(o[0][nt], pf0, bf);
                mma8(o[1][nt], pf1, bf);
            }
        }

        // Vsm free -> prefetch V(n+1) under next tile's QK
        __syncthreads();
        if (n + 1 < 32) issueV(kt + 64);
    }

    // ---- epilogue ----
    const int b = bh >> 4, h = bh & 15;
#pragma unroll
    for (int mf = 0; mf < 2; mf++) {
        const float inv0 = 1.0f / l[mf][0];
        const float inv1 = 1.0f / l[mf][1];
        const int r0 = qb + wid * 32 + mf * 16 + grp;
        float* base0 = Og + ((size_t)b * S_ + r0) * D_ + h * HD_;
        float* base1 = base0 + (size_t)8 * D_;
#pragma unroll
        for (int nt = 0; nt < 8; nt++) {
            *reinterpret_cast<float2*>(base0 + nt * 8 + tg * 2) =
                make_float2(o[mf][nt][0] * inv0, o[mf][nt][1] * inv0);
            *reinterpret_cast<float2*>(base1 + nt * 8 + tg * 2) =
                make_float2(o[mf][nt][2] * inv1, o[mf][nt][3] * inv1);
        }
    }
}

// ---------------------------------------------------------------------------
// LayerNorm over last dim (1024), one block per row
// ---------------------------------------------------------------------------
__global__ __launch_bounds__(256) void ln_kernel(const float* __restrict__ Hm,
                                                 const float* __restrict__ gamma,
                                                 const float* __restrict__ beta,
                                                 float* __restrict__ out) {
    const int row = blockIdx.x;
    const int t   = threadIdx.x;
    const float* hr = Hm + row * D_;
    float4 v = *reinterpret_cast<const float4*>(hr + t * 4);
    float s  = v.x + v.y + v.z + v.w;
    float ss = v.x * v.x + v.y * v.y + v.z * v.z + v.w * v.w;
#pragma unroll
    for (int msk = 16; msk > 0; msk >>= 1) {
        s  += __shfl_xor_sync(0xffffffffu, s, msk);
        ss += __shfl_xor_sync(0xffffffffu, ss, msk);
    }
    __shared__ float rs[8], rss[8];
    __shared__ float mu_s, rstd_s;
    int w = t >> 5;
    if ((t & 31) == 0) { rs[w] = s; rss[w] = ss; }
    __syncthreads();
    if (t == 0) {
        float S = 0.f, SS = 0.f;
#pragma unroll
        for (int i = 0; i < 8; i++) { S += rs[i]; SS += rss[i]; }
        float mu  = S * (1.0f / D_);
        float var = SS * (1.0f / D_) - mu * mu;
        mu_s = mu;
        rstd_s = rsqrtf(var + 1e-5f);
    }
    __syncthreads();
    float mu = mu_s, rstd = rstd_s;
    float4 g4 = *reinterpret_cast<const float4*>(gamma + t * 4);
    float4 b4 = *reinterpret_cast<const float4*>(beta + t * 4);
    float4 o4;
    o4.x = (v.x - mu) * rstd * g4.x + b4.x;
    o4.y = (v.y - mu) * rstd * g4.y + b4.y;
    o4.z = (v.z - mu) * rstd * g4.z + b4.z;
    o4.w = (v.w - mu) * rstd * g4.w + b4.w;
    *reinterpret_cast<float4*>(out + row * D_ + t * 4) = o4;
}

// ---------------------------------------------------------------------------
extern "C" void kernel_launch(void* const* d_in, const int* in_sizes, int n_in,
                              void* d_out, int out_size) {
    (void)in_sizes; (void)n_in; (void)out_size;
    const float* x     = (const float*)d_in[0];
    const float* wq    = (const float*)d_in[1];
    const float* bq    = (const float*)d_in[2];
    const float* wk    = (const float*)d_in[3];
    const float* bk    = (const float*)d_in[4];
    const float* wv    = (const float*)d_in[5];
    const float* bv    = (const float*)d_in[6];
    const float* wo    = (const float*)d_in[7];
    const float* bo    = (const float*)d_in[8];
    const float* gamma = (const float*)d_in[9];
    const float* beta  = (const float*)d_in[10];
    const float* pe    = (const float*)d_in[11];
    float* out = (float*)d_out;

    float *xp, *q, *k, *v, *o, *h, *wt;
    cudaGetSymbolAddress((void**)&xp, g_xp);
    cudaGetSymbolAddress((void**)&q,  g_q);
    cudaGetSymbolAddress((void**)&k,  g_k);
    cudaGetSymbolAddress((void**)&v,  g_v);
    cudaGetSymbolAddress((void**)&o,  g_o);
    cudaGetSymbolAddress((void**)&h,  g_h);
    cudaGetSymbolAddress((void**)&wt, g_wt4);

    cudaFuncSetAttribute(gemm_mma_kernel<0>,
                         cudaFuncAttributeMaxDynamicSharedMemorySize, GSM_TOTAL);
    cudaFuncSetAttribute(gemm_mma_kernel<1>,
                         cudaFuncAttributeMaxDynamicSharedMemorySize, GSM_TOTAL);
    cudaFuncSetAttribute(flash_mma_kernel,
                         cudaFuncAttributeMaxDynamicSharedMemorySize, FSM_TOTAL);

    // 1) x + pe (tf32-rounded)
    pe_add_kernel<<<(MTOT * D_ / 4) / 256, 256>>>(x, pe);

    // 2) transpose + round all 4 weights -> g_wt4 [N,K]
    transpose4_kernel<<<dim3(32, 32, 4), dim3(32, 8)>>>(wq, wk, wv, wo);

    // 3) Q/K/V projections (Q pre-scaled by 1/sqrt(HD))
    dim3 ggrid(D_ / 128, MTOT / 128);
    gemm_mma_kernel<0><<<ggrid, 256, GSM_TOTAL>>>(xp, wt + 0 * (size_t)D_ * D_, bq, nullptr, q, 0.125f);
    gemm_mma_kernel<0><<<ggrid, 256, GSM_TOTAL>>>(xp, wt + 1 * (size_t)D_ * D_, bk, nullptr, k, 1.0f);
    gemm_mma_kernel<0><<<ggrid, 256, GSM_TOTAL>>>(xp, wt + 2 * (size_t)D_ * D_, bv, nullptr, v, 1.0f);

    // 4) attention
    dim3 fgrid(S_ / 128, B_ * H_);
    flash_mma_kernel<<<fgrid, 128, FSM_TOTAL>>>(q, k, v, o);

    // 5) output projection + bias + residual
    gemm_mma_kernel<1><<<ggrid, 256, GSM_TOTAL>>>(o, wt + 3 * (size_t)D_ * D_, bo, xp, h, 1.0f);

    // 6) layernorm
    ln_kernel<<<MTOT, 256>>>(h, gamma, beta, out);
}

// round 13
// speedup vs baseline: 7.5250x; 1.6666x over previous
#include <cuda_runtime.h>
#include <cuda_fp16.h>
#include <cstdint>

#define B_   4
#define S_   2048
#define D_   1024
#define H_   16
#define HD_  64
#define MTOT (B_ * S_)   // 8192

// ---------------------------------------------------------------------------
// Scratch (module-load device globals; allocation-free at run time)
// ---------------------------------------------------------------------------
__device__ __half g_xp [MTOT * D_];     // x + pe (fp16)
__device__ __half g_q  [MTOT * D_];     // [B,H,S,HD] (fp16, pre-scaled)
__device__ __half g_k  [MTOT * D_];
__device__ __half g_v  [MTOT * D_];
__device__ __half g_o  [MTOT * D_];     // attention out [B,S,D] (fp16)
__device__ float  g_h  [MTOT * D_];     // pre-LN hidden (fp32)
__device__ __half g_wt4[4 * D_ * D_];   // 4 transposed weights [N,K] (fp16)

// ---------------------------------------------------------------------------
__device__ __forceinline__ void mma16(float c[4], const uint32_t a[4], const uint32_t b[2]) {
    asm volatile("mma.sync.aligned.m16n8k16.row.col.f32.f16.f16.f32 "
                 "{%0,%1,%2,%3}, {%4,%5,%6,%7}, {%8,%9}, {%0,%1,%2,%3};"
                 : "+f"(c[0]), "+f"(c[1]), "+f"(c[2]), "+f"(c[3])
                 : "r"(a[0]), "r"(a[1]), "r"(a[2]), "r"(a[3]), "r"(b[0]), "r"(b[1]));
}
__device__ __forceinline__ uint32_t cvta_smem(const void* p) {
    uint32_t a;
    asm("{ .reg .u64 t; cvta.to.shared.u64 t, %1; cvt.u32.u64 %0, t; }" : "=r"(a) : "l"(p));
    return a;
}
__device__ __forceinline__ void ldsm4(uint32_t r[4], uint32_t addr) {
    asm volatile("ldmatrix.sync.aligned.m8n8.x4.shared.b16 {%0,%1,%2,%3}, [%4];"
                 : "=r"(r[0]), "=r"(r[1]), "=r"(r[2]), "=r"(r[3]) : "r"(addr));
}
__device__ __forceinline__ void ldsm4t(uint32_t r[4], uint32_t addr) {
    asm volatile("ldmatrix.sync.aligned.m8n8.x4.trans.shared.b16 {%0,%1,%2,%3}, [%4];"
                 : "=r"(r[0]), "=r"(r[1]), "=r"(r[2]), "=r"(r[3]) : "r"(addr));
}
#define CP_ASYNC16(dst, src) \
    asm volatile("cp.async.cg.shared.global [%0], [%1], 16;" :: "r"(dst), "l"(src) : "memory")
#define CP_COMMIT() asm volatile("cp.async.commit_group;" ::: "memory")
#define CP_WAIT0()  asm volatile("cp.async.wait_group 0;" ::: "memory")
#define CP_WAIT1()  asm volatile("cp.async.wait_group 1;" ::: "memory")
#define CP_WAIT2()  asm volatile("cp.async.wait_group 2;" ::: "memory")

// ---------------------------------------------------------------------------
// x + positional encoding -> g_xp (fp16)
// ---------------------------------------------------------------------------
__global__ __launch_bounds__(256) void pe_add_kernel(const float* __restrict__ x,
                                                     const float* __restrict__ pe) {
    int i = blockIdx.x * 256 + threadIdx.x;   // float4 index
    int row = i >> 8;
    int s   = row & (S_ - 1);
    int d4  = i & 255;
    float4 a = reinterpret_cast<const float4*>(x)[i];
    float4 p = reinterpret_cast<const float4*>(pe)[s * 256 + d4];
    __half2 h0 = __floats2half2_rn(a.x + p.x, a.y + p.y);
    __half2 h1 = __floats2half2_rn(a.z + p.z, a.w + p.w);
    *reinterpret_cast<__half2*>(&g_xp[i * 4])     = h0;
    *reinterpret_cast<__half2*>(&g_xp[i * 4 + 2]) = h1;
}

// ---------------------------------------------------------------------------
// Batched transpose of all 4 weights: wt4[z][n][k] = fp16(Wz[k][n])
// ---------------------------------------------------------------------------
__global__ __launch_bounds__(256) void transpose4_kernel(const float* __restrict__ w0,
                                                         const float* __restrict__ w1,
                                                         const float* __restrict__ w2,
                                                         const float* __restrict__ w3) {
    __shared__ float tile[32][33];
    const float* W = (blockIdx.z == 0) ? w0 : (blockIdx.z == 1) ? w1
                   : (blockIdx.z == 2) ? w2 : w3;
    __half* Wt = g_wt4 + (size_t)blockIdx.z * D_ * D_;
    int bx = blockIdx.x * 32, by = blockIdx.y * 32;
#pragma unroll
    for (int i = 0; i < 32; i += 8)
        tile[threadIdx.y + i][threadIdx.x] = W[(by + threadIdx.y + i) * D_ + bx + threadIdx.x];
    __syncthreads();
#pragma unroll
    for (int i = 0; i < 32; i += 8)
        Wt[(size_t)(bx + threadIdx.y + i) * D_ + by + threadIdx.x] =
            __float2half_rn(tile[threadIdx.x][threadIdx.y + i]);
}

// ---------------------------------------------------------------------------
// fp16 mma.sync GEMM: 8 warps (2m x 4n), CTA 128x128, warp tile 64x32.
// 4-stage cp.async pipeline, single barrier per chunk, 2 CTAs/SM.
// SMEM per stage: A 128x40h + B 128x40h = 20480 B.
// ---------------------------------------------------------------------------
#define SSTRH 40
#define ABYT  (128 * SSTRH * 2)
#define BUFB  (2 * ABYT)
#define NSTAGE 4
#define GSM_TOTAL (NSTAGE * BUFB)          // 81920 B

template <int MODE>
__global__ __launch_bounds__(256, 2) void gemm_mma_kernel(const __half* __restrict__ A,
                                                          const __half* __restrict__ Wt,
                                                          const float* __restrict__ bias,
                                                          const __half* __restrict__ resid,
                                                          void* __restrict__ outv,
                                                          float scale) {
    extern __shared__ uint32_t smem[];
    const uint32_t sb = cvta_smem(smem);
    const int t    = threadIdx.x;
    const int wid  = t >> 5;
    const int lane = t & 31;
    const int grp  = lane >> 2;
    const int tg   = lane & 3;
    const int wm   = wid & 1;
    const int wn   = wid >> 1;
    const int mBase = blockIdx.y * 128;
    const int nBase = blockIdx.x * 128;

    const int lm  = lane & 7;
    const int sel = lane >> 3;
    const int a_row_off = lm + ((sel & 1) ? 8 : 0);
    const int a_col_off = (sel & 2) ? 8 : 0;   // halves
    const int b_row_off = lm + ((sel & 2) ? 8 : 0);
    const int b_col_off = (sel & 1) ? 8 : 0;   // halves

    float acc[4][4][4];
#pragma unroll
    for (int i = 0; i < 4; i++)
#pragma unroll
        for (int j = 0; j < 4; j++)
#pragma unroll
            for (int r = 0; r < 4; r++) acc[i][j][r] = 0.f;

    auto issue = [&](int c, int buf) {
        const uint32_t base = sb + buf * BUFB;
#pragma unroll
        for (int ii = 0; ii < 2; ii++) {
            const int i   = t + 256 * ii;      // 0..511
            const int row = i >> 2;            // 0..127
            const int c8  = i & 3;             // 8-half chunk
            const __half* sa = A  + (size_t)(mBase + row) * D_ + c * 32 + c8 * 8;
            const __half* sw = Wt + (size_t)(nBase + row) * D_ + c * 32 + c8 * 8;
            CP_ASYNC16(base + 2 * (row * SSTRH + c8 * 8), sa);
            CP_ASYNC16(base + ABYT + 2 * (row * SSTRH + c8 * 8), sw);
        }
        CP_COMMIT();
    };

    auto compute = [&](int buf) {
        const uint32_t sA = sb + buf * BUFB;
        const uint32_t sB = sA + ABYT;
#pragma unroll
        for (int ks = 0; ks < 2; ks++) {
            const int kb = ks * 16;            // halves
            uint32_t af[4][4], bm[2][4];
#pragma unroll
            for (int mf = 0; mf < 4; mf++)
                ldsm4(af[mf], sA + 2 * ((wm * 64 + mf * 16 + a_row_off) * SSTRH + kb + a_col_off));
#pragma unroll
            for (int p = 0; p < 2; p++)
                ldsm4(bm[p], sB + 2 * ((wn * 32 + p * 16 + b_row_off) * SSTRH + kb + b_col_off));
#pragma unroll
            for (int mf = 0; mf < 4; mf++)
#pragma unroll
                for (int nf = 0; nf < 4; nf++) {
                    uint32_t bf[2] = { bm[nf >> 1][(nf & 1) * 2],
                                       bm[nf >> 1][(nf & 1) * 2 + 1] };
                    mma16(acc[mf][nf], af[mf], bf);
                }
        }
    };

    issue(0, 0);
    issue(1, 1);
    issue(2, 2);
#pragma unroll 1
    for (int c = 0; c < 32; c++) {
        if (c <= 29) CP_WAIT2(); else if (c == 30) CP_WAIT1(); else CP_WAIT0();
        __syncthreads();
        if (c + 3 < 32) issue(c + 3, (c + 3) & 3);
        compute(c & 3);
    }

    // ---- epilogue ----
    float2 bz[4];
#pragma unroll
    for (int nf = 0; nf < 4; nf++)
        bz[nf] = *reinterpret_cast<const float2*>(bias + nBase + wn * 32 + nf * 8 + tg * 2);

#pragma unroll
    for (int mf = 0; mf < 4; mf++) {
#pragma unroll
        for (int half = 0; half < 2; half++) {
            const int gm = mBase + wm * 64 + mf * 16 + grp + half * 8;
            if (MODE == 0) {
                __half* out = (__half*)outv;
                const int h = (nBase + wn * 32) >> 6;
                const int b = gm >> 11;
                const int s = gm & (S_ - 1);
                __half* dst = out + (((size_t)(b * H_ + h)) * S_ + s) * HD_;
#pragma unroll
                for (int nf = 0; nf < 4; nf++) {
                    const int hd = (nBase + wn * 32 + nf * 8 + tg * 2) & 63;
                    *reinterpret_cast<__half2*>(dst + hd) = __floats2half2_rn(
                        (acc[mf][nf][half * 2 + 0] + bz[nf].x) * scale,
                        (acc[mf][nf][half * 2 + 1] + bz[nf].y) * scale);
                }
            } else {
                float* out = (float*)outv;
                const __half* rr = resid + (size_t)gm * D_;
                float* orow      = out   + (size_t)gm * D_;
#pragma unroll
                for (int nf = 0; nf < 4; nf++) {
                    const int n = nBase + wn * 32 + nf * 8 + tg * 2;
                    float2 r2 = __half22float2(*reinterpret_cast<const __half2*>(rr + n));
                    float2 v2;
                    v2.x = acc[mf][nf][half * 2 + 0] + bz[nf].x + r2.x;
                    v2.y = acc[mf][nf][half * 2 + 1] + bz[nf].y + r2.y;
                    *reinterpret_cast<float2*>(orow + n) = v2;
                }
            }
        }
    }
}

// ---------------------------------------------------------------------------
// Flash attention fp16: 4 warps, 32 queries/warp, q-tile 128, keys 64/tile.
// Split-phase cp.async K/V prefetch (R8-proven schedule).
// SMEM (halves): Q 128x72 | K 64x72 | V 64x72 | P 4x(32x72)
// ---------------------------------------------------------------------------
#define QSTRH 72
#define KSTRH 72
#define VSTRH 72
#define PSTRH 72
#define FQH 0
#define FKH (128 * QSTRH)                   // 9216
#define FVH (FKH + 64 * KSTRH)              // 13824
#define FPH (FVH + 64 * VSTRH)              // 18432
#define PWB (32 * PSTRH * 2)                // per-warp P bytes (4608)
#define FSM_TOTAL ((FPH + 4 * 32 * PSTRH) * 2)   // 55296 B

__global__ __launch_bounds__(128, 2) void flash_mma_kernel(const __half* __restrict__ Qg,
                                                           const __half* __restrict__ Kg,
                                                           const __half* __restrict__ Vg,
                                                           __half* __restrict__ Og) {
    extern __shared__ __half fsm[];
    const uint32_t sb  = cvta_smem(fsm);
    const uint32_t sbQ = sb + FQH * 2;
    const uint32_t sbK = sb + FKH * 2;
    const uint32_t sbV = sb + FVH * 2;
    const uint32_t sbP = sb + FPH * 2;
    __half* Psm = fsm + FPH;

    const int t    = threadIdx.x;
    const int wid  = t >> 5;
    const int lane = t & 31;
    const int grp  = lane >> 2;
    const int tg   = lane & 3;
    const int bh   = blockIdx.y;
    const int qb   = blockIdx.x * 128;

    const int lm  = lane & 7;
    const int sel = lane >> 3;
    const int a_row_off = lm + ((sel & 1) ? 8 : 0);
    const int a_col_off = (sel & 2) ? 8 : 0;     // halves
    const int b_row_off = lm + ((sel & 2) ? 8 : 0);
    const int b_col_off = (sel & 1) ? 8 : 0;     // halves
    const int v_row_off = lm + ((sel & 1) ? 8 : 0);   // k-dim rows for trans
    const int v_col_off = (sel & 2) ? 8 : 0;          // n halves

    const __half* Qh = Qg + (size_t)bh * S_ * HD_;
    const __half* Kh = Kg + (size_t)bh * S_ * HD_;
    const __half* Vh = Vg + (size_t)bh * S_ * HD_;

    auto issueK = [&](int kt) {
#pragma unroll
        for (int ii = 0; ii < 4; ii++) {
            const int i   = t + 128 * ii;   // 0..511
            const int row = i >> 3;         // 0..63
            const int c8  = i & 7;          // 8-half chunk
            CP_ASYNC16(sbK + 2 * (row * KSTRH + c8 * 8),
                       Kh + (size_t)(kt + row) * HD_ + c8 * 8);
        }
        CP_COMMIT();
    };
    auto issueV = [&](int kt) {
#pragma unroll
        for (int ii = 0; ii < 4; ii++) {
            const int i   = t + 128 * ii;
            const int row = i >> 3;
            const int c8  = i & 7;
            CP_ASYNC16(sbV + 2 * (row * VSTRH + c8 * 8),
                       Vh + (size_t)(kt + row) * HD_ + c8 * 8);
        }
        CP_COMMIT();
    };

    // ---- Q (group 1), K0 (group 2), V0 (group 3) ----
#pragma unroll
    for (int ii = 0; ii < 8; ii++) {
        const int i   = t + 128 * ii;       // 0..1023
        const int row = i >> 3;             // 0..127
        const int c8  = i & 7;
        CP_ASYNC16(sbQ + 2 * (row * QSTRH + c8 * 8),
                   Qh + (size_t)(qb + row) * HD_ + c8 * 8);
    }
    CP_COMMIT();
    issueK(0);
    issueV(0);

    __half* Pw = Psm + wid * 32 * PSTRH;
    const uint32_t Pw_sb = sbP + wid * PWB;

    float m[2][2], l[2][2];
#pragma unroll
    for (int i = 0; i < 2; i++) { m[i][0] = m[i][1] = -1e30f; l[i][0] = l[i][1] = 0.f; }
    float o[2][8][4];
#pragma unroll
    for (int mf = 0; mf < 2; mf++)
#pragma unroll
        for (int nt = 0; nt < 8; nt++)
#pragma unroll
            for (int r = 0; r < 4; r++) o[mf][nt][r] = 0.f;

#pragma unroll 1
    for (int n = 0; n < 32; n++) {
        const int kt = n * 64;
        // K(n) ready (V(n) may still be in flight)
        CP_WAIT1();
        __syncthreads();

        // ---- scores = Q @ K^T ----
        float sc[2][8][4];
#pragma unroll
        for (int mf = 0; mf < 2; mf++)
#pragma unroll
            for (int nt = 0; nt < 8; nt++)
#pragma unroll
                for (int r = 0; r < 4; r++) sc[mf][nt][r] = 0.f;
#pragma unroll
        for (int s = 0; s < 4; s++) {
            const int kb = s * 16;          // halves of HD
            uint32_t qf0[4], qf1[4], bm[4][4];
            ldsm4(qf0, sbQ + 2 * ((wid * 32 +  0 + a_row_off) * QSTRH + kb + a_col_off));
            ldsm4(qf1, sbQ + 2 * ((wid * 32 + 16 + a_row_off) * QSTRH + kb + a_col_off));
#pragma unroll
            for (int p = 0; p < 4; p++)
                ldsm4(bm[p], sbK + 2 * ((p * 16 + b_row_off) * KSTRH + kb + b_col_off));
#pragma unroll
            for (int nt = 0; nt < 8; nt++) {
                uint32_t bf[2] = { bm[nt >> 1][(nt & 1) * 2],
                                   bm[nt >> 1][(nt & 1) * 2 + 1] };
                mma16(sc[0][nt], qf0, bf);
                mma16(sc[1][nt], qf1, bf);
            }
        }

        // Ksm free -> prefetch K(n+1) under softmax+PV
        __syncthreads();
        if (n + 1 < 32) issueK(kt + 64);

        // ---- online softmax per m-frag ----
#pragma unroll
        for (int mf = 0; mf < 2; mf++) {
            float mx0 = -1e30f, mx1 = -1e30f;
#pragma unroll
            for (int nt = 0; nt < 8; nt++) {
                mx0 = fmaxf(mx0, fmaxf(sc[mf][nt][0], sc[mf][nt][1]));
                mx1 = fmaxf(mx1, fmaxf(sc[mf][nt][2], sc[mf][nt][3]));
            }
            mx0 = fmaxf(mx0, __shfl_xor_sync(0xffffffffu, mx0, 1));
            mx0 = fmaxf(mx0, __shfl_xor_sync(0xffffffffu, mx0, 2));
            mx1 = fmaxf(mx1, __shfl_xor_sync(0xffffffffu, mx1, 1));
            mx1 = fmaxf(mx1, __shfl_xor_sync(0xffffffffu, mx1, 2));
            const float mn0 = fmaxf(m[mf][0], mx0);
            const float mn1 = fmaxf(m[mf][1], mx1);
            const float a0 = __expf(m[mf][0] - mn0);
            const float a1 = __expf(m[mf][1] - mn1);
            m[mf][0] = mn0; m[mf][1] = mn1;
            float s0 = 0.f, s1 = 0.f;
#pragma unroll
            for (int nt = 0; nt < 8; nt++) {
                sc[mf][nt][0] = __expf(sc[mf][nt][0] - mn0);
                sc[mf][nt][1] = __expf(sc[mf][nt][1] - mn0);
                sc[mf][nt][2] = __expf(sc[mf][nt][2] - mn1);
                sc[mf][nt][3] = __expf(sc[mf][nt][3] - mn1);
                s0 += sc[mf][nt][0] + sc[mf][nt][1];
                s1 += sc[mf][nt][2] + sc[mf][nt][3];
            }
            s0 += __shfl_xor_sync(0xffffffffu, s0, 1);
            s0 += __shfl_xor_sync(0xffffffffu, s0, 2);
            s1 += __shfl_xor_sync(0xffffffffu, s1, 1);
            s1 += __shfl_xor_sync(0xffffffffu, s1, 2);
            l[mf][0] = l[mf][0] * a0 + s0;
            l[mf][1] = l[mf][1] * a1 + s1;
#pragma unroll
            for (int nt = 0; nt < 8; nt++) {
                o[mf][nt][0] *= a0; o[mf][nt][1] *= a0;
                o[mf][nt][2] *= a1; o[mf][nt][3] *= a1;
            }
            // store P (fp16): row = mf*16+grp (+8), col = nt*8+tg*2 (64 cols < 72)
#pragma unroll
            for (int nt = 0; nt < 8; nt++) {
                *reinterpret_cast<__half2*>(&Pw[(mf * 16 + grp) * PSTRH + nt * 8 + tg * 2]) =
                    __floats2half2_rn(sc[mf][nt][0], sc[mf][nt][1]);
                *reinterpret_cast<__half2*>(&Pw[(mf * 16 + grp + 8) * PSTRH + nt * 8 + tg * 2]) =
                    __floats2half2_rn(sc[mf][nt][2], sc[mf][nt][3]);
            }
        }
        __syncwarp();

        // V(n) ready (K(n+1) may still be in flight)
        if (n + 1 < 32) CP_WAIT1(); else CP_WAIT0();
        __syncthreads();

        // ---- O += P @ V ----
#pragma unroll
        for (int s = 0; s < 4; s++) {
            const int kb = s * 16;           // key halves
            uint32_t pf0[4], pf1[4], bm[4][4];
            ldsm4(pf0, Pw_sb + 2 * (( 0 + a_row_off) * PSTRH + kb + a_col_off));
            ldsm4(pf1, Pw_sb + 2 * ((16 + a_row_off) * PSTRH + kb + a_col_off));
#pragma unroll
            for (int p = 0; p < 4; p++)
                ldsm4t(bm[p], sbV + 2 * ((kb + v_row_off) * VSTRH + p * 16 + v_col_off));
#pragma unroll
            for (int nt = 0; nt < 8; nt++) {
                uint32_t bf[2] = { bm[nt >> 1][(nt & 1) * 2],
                                   bm[nt >> 1][(nt & 1) * 2 + 1] };
                mma16(o[0][nt], pf0, bf);
                mma16(o[1][nt], pf1, bf);
            }
        }

        // Vsm free -> prefetch V(n+1) under next tile's QK
        __syncthreads();
        if (n + 1 < 32) issueV(kt + 64);
    }

    // ---- epilogue: O/l -> g_o (fp16, [B,S,D]) ----
    const int b = bh >> 4, h = bh & 15;
#pragma unroll
    for (int mf = 0; mf < 2; mf++) {
        const float inv0 = 1.0f / l[mf][0];
        const float inv1 = 1.0f / l[mf][1];
        const int r0 = qb + wid * 32 + mf * 16 + grp;
        __half* base0 = Og + ((size_t)b * S_ + r0) * D_ + h * HD_;
        __half* base1 = base0 + (size_t)8 * D_;
#pragma unroll
        for (int nt = 0; nt < 8; nt++) {
            *reinterpret_cast<__half2*>(base0 + nt * 8 + tg * 2) =
                __floats2half2_rn(o[mf][nt][0] * inv0, o[mf][nt][1] * inv0);
            *reinterpret_cast<__half2*>(base1 + nt * 8 + tg * 2) =
                __floats2half2_rn(o[mf][nt][2] * inv1, o[mf][nt][3] * inv1);
        }
    }
}

// ---------------------------------------------------------------------------
// LayerNorm over last dim (1024), one block per row
// ---------------------------------------------------------------------------
__global__ __launch_bounds__(256) void ln_kernel(const float* __restrict__ Hm,
                                                 const float* __restrict__ gamma,
                                                 const float* __restrict__ beta,
                                                 float* __restrict__ out) {
    const int row = blockIdx.x;
    const int t   = threadIdx.x;
    const float* hr = Hm + (size_t)row * D_;
    float4 v = *reinterpret_cast<const float4*>(hr + t * 4);
    float s  = v.x + v.y + v.z + v.w;
    float ss = v.x * v.x + v.y * v.y + v.z * v.z + v.w * v.w;
#pragma unroll
    for (int msk = 16; msk > 0; msk >>= 1) {
        s  += __shfl_xor_sync(0xffffffffu, s, msk);
        ss += __shfl_xor_sync(0xffffffffu, ss, msk);
    }
    __shared__ float rs[8], rss[8];
    __shared__ float mu_s, rstd_s;
    int w = t >> 5;
    if ((t & 31) == 0) { rs[w] = s; rss[w] = ss; }
    __syncthreads();
    if (t == 0) {
        float S = 0.f, SS = 0.f;
#pragma unroll
        for (int i = 0; i < 8; i++) { S += rs[i]; SS += rss[i]; }
        float mu  = S * (1.0f / D_);
        float var = SS * (1.0f / D_) - mu * mu;
        mu_s = mu;
        rstd_s = rsqrtf(var + 1e-5f);
    }
    __syncthreads();
    float mu = mu_s, rstd = rstd_s;
    float4 g4 = *reinterpret_cast<const float4*>(gamma + t * 4);
    float4 b4 = *reinterpret_cast<const float4*>(beta + t * 4);
    float4 o4;
    o4.x = (v.x - mu) * rstd * g4.x + b4.x;
    o4.y = (v.y - mu) * rstd * g4.y + b4.y;
    o4.z = (v.z - mu) * rstd * g4.z + b4.z;
    o4.w = (v.w - mu) * rstd * g4.w + b4.w;
    *reinterpret_cast<float4*>(out + (size_t)row * D_ + t * 4) = o4;
}

// ---------------------------------------------------------------------------
extern "C" void kernel_launch(void* const* d_in, const int* in_sizes, int n_in,
                              void* d_out, int out_size) {
    (void)in_sizes; (void)n_in; (void)out_size;
    const float* x     = (const float*)d_in[0];
    const float* wq    = (const float*)d_in[1];
    const float* bq    = (const float*)d_in[2];
    const float* wk    = (const float*)d_in[3];
    const float* bk    = (const float*)d_in[4];
    const float* wv    = (const float*)d_in[5];
    const float* bv    = (const float*)d_in[6];
    const float* wo    = (const float*)d_in[7];
    const float* bo    = (const float*)d_in[8];
    const float* gamma = (const float*)d_in[9];
    const float* beta  = (const float*)d_in[10];
    const float* pe    = (const float*)d_in[11];
    float* out = (float*)d_out;

    __half *xp, *q, *k, *v, *o, *wt;
    float *h;
    cudaGetSymbolAddress((void**)&xp, g_xp);
    cudaGetSymbolAddress((void**)&q,  g_q);
    cudaGetSymbolAddress((void**)&k,  g_k);
    cudaGetSymbolAddress((void**)&v,  g_v);
    cudaGetSymbolAddress((void**)&o,  g_o);
    cudaGetSymbolAddress((void**)&h,  g_h);
    cudaGetSymbolAddress((void**)&wt, g_wt4);

    cudaFuncSetAttribute(gemm_mma_kernel<0>,
                         cudaFuncAttributeMaxDynamicSharedMemorySize, GSM_TOTAL);
    cudaFuncSetAttribute(gemm_mma_kernel<1>,
                         cudaFuncAttributeMaxDynamicSharedMemorySize, GSM_TOTAL);
    cudaFuncSetAttribute(flash_mma_kernel,
                         cudaFuncAttributeMaxDynamicSharedMemorySize, FSM_TOTAL);

    // 1) x + pe (fp16)
    pe_add_kernel<<<(MTOT * D_ / 4) / 256, 256>>>(x, pe);

    // 2) transpose + convert all 4 weights -> g_wt4 [N,K] fp16
    transpose4_kernel<<<dim3(32, 32, 4), dim3(32, 8)>>>(wq, wk, wv, wo);

    // 3) Q/K/V projections (Q pre-scaled by 1/sqrt(HD))
    dim3 ggrid(D_ / 128, MTOT / 128);
    gemm_mma_kernel<0><<<ggrid, 256, GSM_TOTAL>>>(xp, wt + 0 * (size_t)D_ * D_, bq, nullptr, q, 0.125f);
    gemm_mma_kernel<0><<<ggrid, 256, GSM_TOTAL>>>(xp, wt + 1 * (size_t)D_ * D_, bk, nullptr, k, 1.0f);
    gemm_mma_kernel<0><<<ggrid, 256, GSM_TOTAL>>>(xp, wt + 2 * (size_t)D_ * D_, bv, nullptr, v, 1.0f);

    // 4) attention
    dim3 fgrid(S_ / 128, B_ * H_);
    flash_mma_kernel<<<fgrid, 128, FSM_TOTAL>>>(q, k, v, o);

    // 5) output projection + bias + residual (fp32 out)
    gemm_mma_kernel<1><<<ggrid, 256, GSM_TOTAL>>>(o, wt + 3 * (size_t)D_ * D_, bo, xp, h, 1.0f);

    // 6) layernorm
    ln_kernel<<<MTOT, 256>>>(h, gamma, beta, out);
}

// round 15
// speedup vs baseline: 8.2180x; 1.0921x over previous
#include <cuda_runtime.h>
#include <cuda_fp16.h>
#include <cstdint>

#define B_   4
#define S_   2048
#define D_   1024
#define H_   16
#define HD_  64
#define MTOT (B_ * S_)   // 8192

// ---------------------------------------------------------------------------
// Scratch (module-load device globals; allocation-free at run time)
// ---------------------------------------------------------------------------
__device__ __half g_xp [MTOT * D_];     // x + pe (fp16)
__device__ __half g_q  [MTOT * D_];     // [B,H,S,HD] (fp16, pre-scaled)
__device__ __half g_k  [MTOT * D_];
__device__ __half g_v  [MTOT * D_];
__device__ __half g_o  [MTOT * D_];     // attention out [B,S,D] (fp16)
__device__ float  g_h  [MTOT * D_];     // pre-LN hidden (fp32)
__device__ __half g_wt4[4 * D_ * D_];   // 4 transposed weights [N,K] (fp16), q|k|v|o

// ---------------------------------------------------------------------------
__device__ __forceinline__ void mma16(float c[4], const uint32_t a[4], const uint32_t b[2]) {
    asm volatile("mma.sync.aligned.m16n8k16.row.col.f32.f16.f16.f32 "
                 "{%0,%1,%2,%3}, {%4,%5,%6,%7}, {%8,%9}, {%0,%1,%2,%3};"
                 : "+f"(c[0]), "+f"(c[1]), "+f"(c[2]), "+f"(c[3])
                 : "r"(a[0]), "r"(a[1]), "r"(a[2]), "r"(a[3]), "r"(b[0]), "r"(b[1]));
}
__device__ __forceinline__ uint32_t cvta_smem(const void* p) {
    uint32_t a;
    asm("{ .reg .u64 t; cvta.to.shared.u64 t, %1; cvt.u32.u64 %0, t; }" : "=r"(a) : "l"(p));
    return a;
}
__device__ __forceinline__ void ldsm4(uint32_t r[4], uint32_t addr) {
    asm volatile("ldmatrix.sync.aligned.m8n8.x4.shared.b16 {%0,%1,%2,%3}, [%4];"
                 : "=r"(r[0]), "=r"(r[1]), "=r"(r[2]), "=r"(r[3]) : "r"(addr));
}
__device__ __forceinline__ void ldsm4t(uint32_t r[4], uint32_t addr) {
    asm volatile("ldmatrix.sync.aligned.m8n8.x4.trans.shared.b16 {%0,%1,%2,%3}, [%4];"
                 : "=r"(r[0]), "=r"(r[1]), "=r"(r[2]), "=r"(r[3]) : "r"(addr));
}
#define CP_ASYNC16(dst, src) \
    asm volatile("cp.async.cg.shared.global [%0], [%1], 16;" :: "r"(dst), "l"(src) : "memory")
#define CP_COMMIT() asm volatile("cp.async.commit_group;" ::: "memory")
#define CP_WAIT0()  asm volatile("cp.async.wait_group 0;" ::: "memory")
#define CP_WAIT1()  asm volatile("cp.async.wait_group 1;" ::: "memory")

// ---------------------------------------------------------------------------
// x + positional encoding -> g_xp (fp16)
// ---------------------------------------------------------------------------
__global__ __launch_bounds__(256) void pe_add_kernel(const float* __restrict__ x,
                                                     const float* __restrict__ pe) {
    int i = blockIdx.x * 256 + threadIdx.x;   // float4 index
    int row = i >> 8;
    int s   = row & (S_ - 1);
    int d4  = i & 255;
    float4 a = reinterpret_cast<const float4*>(x)[i];
    float4 p = reinterpret_cast<const float4*>(pe)[s * 256 + d4];
    __half2 h0 = __floats2half2_rn(a.x + p.x, a.y + p.y);
    __half2 h1 = __floats2half2_rn(a.z + p.z, a.w + p.w);
    *reinterpret_cast<__half2*>(&g_xp[i * 4])     = h0;
    *reinterpret_cast<__half2*>(&g_xp[i * 4 + 2]) = h1;
}

// ---------------------------------------------------------------------------
// Batched transpose of all 4 weights: wt4[z][n][k] = fp16(Wz[k][n])
// ---------------------------------------------------------------------------
__global__ __launch_bounds__(256) void transpose4_kernel(const float* __restrict__ w0,
                                                         const float* __restrict__ w1,
                                                         const float* __restrict__ w2,
                                                         const float* __restrict__ w3) {
    __shared__ float tile[32][33];
    const float* W = (blockIdx.z == 0) ? w0 : (blockIdx.z == 1) ? w1
                   : (blockIdx.z == 2) ? w2 : w3;
    __half* Wt = g_wt4 + (size_t)blockIdx.z * D_ * D_;
    int bx = blockIdx.x * 32, by = blockIdx.y * 32;
#pragma unroll
    for (int i = 0; i < 32; i += 8)
        tile[threadIdx.y + i][threadIdx.x] = W[(by + threadIdx.y + i) * D_ + bx + threadIdx.x];
    __syncthreads();
#pragma unroll
    for (int i = 0; i < 32; i += 8)
        Wt[(size_t)(bx + threadIdx.y + i) * D_ + by + threadIdx.x] =
            __float2half_rn(tile[threadIdx.x][threadIdx.y + i]);
}

// ---------------------------------------------------------------------------
// fp16 mma.sync GEMM: 8 warps (2m x 4n), CTA 128x128, warp tile 64x32.
// K-chunk 64 halves, 3-stage cp.async pipeline, 16 barrier rounds, 2 CTAs/SM.
// MODE 0: fused QKV (grid.x = 24 over N=3072); z selects bias/scale/output,
//         scatter to [B,H,S,HD] fp16.
// MODE 1: out-proj (grid.x = 8), + bias + residual -> fp32 [M,N].
// SMEM per stage: A 128x72h + B 128x72h = 36864 B; 3 stages = 110592 B.
// ---------------------------------------------------------------------------
#define SSTRH 72
#define ABYT  (128 * SSTRH * 2)
#define BUFB  (2 * ABYT)
#define NSTAGE 3
#define GSM_TOTAL (NSTAGE * BUFB)          // 110592 B
#define NCHUNK 16

template <int MODE>
__global__ __launch_bounds__(256, 2) void gemm_mma_kernel(const __half* __restrict__ A,
                                                          const __half* __restrict__ Wt,
                                                          const float* __restrict__ b0,
                                                          const float* __restrict__ b1,
                                                          const float* __restrict__ b2,
                                                          const __half* __restrict__ resid,
                                                          void* __restrict__ out0,
                                                          void* __restrict__ out1,
                                                          void* __restrict__ out2) {
    extern __shared__ uint32_t smem[];
    const uint32_t sb = cvta_smem(smem);
    const int t    = threadIdx.x;
    const int wid  = t >> 5;
    const int lane = t & 31;
    const int grp  = lane >> 2;
    const int tg   = lane & 3;
    const int wm   = wid & 1;
    const int wn   = wid >> 1;
    const int mBase = blockIdx.y * 128;
    const int nGlob = blockIdx.x * 128;    // over 3072 (MODE0) or 1024 (MODE1)

    const int lm  = lane & 7;
    const int sel = lane >> 3;
    const int a_row_off = lm + ((sel & 1) ? 8 : 0);
    const int a_col_off = (sel & 2) ? 8 : 0;   // halves
    const int b_row_off = lm + ((sel & 2) ? 8 : 0);
    const int b_col_off = (sel & 1) ? 8 : 0;   // halves

    float acc[4][4][4];
#pragma unroll
    for (int i = 0; i < 4; i++)
#pragma unroll
        for (int j = 0; j < 4; j++)
#pragma unroll
            for (int r = 0; r < 4; r++) acc[i][j][r] = 0.f;

    auto issue = [&](int c, int buf) {
        const uint32_t base = sb + buf * BUFB;
#pragma unroll
        for (int ii = 0; ii < 4; ii++) {
            const int i   = t + 256 * ii;      // 0..1023
            const int row = i >> 3;            // 0..127
            const int c8  = i & 7;             // 8-half chunk within 64
            const __half* sa = A  + (size_t)(mBase + row) * D_ + c * 64 + c8 * 8;
            const __half* sw = Wt + (size_t)(nGlob + row) * D_ + c * 64 + c8 * 8;
            CP_ASYNC16(base + 2 * (row * SSTRH + c8 * 8), sa);
            CP_ASYNC16(base + ABYT + 2 * (row * SSTRH + c8 * 8), sw);
        }
        CP_COMMIT();
    };

    auto compute = [&](int buf) {
        const uint32_t sA = sb + buf * BUFB;
        const uint32_t sB = sA + ABYT;
#pragma unroll
        for (int ks = 0; ks < 4; ks++) {
            const int kb = ks * 16;            // halves
            uint32_t af[4][4], bm[2][4];
#pragma unroll
            for (int mf = 0; mf < 4; mf++)
                ldsm4(af[mf], sA + 2 * ((wm * 64 + mf * 16 + a_row_off) * SSTRH + kb + a_col_off));
#pragma unroll
            for (int p = 0; p < 2; p++)
                ldsm4(bm[p], sB + 2 * ((wn * 32 + p * 16 + b_row_off) * SSTRH + kb + b_col_off));
#pragma unroll
            for (int mf = 0; mf < 4; mf++)
#pragma unroll
                for (int nf = 0; nf < 4; nf++) {
                    uint32_t bf[2] = { bm[nf >> 1][(nf & 1) * 2],
                                       bm[nf >> 1][(nf & 1) * 2 + 1] };
                    mma16(acc[mf][nf], af[mf], bf);
                }
        }
    };

    issue(0, 0);
    issue(1, 1);
#pragma unroll 1
    for (int c = 0; c < NCHUNK; c++) {
        if (c <= NCHUNK - 3) CP_WAIT1(); else CP_WAIT0();
        __syncthreads();
        if (c + 2 < NCHUNK) issue(c + 2, (c + 2) % 3);
        compute(c % 3);
    }

    // ---- epilogue ----
    const int z = (MODE == 0) ? (nGlob >> 10) : 0;
    const float* bias = (MODE == 0) ? ((z == 0) ? b0 : (z == 1) ? b1 : b2) : b0;
    const float scale = (MODE == 0 && z == 0) ? 0.125f : 1.0f;
    const int nIn = nGlob & 1023;

    float2 bz[4];
#pragma unroll
    for (int nf = 0; nf < 4; nf++)
        bz[nf] = *reinterpret_cast<const float2*>(bias + nIn + wn * 32 + nf * 8 + tg * 2);

#pragma unroll
    for (int mf = 0; mf < 4; mf++) {
#pragma unroll
        for (int half = 0; half < 2; half++) {
            const int gm = mBase + wm * 64 + mf * 16 + grp + half * 8;
            if (MODE == 0) {
                __half* out = (__half*)((z == 0) ? out0 : (z == 1) ? out1 : out2);
                const int h = (nIn + wn * 32) >> 6;
                const int b = gm >> 11;
                const int s = gm & (S_ - 1);
                __half* dst = out + (((size_t)(b * H_ + h)) * S_ + s) * HD_;
#pragma unroll
                for (int nf = 0; nf < 4; nf++) {
                    const int hd = (nIn + wn * 32 + nf * 8 + tg * 2) & 63;
                    *reinterpret_cast<__half2*>(dst + hd) = __floats2half2_rn(
                        (acc[mf][nf][half * 2 + 0] + bz[nf].x) * scale,
                        (acc[mf][nf][half * 2 + 1] + bz[nf].y) * scale);
                }
            } else {
                float* out = (float*)out0;
                const __half* rr = resid + (size_t)gm * D_;
                float* orow      = out   + (size_t)gm * D_;
#pragma unroll
                for (int nf = 0; nf < 4; nf++) {
                    const int n = nIn + wn * 32 + nf * 8 + tg * 2;
                    float2 r2 = __half22float2(*reinterpret_cast<const __half2*>(rr + n));
                    float2 v2;
                    v2.x = acc[mf][nf][half * 2 + 0] + bz[nf].x + r2.x;
                    v2.y = acc[mf][nf][half * 2 + 1] + bz[nf].y + r2.y;
                    *reinterpret_cast<float2*>(orow + n) = v2;
                }
            }
        }
    }
}

// ---------------------------------------------------------------------------
// Flash attention fp16 (unchanged from round 12): 4 warps, 32 queries/warp,
// q-tile 128, keys 64/tile, split-phase cp.async K/V prefetch.
// SMEM (halves): Q 128x72 | K 64x72 | V 64x72 | P 4x(32x72)
// ---------------------------------------------------------------------------
#define QSTRH 72
#define KSTRH 72
#define VSTRH 72
#define PSTRH 72
#define FQH 0
#define FKH (128 * QSTRH)
#define FVH (FKH + 64 * KSTRH)
#define FPH (FVH + 64 * VSTRH)
#define PWB (32 * PSTRH * 2)
#define FSM_TOTAL ((FPH + 4 * 32 * PSTRH) * 2)   // 55296 B

__global__ __launch_bounds__(128, 2) void flash_mma_kernel(const __half* __restrict__ Qg,
                                                           const __half* __restrict__ Kg,
                                                           const __half* __restrict__ Vg,
                                                           __half* __restrict__ Og) {
    extern __shared__ __half fsm[];
    const uint32_t sb  = cvta_smem(fsm);
    const uint32_t sbQ = sb + FQH * 2;
    const uint32_t sbK = sb + FKH * 2;
    const uint32_t sbV = sb + FVH * 2;
    const uint32_t sbP = sb + FPH * 2;
    __half* Psm = fsm + FPH;

    const int t    = threadIdx.x;
    const int wid  = t >> 5;
    const int lane = t & 31;
    const int grp  = lane >> 2;
    const int tg   = lane & 3;
    const int bh   = blockIdx.y;
    const int qb   = blockIdx.x * 128;

    const int lm  = lane & 7;
    const int sel = lane >> 3;
    const int a_row_off = lm + ((sel & 1) ? 8 : 0);
    const int a_col_off = (sel & 2) ? 8 : 0;
    const int b_row_off = lm + ((sel & 2) ? 8 : 0);
    const int b_col_off = (sel & 1) ? 8 : 0;
    const int v_row_off = lm + ((sel & 1) ? 8 : 0);
    const int v_col_off = (sel & 2) ? 8 : 0;

    const __half* Qh = Qg + (size_t)bh * S_ * HD_;
    const __half* Kh = Kg + (size_t)bh * S_ * HD_;
    const __half* Vh = Vg + (size_t)bh * S_ * HD_;

    auto issueK = [&](int kt) {
#pragma unroll
        for (int ii = 0; ii < 4; ii++) {
            const int i   = t + 128 * ii;
            const int row = i >> 3;
            const int c8  = i & 7;
            CP_ASYNC16(sbK + 2 * (row * KSTRH + c8 * 8),
                       Kh + (size_t)(kt + row) * HD_ + c8 * 8);
        }
        CP_COMMIT();
    };
    auto issueV = [&](int kt) {
#pragma unroll
        for (int ii = 0; ii < 4; ii++) {
            const int i   = t + 128 * ii;
            const int row = i >> 3;
            const int c8  = i & 7;
            CP_ASYNC16(sbV + 2 * (row * VSTRH + c8 * 8),
                       Vh + (size_t)(kt + row) * HD_ + c8 * 8);
        }
        CP_COMMIT();
    };

#pragma unroll
    for (int ii = 0; ii < 8; ii++) {
        const int i   = t + 128 * ii;
        const int row = i >> 3;
        const int c8  = i & 7;
        CP_ASYNC16(sbQ + 2 * (row * QSTRH + c8 * 8),
                   Qh + (size_t)(qb + row) * HD_ + c8 * 8);
    }
    CP_COMMIT();
    issueK(0);
    issueV(0);

    __half* Pw = Psm + wid * 32 * PSTRH;
    const uint32_t Pw_sb = sbP + wid * PWB;

    float m[2][2], l[2][2];
#pragma unroll
    for (int i = 0; i < 2; i++) { m[i][0] = m[i][1] = -1e30f; l[i][0] = l[i][1] = 0.f; }
    float o[2][8][4];
#pragma unroll
    for (int mf = 0; mf < 2; mf++)
#pragma unroll
        for (int nt = 0; nt < 8; nt++)
#pragma unroll
            for (int r = 0; r < 4; r++) o[mf][nt][r] = 0.f;

#pragma unroll 1
    for (int n = 0; n < 32; n++) {
        const int kt = n * 64;
        CP_WAIT1();
        __syncthreads();

        float sc[2][8][4];
#pragma unroll
        for (int mf = 0; mf < 2; mf++)
#pragma unroll
            for (int nt = 0; nt < 8; nt++)
#pragma unroll
                for (int r = 0; r < 4; r++) sc[mf][nt][r] = 0.f;
#pragma unroll
        for (int s = 0; s < 4; s++) {
            const int kb = s * 16;
            uint32_t qf0[4], qf1[4], bm[4][4];
            ldsm4(qf0, sbQ + 2 * ((wid * 32 +  0 + a_row_off) * QSTRH + kb + a_col_off));
            ldsm4(qf1, sbQ + 2 * ((wid * 32 + 16 + a_row_off) * QSTRH + kb + a_col_off));
#pragma unroll
            for (int p = 0; p < 4; p++)
                ldsm4(bm[p], sbK + 2 * ((p * 16 + b_row_off) * KSTRH + kb + b_col_off));
#pragma unroll
            for (int nt = 0; nt < 8; nt++) {
                uint32_t bf[2] = { bm[nt >> 1][(nt & 1) * 2],
                                   bm[nt >> 1][(nt & 1) * 2 + 1] };
                mma16(sc[0][nt], qf0, bf);
                mma16(sc[1][nt], qf1, bf);
            }
        }

        __syncthreads();
        if (n + 1 < 32) issueK(kt + 64);

#pragma unroll
        for (int mf = 0; mf < 2; mf++) {
            float mx0 = -1e30f, mx1 = -1e30f;
#pragma unroll
            for (int nt = 0; nt < 8; nt++) {
                mx0 = fmaxf(mx0, fmaxf(sc[mf][nt][0], sc[mf][nt][1]));
                mx1 = fmaxf(mx1, fmaxf(sc[mf][nt][2], sc[mf][nt][3]));
            }
            mx0 = fmaxf(mx0, __shfl_xor_sync(0xffffffffu, mx0, 1));
            mx0 = fmaxf(mx0, __shfl_xor_sync(0xffffffffu, mx0, 2));
            mx1 = fmaxf(mx1, __shfl_xor_sync(0xffffffffu, mx1, 1));
            mx1 = fmaxf(mx1, __shfl_xor_sync(0xffffffffu, mx1, 2));
            const float mn0 = fmaxf(m[mf][0], mx0);
            const float mn1 = fmaxf(m[mf][1], mx1);
            const float a0 = __expf(m[mf][0] - mn0);
            const float a1 = __expf(m[mf][1] - mn1);
            m[mf][0] = mn0; m[mf][1] = mn1;
            float s0 = 0.f, s1 = 0.f;
#pragma unroll
            for (int nt = 0; nt < 8; nt++) {
                sc[mf][nt][0] = __expf(sc[mf][nt][0] - mn0);
                sc[mf][nt][1] = __expf(sc[mf][nt][1] - mn0);
                sc[mf][nt][2] = __expf(sc[mf][nt][2] - mn1);
                sc[mf][nt][3] = __expf(sc[mf][nt][3] - mn1);
                s0 += sc[mf][nt][0] + sc[mf][nt][1];
                s1 += sc[mf][nt][2] + sc[mf][nt][3];
            }
            s0 += __shfl_xor_sync(0xffffffffu, s0, 1);
            s0 += __shfl_xor_sync(0xffffffffu, s0, 2);
            s1 += __shfl_xor_sync(0xffffffffu, s1, 1);
            s1 += __shfl_xor_sync(0xffffffffu, s1, 2);
            l[mf][0] = l[mf][0] * a0 + s0;
            l[mf][1] = l[mf][1] * a1 + s1;
#pragma unroll
            for (int nt = 0; nt < 8; nt++) {
                o[mf][nt][0] *= a0; o[mf][nt][1] *= a0;
                o[mf][nt][2] *= a1; o[mf][nt][3] *= a1;
            }
#pragma unroll
            for (int nt = 0; nt < 8; nt++) {
                *reinterpret_cast<__half2*>(&Pw[(mf * 16 + grp) * PSTRH + nt * 8 + tg * 2]) =
                    __floats2half2_rn(sc[mf][nt][0], sc[mf][nt][1]);
                *reinterpret_cast<__half2*>(&Pw[(mf * 16 + grp + 8) * PSTRH + nt * 8 + tg * 2]) =
                    __floats2half2_rn(sc[mf][nt][2], sc[mf][nt][3]);
            }
        }
        __syncwarp();

        if (n + 1 < 32) CP_WAIT1(); else CP_WAIT0();
        __syncthreads();

#pragma unroll
        for (int s = 0; s < 4; s++) {
            const int kb = s * 16;
            uint32_t pf0[4], pf1[4], bm[4][4];
            ldsm4(pf0, Pw_sb + 2 * (( 0 + a_row_off) * PSTRH + kb + a_col_off));
            ldsm4(pf1, Pw_sb + 2 * ((16 + a_row_off) * PSTRH + kb + a_col_off));
#pragma unroll
            for (int p = 0; p < 4; p++)
                ldsm4t(bm[p], sbV + 2 * ((kb + v_row_off) * VSTRH + p * 16 + v_col_off));
#pragma unroll
            for (int nt = 0; nt < 8; nt++) {
                uint32_t bf[2] = { bm[nt >> 1][(nt & 1) * 2],
                                   bm[nt >> 1][(nt & 1) * 2 + 1] };
                mma16(o[0][nt], pf0, bf);
                mma16(o[1][nt], pf1, bf);
            }
        }

        __syncthreads();
        if (n + 1 < 32) issueV(kt + 64);
    }

    const int b = bh >> 4, h = bh & 15;
#pragma unroll
    for (int mf = 0; mf < 2; mf++) {
        const float inv0 = 1.0f / l[mf][0];
        const float inv1 = 1.0f / l[mf][1];
        const int r0 = qb + wid * 32 + mf * 16 + grp;
        __half* base0 = Og + ((size_t)b * S_ + r0) * D_ + h * HD_;
        __half* base1 = base0 + (size_t)8 * D_;
#pragma unroll
        for (int nt = 0; nt < 8; nt++) {
            *reinterpret_cast<__half2*>(base0 + nt * 8 + tg * 2) =
                __floats2half2_rn(o[mf][nt][0] * inv0, o[mf][nt][1] * inv0);
            *reinterpret_cast<__half2*>(base1 + nt * 8 + tg * 2) =
                __floats2half2_rn(o[mf][nt][2] * inv1, o[mf][nt][3] * inv1);
        }
    }
}

// ---------------------------------------------------------------------------
// LayerNorm over last dim (1024), one block per row
// ---------------------------------------------------------------------------
__global__ __launch_bounds__(256) void ln_kernel(const float* __restrict__ Hm,
                                                 const float* __restrict__ gamma,
                                                 const float* __restrict__ beta,
                                                 float* __restrict__ out) {
    const int row = blockIdx.x;
    const int t   = threadIdx.x;
    const float* hr = Hm + (size_t)row * D_;
    float4 v = *reinterpret_cast<const float4*>(hr + t * 4);
    float s  = v.x + v.y + v.z + v.w;
    float ss = v.x * v.x + v.y * v.y + v.z * v.z + v.w * v.w;
#pragma unroll
    for (int msk = 16; msk > 0; msk >>= 1) {
        s  += __shfl_xor_sync(0xffffffffu, s, msk);
        ss += __shfl_xor_sync(0xffffffffu, ss, msk);
    }
    __shared__ float rs[8], rss[8];
    __shared__ float mu_s, rstd_s;
    int w = t >> 5;
    if ((t & 31) == 0) { rs[w] = s; rss[w] = ss; }
    __syncthreads();
    if (t == 0) {
        float S = 0.f, SS = 0.f;
#pragma unroll
        for (int i = 0; i < 8; i++) { S += rs[i]; SS += rss[i]; }
        float mu  = S * (1.0f / D_);
        float var = SS * (1.0f / D_) - mu * mu;
        mu_s = mu;
        rstd_s = rsqrtf(var + 1e-5f);
    }
    __syncthreads();
    float mu = mu_s, rstd = rstd_s;
    float4 g4 = *reinterpret_cast<const float4*>(gamma + t * 4);
    float4 b4 = *reinterpret_cast<const float4*>(beta + t * 4);
    float4 o4;
    o4.x = (v.x - mu) * rstd * g4.x + b4.x;
    o4.y = (v.y - mu) * rstd * g4.y + b4.y;
    o4.z = (v.z - mu) * rstd * g4.z + b4.z;
    o4.w = (v.w - mu) * rstd * g4.w + b4.w;
    *reinterpret_cast<float4*>(out + (size_t)row * D_ + t * 4) = o4;
}

// ---------------------------------------------------------------------------
extern "C" void kernel_launch(void* const* d_in, const int* in_sizes, int n_in,
                              void* d_out, int out_size) {
    (void)in_sizes; (void)n_in; (void)out_size;
    const float* x     = (const float*)d_in[0];
    const float* wq    = (const float*)d_in[1];
    const float* bq    = (const float*)d_in[2];
    const float* wk    = (const float*)d_in[3];
    const float* bk    = (const float*)d_in[4];
    const float* wv    = (const float*)d_in[5];
    const float* bv    = (const float*)d_in[6];
    const float* wo    = (const float*)d_in[7];
    const float* bo    = (const float*)d_in[8];
    const float* gamma = (const float*)d_in[9];
    const float* beta  = (const float*)d_in[10];
    const float* pe    = (const float*)d_in[11];
    float* out = (float*)d_out;

    __half *xp, *q, *k, *v, *o, *wt;
    float *h;
    cudaGetSymbolAddress((void**)&xp, g_xp);
    cudaGetSymbolAddress((void**)&q,  g_q);
    cudaGetSymbolAddress((void**)&k,  g_k);
    cudaGetSymbolAddress((void**)&v,  g_v);
    cudaGetSymbolAddress((void**)&o,  g_o);
    cudaGetSymbolAddress((void**)&h,  g_h);
    cudaGetSymbolAddress((void**)&wt, g_wt4);

    cudaFuncSetAttribute(gemm_mma_kernel<0>,
                         cudaFuncAttributeMaxDynamicSharedMemorySize, GSM_TOTAL);
    cudaFuncSetAttribute(gemm_mma_kernel<1>,
                         cudaFuncAttributeMaxDynamicSharedMemorySize, GSM_TOTAL);
    cudaFuncSetAttribute(flash_mma_kernel,
                         cudaFuncAttributeMaxDynamicSharedMemorySize, FSM_TOTAL);

    // 1) x + pe (fp16)
    pe_add_kernel<<<(MTOT * D_ / 4) / 256, 256>>>(x, pe);

    // 2) transpose + convert all 4 weights -> g_wt4 [N,K] fp16 (q|k|v|o contiguous)
    transpose4_kernel<<<dim3(32, 32, 4), dim3(32, 8)>>>(wq, wk, wv, wo);

    // 3) fused Q/K/V projection: N = 3072 in one launch
    dim3 qkvgrid(3 * D_ / 128, MTOT / 128);
    gemm_mma_kernel<0><<<qkvgrid, 256, GSM_TOTAL>>>(xp, wt, bq, bk, bv, nullptr,
                                                    q, k, v);

    // 4) attention
    dim3 fgrid(S_ / 128, B_ * H_);
    flash_mma_kernel<<<fgrid, 128, FSM_TOTAL>>>(q, k, v, o);

    // 5) output projection + bias + residual (fp32 out)
    dim3 ogrid(D_ / 128, MTOT / 128);
    gemm_mma_kernel<1><<<ogrid, 256, GSM_TOTAL>>>(o, wt + 3 * (size_t)D_ * D_, bo,
                                                  nullptr, nullptr, xp, h, nullptr, nullptr);

    // 6) layernorm
    ln_kernel<<<MTOT, 256>>>(h, gamma, beta, out);
}